// round 9
// baseline (speedup 1.0000x reference)
#include <cuda_runtime.h>
#include <cuda_bf16.h>
#include <math.h>
#include <stdint.h>

// Problem constants
#define B    4
#define N1   2048
#define N2   2048
#define NC   4096           // N1+N2
#define D    256
#define HP   64
#define HA   64
#define KNN  16
#define MROW (B*N1*KNN)     // 131072
#define INV_MROW (1.0f/131072.0f)

// ---------------- scratch (device globals; no allocation allowed) -------------
__device__ float g_dx  [B*N1*D];
__device__ float g_ex  [B*N2*D];
__device__ float g_sx  [B*N1*D];
__device__ float g_spc [B*N1*3];
__device__ int   g_fidx[B*N1];
__device__ float g_qa  [B*N1*HA];
__device__ float g_ka  [B*N1*HA];
__device__ float g_v   [B*N1*D];
__device__ int   g_nidx[B*N1*KNN];
__device__ float g_hpos [MROW*HP];
__device__ float g_hattn[MROW*HA];
__device__ float g_x   [B*N1*D];
__device__ float g_WkWa1[D*HA];
__device__ float g_WqWa1[D*HA];
__device__ float g_Wp2a [HP*HA];
__device__ float g_cvec [HA];
// [0:64) psum [64:128) psq [128:192) asum [192:256) asq
__device__ float g_stats[256];

// ================= packed f32x2 helpers (sm_103a FFMA2 path) ==================
#define ADD2(o,a,b)   asm("add.rn.f32x2 %0, %1, %2;" : "=l"(o) : "l"(a), "l"(b))
#define MUL2(o,a,b)   asm("mul.rn.f32x2 %0, %1, %2;" : "=l"(o) : "l"(a), "l"(b))
#define FMA2(o,a,b,c) asm("fma.rn.f32x2 %0, %1, %2, %3;" : "=l"(o) : "l"(a), "l"(b), "l"(c))
__device__ __forceinline__ unsigned long long pack2(float lo, float hi) {
    unsigned long long o;
    asm("mov.b64 %0, {%1, %2};" : "=l"(o) : "r"(__float_as_uint(lo)), "r"(__float_as_uint(hi)));
    return o;
}
__device__ __forceinline__ void unpack2(unsigned long long v, float& lo, float& hi) {
    uint32_t a, b;
    asm("mov.b64 {%0, %1}, %2;" : "=r"(a), "=r"(b) : "l"(v));
    lo = __uint_as_float(a); hi = __uint_as_float(b);
}

// ================= tf32 mma helpers ===========================================
__device__ __forceinline__ uint32_t f2tf(float x) {
    uint32_t r; asm("cvt.rna.tf32.f32 %0, %1;" : "=r"(r) : "f"(x)); return r;
}
__device__ __forceinline__ void mma8(float* d, const uint32_t* a, const uint32_t* b) {
    asm volatile("mma.sync.aligned.m16n8k8.row.col.f32.tf32.tf32.f32 "
        "{%0,%1,%2,%3}, {%4,%5,%6,%7}, {%8,%9}, {%0,%1,%2,%3};"
        : "+f"(d[0]), "+f"(d[1]), "+f"(d[2]), "+f"(d[3])
        : "r"(a[0]), "r"(a[1]), "r"(a[2]), "r"(a[3]), "r"(b[0]), "r"(b[1]));
}

// ------ tf32x2 GEMM body: 128x128 tile, 512 threads, hi/lo planes, 3-mma ------
#define APITCH 36
#define BPITCH 136
#define TF32_SMEM_FLOATS (2*128*APITCH + 2*32*BPITCH)

__device__ __forceinline__ void gemm_tf32_body(
    const float* __restrict__ A, const float* __restrict__ W,
    const float* __restrict__ bias, const float* __restrict__ resid,
    float* __restrict__ C, int bx, int by, int N, int K)
{
    extern __shared__ float smext[];
    float* AHs = smext;
    float* ALs = AHs + 128*APITCH;
    float* BHs = ALs + 128*APITCH;
    float* BLs = BHs + 32*BPITCH;
    int tid = threadIdx.x;
    int row0 = by * 128, col0 = bx * 128;
    int warp = tid >> 5, lane = tid & 31;
    int mw = (warp & 3) * 32, nw = (warp >> 2) * 32;
    int g = lane >> 2, tg = lane & 3;
    float acc[8][4] = {};
    for (int k0 = 0; k0 < K; k0 += 32) {
#pragma unroll
        for (int i = 0; i < 2; i++) {
            int idx = tid + i*512;
            int r = idx >> 3, c4 = (idx & 7) * 4;
            float4 v = *(const float4*)&A[(size_t)(row0+r)*K + k0 + c4];
            float xs[4] = {v.x, v.y, v.z, v.w};
#pragma unroll
            for (int u = 0; u < 4; u++) {
                uint32_t hi = f2tf(xs[u]);
                AHs[r*APITCH + c4+u] = __uint_as_float(hi);
                ALs[r*APITCH + c4+u] = __uint_as_float(f2tf(xs[u] - __uint_as_float(hi)));
            }
        }
#pragma unroll
        for (int i = 0; i < 2; i++) {
            int idx = tid + i*512;
            int r = idx >> 5, c4 = (idx & 31) * 4;
            float4 v = *(const float4*)&W[(size_t)(k0+r)*N + col0 + c4];
            float xs[4] = {v.x, v.y, v.z, v.w};
#pragma unroll
            for (int u = 0; u < 4; u++) {
                uint32_t hi = f2tf(xs[u]);
                BHs[r*BPITCH + c4+u] = __uint_as_float(hi);
                BLs[r*BPITCH + c4+u] = __uint_as_float(f2tf(xs[u] - __uint_as_float(hi)));
            }
        }
        __syncthreads();
#pragma unroll
        for (int ks = 0; ks < 32; ks += 8) {
            uint32_t ah[2][4], al[2][4], bh[4][2], bl[4][2];
#pragma unroll
            for (int mi = 0; mi < 2; mi++) {
                int rb = mw + mi*16;
                ah[mi][0] = __float_as_uint(AHs[(rb+g  )*APITCH + ks+tg  ]);
                ah[mi][1] = __float_as_uint(AHs[(rb+g+8)*APITCH + ks+tg  ]);
                ah[mi][2] = __float_as_uint(AHs[(rb+g  )*APITCH + ks+tg+4]);
                ah[mi][3] = __float_as_uint(AHs[(rb+g+8)*APITCH + ks+tg+4]);
                al[mi][0] = __float_as_uint(ALs[(rb+g  )*APITCH + ks+tg  ]);
                al[mi][1] = __float_as_uint(ALs[(rb+g+8)*APITCH + ks+tg  ]);
                al[mi][2] = __float_as_uint(ALs[(rb+g  )*APITCH + ks+tg+4]);
                al[mi][3] = __float_as_uint(ALs[(rb+g+8)*APITCH + ks+tg+4]);
            }
#pragma unroll
            for (int ni = 0; ni < 4; ni++) {
                bh[ni][0] = __float_as_uint(BHs[(ks+tg  )*BPITCH + nw + ni*8 + g]);
                bh[ni][1] = __float_as_uint(BHs[(ks+tg+4)*BPITCH + nw + ni*8 + g]);
                bl[ni][0] = __float_as_uint(BLs[(ks+tg  )*BPITCH + nw + ni*8 + g]);
                bl[ni][1] = __float_as_uint(BLs[(ks+tg+4)*BPITCH + nw + ni*8 + g]);
            }
#pragma unroll
            for (int mi = 0; mi < 2; mi++)
#pragma unroll
                for (int ni = 0; ni < 4; ni++) {
                    mma8(acc[mi*4+ni], ah[mi], bh[ni]);
                    mma8(acc[mi*4+ni], ah[mi], bl[ni]);
                    mma8(acc[mi*4+ni], al[mi], bh[ni]);
                }
        }
        __syncthreads();
    }
#pragma unroll
    for (int mi = 0; mi < 2; mi++) {
#pragma unroll
        for (int ni = 0; ni < 4; ni++) {
            int c = col0 + nw + ni*8 + 2*tg;
            float b0 = bias ? bias[c]   : 0.f;
            float b1 = bias ? bias[c+1] : 0.f;
            size_t r1 = (size_t)(row0 + mw + mi*16 + g);
            size_t r2 = r1 + 8;
            float v00 = acc[mi*4+ni][0] + b0, v01 = acc[mi*4+ni][1] + b1;
            float v10 = acc[mi*4+ni][2] + b0, v11 = acc[mi*4+ni][3] + b1;
            if (resid) {
                v00 += resid[r1*N+c]; v01 += resid[r1*N+c+1];
                v10 += resid[r2*N+c]; v11 += resid[r2*N+c+1];
            }
            *(float2*)&C[r1*N + c] = make_float2(v00, v01);
            *(float2*)&C[r2*N + c] = make_float2(v10, v11);
        }
    }
}

// ---------------- combined post-GEMMs (z selects output head) ------------------
__global__ void __launch_bounds__(512)
gemm_post_kernel(const float* __restrict__ X,
                 const float* __restrict__ W1, const float* __restrict__ b1,
                 const float* __restrict__ resid1, float* __restrict__ out1,
                 const float* __restrict__ W2, const float* __restrict__ b2,
                 float* __restrict__ out2)
{
    if (blockIdx.z == 0)
        gemm_tf32_body(X, W1, b1, resid1, out1, blockIdx.x, blockIdx.y, D, D);
    else
        gemm_tf32_body(X, W2, b2, nullptr, out2, blockIdx.x, blockIdx.y, D, D);
}

// ---------------- FPS body: 512 threads, packed f32x2 distance math -----------
__device__ void fps_body(int b, const float* __restrict__ decpc,
                         const float* __restrict__ encpc)
{
    extern __shared__ float smext[];
    float* sx = smext;
    float* sy = smext + NC;
    float* sz = smext + 2*NC;
    __shared__ unsigned long long swk[2][16];

    int tid = threadIdx.x;
    int wid = tid >> 5, lid = tid & 31;

    for (int j = tid; j < N1; j += 512) {
        sx[j] = decpc[((size_t)b*N1 + j)*3 + 0];
        sy[j] = decpc[((size_t)b*N1 + j)*3 + 1];
        sz[j] = decpc[((size_t)b*N1 + j)*3 + 2];
        sx[N1+j] = encpc[((size_t)b*N2 + j)*3 + 0];
        sy[N1+j] = encpc[((size_t)b*N2 + j)*3 + 1];
        sz[N1+j] = encpc[((size_t)b*N2 + j)*3 + 2];
    }
    if (tid == 0) g_fidx[b*N1] = 0;
    int cur = 0;
    __syncthreads();

    // coords packed in registers (2 points per 64-bit)
    unsigned long long PX[4], PY[4], PZ[4];
    float md[8];
#pragma unroll
    for (int p = 0; p < 4; p++) {
        int j0 = tid + (2*p)*512, j1 = tid + (2*p+1)*512;
        PX[p] = pack2(sx[j0], sx[j1]);
        PY[p] = pack2(sy[j0], sy[j1]);
        PZ[p] = pack2(sz[j0], sz[j1]);
        md[2*p] = 1e10f; md[2*p+1] = 1e10f;
    }

    for (int i = 1; i < N1; i++) {
        float lx = sx[cur], ly = sy[cur], lz = sz[cur];
        unsigned long long ncx = pack2(-lx, -lx);
        unsigned long long ncy = pack2(-ly, -ly);
        unsigned long long ncz = pack2(-lz, -lz);
        float bv = -1.0f;
#pragma unroll
        for (int p = 0; p < 4; p++) {
            unsigned long long dx, dy, dz, dd;
            ADD2(dx, PX[p], ncx);
            ADD2(dy, PY[p], ncy);
            ADD2(dz, PZ[p], ncz);
            MUL2(dd, dx, dx);
            FMA2(dd, dy, dy, dd);
            FMA2(dd, dz, dz, dd);
            float d0, d1; unpack2(dd, d0, d1);
            float m0 = fminf(md[2*p], d0);
            float m1 = fminf(md[2*p+1], d1);
            md[2*p] = m0; md[2*p+1] = m1;
            bv = fmaxf(bv, fmaxf(m0, m1));
        }
        // smallest t with md[t]==bv  -> smallest index
        int bt = 7;
#pragma unroll
        for (int t = 6; t >= 0; t--) if (md[t] == bv) bt = t;
        if (md[7] == bv && md[bt] != bv) bt = 7;   // (redundant safety; md[bt]==bv always)
        int besti = tid + bt*512;

        unsigned kb = __float_as_uint(bv);
        kb = ((int)kb < 0) ? ~kb : (kb | 0x80000000u);
        unsigned mk;
        asm("redux.sync.max.u32 %0, %1, 0xffffffff;" : "=r"(mk) : "r"(kb));
        unsigned idxc = (kb == mk) ? (unsigned)besti : 0xffffffffu;
        unsigned mi;
        asm("redux.sync.min.u32 %0, %1, 0xffffffff;" : "=r"(mi) : "r"(idxc));
        int pb = i & 1;
        if (lid == 0)
            swk[pb][wid] = (((unsigned long long)mk) << 32) | (unsigned long long)(0xffffffffu - mi);
        __syncthreads();
        // depth-4 tree max over 16 partials
        unsigned long long t0 = swk[pb][0] > swk[pb][1] ? swk[pb][0] : swk[pb][1];
        unsigned long long t1 = swk[pb][2] > swk[pb][3] ? swk[pb][2] : swk[pb][3];
        unsigned long long t2 = swk[pb][4] > swk[pb][5] ? swk[pb][4] : swk[pb][5];
        unsigned long long t3 = swk[pb][6] > swk[pb][7] ? swk[pb][6] : swk[pb][7];
        unsigned long long t4 = swk[pb][8] > swk[pb][9] ? swk[pb][8] : swk[pb][9];
        unsigned long long t5 = swk[pb][10] > swk[pb][11] ? swk[pb][10] : swk[pb][11];
        unsigned long long t6 = swk[pb][12] > swk[pb][13] ? swk[pb][12] : swk[pb][13];
        unsigned long long t7 = swk[pb][14] > swk[pb][15] ? swk[pb][14] : swk[pb][15];
        t0 = t0 > t1 ? t0 : t1;  t2 = t2 > t3 ? t2 : t3;
        t4 = t4 > t5 ? t4 : t5;  t6 = t6 > t7 ? t6 : t7;
        t0 = t0 > t2 ? t0 : t2;  t4 = t4 > t6 ? t4 : t6;
        t0 = t0 > t4 ? t0 : t4;
        cur = (int)(0xffffffffu - (unsigned)t0);
        if (tid == 0) g_fidx[b*N1 + i] = cur;
    }
}

// ---------------- small 64-col GEMM body (weight precomputes), 512 thr --------
#define TBM 64
#define TBK 16
__device__ void gemm64_body(const float* __restrict__ A, const float* __restrict__ W,
                            float* __restrict__ C, int row0, int N, int K)
{
    __shared__ float As64[TBK][TBM];
    __shared__ float Bs64[TBK][64];
    int tid = threadIdx.x;
    for (int k0 = 0; k0 < K; k0 += TBK) {
#pragma unroll
        for (int u = 0; u < 2; u++) {
            int e = tid + u*512;
            int r = e >> 4, c = e & 15;
            As64[c][r] = A[(size_t)(row0 + r)*K + k0 + c];
            int r2 = e >> 6, c2 = e & 63;
            Bs64[r2][c2] = W[(size_t)(k0 + r2)*N + c2];
        }
        __syncthreads();
        if (tid < 256) {
            int tx = tid & 15, ty = tid >> 4;
            float acc[4][4] = {};
#pragma unroll
            for (int kk = 0; kk < TBK; kk++) {
                float a[4], bb[4];
#pragma unroll
                for (int i = 0; i < 4; i++) a[i] = As64[kk][ty*4+i];
#pragma unroll
                for (int j = 0; j < 4; j++) bb[j] = Bs64[kk][tx*4+j];
#pragma unroll
                for (int i = 0; i < 4; i++)
#pragma unroll
                    for (int j = 0; j < 4; j++)
                        acc[i][j] += a[i]*bb[j];
            }
#pragma unroll
            for (int i = 0; i < 4; i++)
#pragma unroll
                for (int j = 0; j < 4; j++) {
                    size_t off = (size_t)(row0 + ty*4 + i)*N + tx*4 + j;
                    if (k0 == 0) C[off] = acc[i][j];
                    else         C[off] += acc[i][j];
                }
        }
        __syncthreads();
    }
}

// ---------------- cvec body: (bk - bq + bp2) @ Wa1 + ba1, 512 thr --------------
__device__ void cvec_body(const float* __restrict__ bk, const float* __restrict__ bq,
                          const float* __restrict__ bp2, const float* __restrict__ Wa1,
                          const float* __restrict__ ba1)
{
    __shared__ float shc[512];
    int c = threadIdx.x & 63;
    int part = threadIdx.x >> 6;     // 0..7
    float s = 0.f;
    for (int i = part*32; i < part*32 + 32; i++)
        s += (bk[i] - bq[i] + bp2[i]) * Wa1[(size_t)i*HA + c];
    shc[threadIdx.x] = s;
    __syncthreads();
    if (part == 0) {
        float t = ba1[c];
#pragma unroll
        for (int p = 0; p < 8; p++) t += shc[p*64 + c];
        g_cvec[c] = t;
    }
}

// ---------------- phase-1 mega-kernel -----------------------------------------
__global__ void __launch_bounds__(512)
phase1_kernel(const float* __restrict__ dec_pc, const float* __restrict__ enc_pc,
              const float* __restrict__ dec_x,  const float* __restrict__ enc_x,
              const float* __restrict__ W_pre1, const float* __restrict__ b_pre1,
              const float* __restrict__ W_pre2, const float* __restrict__ b_pre2,
              const float* __restrict__ Wk, const float* __restrict__ Wq,
              const float* __restrict__ Wa1, const float* __restrict__ Wp2,
              const float* __restrict__ bk, const float* __restrict__ bq,
              const float* __restrict__ bp2, const float* __restrict__ ba1)
{
    int bid = blockIdx.x;
    if (bid < 4) {
        fps_body(bid, dec_pc, enc_pc);
    } else if (bid < 132) {
        int t = bid - 4;
        gemm_tf32_body(dec_x, W_pre1, b_pre1, nullptr, g_dx, t & 1, t >> 1, D, D);
    } else if (bid < 260) {
        int t = bid - 132;
        gemm_tf32_body(enc_x, W_pre2, b_pre2, nullptr, g_ex, t & 1, t >> 1, D, D);
    } else if (bid < 264) {
        gemm64_body(Wk, Wa1, g_WkWa1, (bid-260)*64, HA, D);
    } else if (bid < 268) {
        gemm64_body(Wq, Wa1, g_WqWa1, (bid-264)*64, HA, D);
    } else if (bid == 268) {
        gemm64_body(Wp2, Wa1, g_Wp2a, 0, HA, D);
    } else if (bid == 269) {
        cvec_body(bk, bq, bp2, Wa1, ba1);
    } else {
        if (threadIdx.x < 256) g_stats[threadIdx.x] = 0.0f;
    }
}

// ---------------- gather sampled features + coords ----------------------------
__global__ void gather_kernel(const float* __restrict__ decpc,
                              const float* __restrict__ encpc)
{
    int row = blockIdx.x*4 + (threadIdx.x >> 6);
    int c4  = (threadIdx.x & 63) * 4;
    int b = row >> 11;
    int j = g_fidx[row];
    const float* src = (j < N1) ? &g_dx[((size_t)b*N1 + j)*D]
                                : &g_ex[((size_t)b*N2 + (j - N1))*D];
    *(float4*)&g_sx[(size_t)row*D + c4] = *(const float4*)&src[c4];
    if ((threadIdx.x & 63) < 3) {
        int cc = threadIdx.x & 63;
        const float* ps = (j < N1) ? &decpc[((size_t)b*N1 + j)*3]
                                   : &encpc[((size_t)b*N2 + (j - N1))*3];
        g_spc[(size_t)row*3 + cc] = ps[cc];
    }
}

// ---------------- N=64 GEMM body for 512 threads (qa/ka) -----------------------
__device__ void n64_body_512(const float* __restrict__ A, const float* __restrict__ W,
                             float* __restrict__ C, int row0)
{
    __shared__ float Asq[16][132];
    __shared__ float Bsq[16][64];
    int tid = threadIdx.x;
    int tx = tid & 15, ty = tid >> 4;          // ty 0..31
    float acc[4][4] = {};
    for (int k0 = 0; k0 < D; k0 += 16) {
        {
            int r = tid >> 2, kq = (tid & 3) * 4;
            float4 va = *(const float4*)&A[(size_t)(row0 + r)*D + k0 + kq];
            Asq[kq+0][r] = va.x; Asq[kq+1][r] = va.y;
            Asq[kq+2][r] = va.z; Asq[kq+3][r] = va.w;
        }
        if (tid < 256) {
            int r = tid >> 4, cq = (tid & 15) * 4;
            *(float4*)&Bsq[r][cq] = *(const float4*)&W[(size_t)(k0 + r)*HA + cq];
        }
        __syncthreads();
#pragma unroll
        for (int kk = 0; kk < 16; kk++) {
            float a[4], bb[4];
#pragma unroll
            for (int i = 0; i < 4; i++) a[i] = Asq[kk][ty*4+i];
#pragma unroll
            for (int j = 0; j < 4; j++) bb[j] = Bsq[kk][tx*4+j];
#pragma unroll
            for (int i = 0; i < 4; i++)
#pragma unroll
                for (int j = 0; j < 4; j++)
                    acc[i][j] += a[i]*bb[j];
        }
        __syncthreads();
    }
#pragma unroll
    for (int i = 0; i < 4; i++)
#pragma unroll
        for (int j = 0; j < 4; j++)
            C[(size_t)(row0 + ty*4 + i)*HA + tx*4 + j] = acc[i][j];
}

// ---------------- phase-2 mega-kernel: KNN + qa/ka + v -------------------------
__global__ void __launch_bounds__(512)
phase2_kernel(const float* __restrict__ decpc,
              const float* __restrict__ Wv, const float* __restrict__ bv)
{
    int bid = blockIdx.x;
    if (bid < 32) {
        extern __shared__ float s2[];
        float* px = s2; float* py = px + 2048; float* pz = py + 2048; float* s2s = pz + 2048;
        unsigned long long* buf = (unsigned long long*)(s2 + 8192);
        int tid = threadIdx.x;
        int b = bid >> 3, qb = bid & 7;
        for (int m = tid; m < 2048; m += 512) {
            float x = g_spc[((size_t)b*N1 + m)*3 + 0];
            float y = g_spc[((size_t)b*N1 + m)*3 + 1];
            float z = g_spc[((size_t)b*N1 + m)*3 + 2];
            px[m] = x; py[m] = y; pz[m] = z;
            s2s[m] = x*x + y*y + z*z;
        }
        __syncthreads();
        int qi = tid & 255, h = tid >> 8;
        int q = qb*256 + qi;
        float qx = decpc[((size_t)b*N1 + q)*3 + 0];
        float qy = decpc[((size_t)b*N1 + q)*3 + 1];
        float qz = decpc[((size_t)b*N1 + q)*3 + 2];
        float s1 = qx*qx + qy*qy + qz*qz;
        float bd[KNN]; int bi[KNN];
#pragma unroll
        for (int t = 0; t < KNN; t++) { bd[t] = 1e30f; bi[t] = 0; }
        int mbase = h * 1024;
        for (int mm = 0; mm < 1024; mm++) {
            int m = mbase + mm;
            float d = s1 + s2s[m] - 2.0f*(qx*px[m] + qy*py[m] + qz*pz[m]);
            if (d < bd[KNN-1]) {
                bd[KNN-1] = d; bi[KNN-1] = m;
#pragma unroll
                for (int t = KNN-1; t > 0; t--) {
                    if (bd[t] < bd[t-1]) {
                        float td = bd[t]; bd[t] = bd[t-1]; bd[t-1] = td;
                        int   ti = bi[t]; bi[t] = bi[t-1]; bi[t-1] = ti;
                    }
                }
            }
        }
#pragma unroll
        for (int t = 0; t < KNN; t++) {
            unsigned u = __float_as_uint(bd[t]);
            u = ((int)u < 0) ? ~u : (u | 0x80000000u);
            buf[(size_t)tid*KNN + t] = (((unsigned long long)u) << 32) | (unsigned)bi[t];
        }
        __syncthreads();
        if (h == 0) {
            const unsigned long long* A_ = &buf[(size_t)qi*KNN];
            const unsigned long long* B_ = &buf[(size_t)(qi+256)*KNN];
            int* outp = &g_nidx[((size_t)b*N1 + q)*KNN];
            int ia = 0, ib = 0;
#pragma unroll
            for (int o = 0; o < KNN; o++) {
                unsigned long long av = A_[ia], bv_ = B_[ib];
                if ((av >> 32) <= (bv_ >> 32)) { outp[o] = (int)(unsigned)av; ia++; }
                else                           { outp[o] = (int)(unsigned)bv_; ib++; }
            }
        }
    } else if (bid < 160) {
        int t = bid - 32;
        int sel = t >> 6, tile = t & 63;
        n64_body_512(sel ? g_sx : g_dx, sel ? g_WkWa1 : g_WqWa1,
                     sel ? g_ka : g_qa, tile*128);
    } else {
        int t = bid - 160;
        gemm_tf32_body(g_sx, Wv, bv, nullptr, g_v, t & 1, t >> 1, D, D);
    }
}

// ---------------- hpos + fused BN stats ----------------------------------------
__global__ void __launch_bounds__(256)
hpos_kernel(const float* __restrict__ decpc,
            const float* __restrict__ Wp1,
            const float* __restrict__ bp1)
{
    int tid = threadIdx.x;
    int c = tid & 63;
    int rg = tid >> 6;
    float w0 = Wp1[c], w1 = Wp1[64+c], w2 = Wp1[128+c], bb = bp1[c];
    float s = 0.f, s2 = 0.f;
    int base = blockIdx.x * 256;
    for (int it = 0; it < 64; it++) {
        int m = base + it*4 + rg;
        int b = m >> 15;
        int n = (m >> 4) & 2047;
        int j = g_nidx[m];
        const float* pp = &g_spc[((size_t)b*N1 + j)*3];
        const float* qq = &decpc[((size_t)b*N1 + n)*3];
        float p0 = pp[0]-qq[0], p1 = pp[1]-qq[1], p2 = pp[2]-qq[2];
        float h = p0*w0 + p1*w1 + p2*w2 + bb;
        g_hpos[(size_t)m*HP + c] = h;
        s += h; s2 += h*h;
    }
    __shared__ float sh[256], sh2[256];
    sh[tid] = s; sh2[tid] = s2;
    __syncthreads();
    if (rg == 0) {
        atomicAdd(&g_stats[c],    sh[c] + sh[64+c] + sh[128+c] + sh[192+c]);
        atomicAdd(&g_stats[64+c], sh2[c] + sh2[64+c] + sh2[128+c] + sh2[192+c]);
    }
}

// ---- hattn = relu(bn_pos(hp)) @ Wp2a + ka[gather] - qa + cvec + stats --------
__global__ void __launch_bounds__(256)
hattn_kernel(const float* __restrict__ gp, const float* __restrict__ betap)
{
    __shared__ float Aw[64][65];
    __shared__ float Bw[64*64];
    __shared__ float psc[64], psh[64];
    __shared__ float rs[16][64], rs2[16][64];
    int tid = threadIdx.x;
    int m0 = blockIdx.x * 64;
    if (tid < 64) {
        float mean = g_stats[tid] * INV_MROW;
        float var  = g_stats[64+tid] * INV_MROW - mean*mean;
        float sc = gp[tid]*rsqrtf(var + 1e-5f);
        psc[tid] = sc;
        psh[tid] = betap[tid] - mean*sc;
    }
    __syncthreads();
#pragma unroll
    for (int i = 0; i < 16; i++) {
        int idx = tid + i*256;
        int r = idx >> 6, k = idx & 63;
        float h = g_hpos[(size_t)(m0+r)*64 + k];
        Aw[r][k] = fmaxf(h*psc[k] + psh[k], 0.0f);
        Bw[idx] = g_Wp2a[idx];
    }
    __syncthreads();
    int tx = tid & 15, ty = tid >> 4;
    float acc[4][4] = {};
#pragma unroll 4
    for (int kk = 0; kk < 64; kk++) {
        float a[4], bb[4];
#pragma unroll
        for (int i = 0; i < 4; i++) a[i] = Aw[ty*4+i][kk];
#pragma unroll
        for (int j = 0; j < 4; j++) bb[j] = Bw[kk*64 + tx*4 + j];
#pragma unroll
        for (int i = 0; i < 4; i++)
#pragma unroll
            for (int j = 0; j < 4; j++)
                acc[i][j] += a[i]*bb[j];
    }
    float ps[4] = {0,0,0,0}, ps2[4] = {0,0,0,0};
#pragma unroll
    for (int i = 0; i < 4; i++) {
        int m = m0 + ty*4 + i;
        int b = m >> 15;
        int n = (m >> 4) & 2047;
        int jj = g_nidx[m];
        const float* kar = &g_ka[(((size_t)b<<11) + jj)*HA];
        const float* qar = &g_qa[(((size_t)b<<11) + n )*HA];
#pragma unroll
        for (int j = 0; j < 4; j++) {
            int c = tx*4 + j;
            float v = acc[i][j] + kar[c] - qar[c] + g_cvec[c];
            g_hattn[(size_t)m*HA + c] = v;
            ps[j] += v; ps2[j] += v*v;
        }
    }
#pragma unroll
    for (int j = 0; j < 4; j++) {
        rs[ty][tx*4+j] = ps[j];
        rs2[ty][tx*4+j] = ps2[j];
    }
    __syncthreads();
    if (tid < 64) {
        float s = 0.f, s2 = 0.f;
#pragma unroll
        for (int t = 0; t < 16; t++) { s += rs[t][tid]; s2 += rs2[t][tid]; }
        atomicAdd(&g_stats[128+tid], s);
        atomicAdd(&g_stats[192+tid], s2);
    }
}

// ---- fused: attn GEMM -> softmax-in-place -> pos GEMM w/ fused aggregation ----
// grid 2048; block handles 64 rows (4 queries) x 256 cols (two 128-col halves)
__global__ void __launch_bounds__(256)
attnout_kernel(const float* __restrict__ Wa2,
               const float* __restrict__ ba2,
               const float* __restrict__ Wp2,
               const float* __restrict__ bp2,
               const float* __restrict__ gp, const float* __restrict__ betap,
               const float* __restrict__ ga, const float* __restrict__ betaa)
{
    extern __shared__ float sm[];
    float* Ahr    = sm;                 // [64][68]
    float* Apr    = Ahr + 64*68;        // [64][68]
    float* attn_s = Apr + 64*68;        // [64][132] -> becomes softmax weights
    float* Bh     = attn_s + 64*132;    // [16][136]
    float* Bl     = Bh + 16*136;        // [16][136]
    float* scbuf  = Bl + 16*136;        // psc,psh,asc,ash [4][64]
    int*   sj     = (int*)(scbuf + 256);// [64]

    int tid = threadIdx.x;
    int m0 = blockIdx.x * 64;
    int warp = tid >> 5, lane = tid & 31;
    int mw = (warp & 3) * 16, nw = (warp >> 2) * 64;
    int g = lane >> 2, tg = lane & 3;

    if (tid < 64) {
        float mean = g_stats[tid] * INV_MROW;
        float var  = g_stats[64+tid] * INV_MROW - mean*mean;
        float sc = gp[tid]*rsqrtf(var + 1e-5f);
        scbuf[tid] = sc;
        scbuf[64+tid] = betap[tid] - mean*sc;
        mean = g_stats[128+tid] * INV_MROW;
        var  = g_stats[192+tid] * INV_MROW - mean*mean;
        sc = ga[tid]*rsqrtf(var + 1e-5f);
        scbuf[128+tid] = sc;
        scbuf[192+tid] = betaa[tid] - mean*sc;
        sj[tid] = g_nidx[m0 + tid];
    }
    __syncthreads();

#pragma unroll
    for (int i = 0; i < 16; i++) {
        int idx = tid + i*256;
        int r = idx >> 6, k = idx & 63;
        float ha = g_hattn[(size_t)(m0+r)*64 + k];
        Ahr[r*68 + k] = fmaxf(ha*scbuf[128+k] + scbuf[192+k], 0.0f);
        float hp = g_hpos[(size_t)(m0+r)*64 + k];
        Apr[r*68 + k] = fmaxf(hp*scbuf[k] + scbuf[64+k], 0.0f);
    }

    int q = warp & 3;
    int qg = (m0 >> 4) + q;
    int bb = qg >> 11;
    int r1 = mw + g, r2 = mw + g + 8;

    for (int half = 0; half < 2; half++) {
        int c0 = half * 128;

        // ---- pass 0: attn = relu_bn(hattn) @ Wa2 + ba2  -> attn_s
        {
            float acc[8][4] = {};
            for (int k0 = 0; k0 < 64; k0 += 16) {
                __syncthreads();
#pragma unroll
                for (int i = 0; i < 8; i++) {
                    int idx = tid + i*256;
                    int r = idx >> 7, c = idx & 127;
                    float x = Wa2[(size_t)(k0+r)*D + c0 + c];
                    uint32_t hi = f2tf(x);
                    Bh[r*136 + c] = __uint_as_float(hi);
                    Bl[r*136 + c] = __uint_as_float(f2tf(x - __uint_as_float(hi)));
                }
                __syncthreads();
#pragma unroll
                for (int ks = 0; ks < 16; ks += 8) {
                    uint32_t ah[4], al[4];
                    {
                        float x0 = Ahr[(mw+g  )*68 + k0+ks+tg  ];
                        float x1 = Ahr[(mw+g+8)*68 + k0+ks+tg  ];
                        float x2 = Ahr[(mw+g  )*68 + k0+ks+tg+4];
                        float x3 = Ahr[(mw+g+8)*68 + k0+ks+tg+4];
                        ah[0] = f2tf(x0); al[0] = f2tf(x0 - __uint_as_float(ah[0]));
                        ah[1] = f2tf(x1); al[1] = f2tf(x1 - __uint_as_float(ah[1]));
                        ah[2] = f2tf(x2); al[2] = f2tf(x2 - __uint_as_float(ah[2]));
                        ah[3] = f2tf(x3); al[3] = f2tf(x3 - __uint_as_float(ah[3]));
                    }
#pragma unroll
                    for (int ni = 0; ni < 8; ni++) {
                        uint32_t bhf[2], blf[2];
                        bhf[0] = __float_as_uint(Bh[(ks+tg  )*136 + nw + ni*8 + g]);
                        bhf[1] = __float_as_uint(Bh[(ks+tg+4)*136 + nw + ni*8 + g]);
                        blf[0] = __float_as_uint(Bl[(ks+tg  )*136 + nw + ni*8 + g]);
                        blf[1] = __float_as_uint(Bl[(ks+tg+4)*136 + nw + ni*8 + g]);
                        mma8(acc[ni], ah, bhf);
                        mma8(acc[ni], ah, blf);
                        mma8(acc[ni], al, bhf);
                    }
                }
            }
#pragma unroll
            for (int ni = 0; ni < 8; ni++) {
                int c = nw + ni*8 + 2*tg;
                float b0 = ba2[c0 + c], b1 = ba2[c0 + c + 1];
                attn_s[r1*132 + c]     = acc[ni][0] + b0;
                attn_s[r1*132 + c + 1] = acc[ni][1] + b1;
                attn_s[r2*132 + c]     = acc[ni][2] + b0;
                attn_s[r2*132 + c + 1] = acc[ni][3] + b1;
            }
        }
        __syncthreads();

        // ---- softmax over 16 neighbors, in place (attn_s -> weights)
#pragma unroll
        for (int e = tid; e < 512; e += 256) {
            int qq = e >> 7;
            int c = e & 127;
            int mrow = qq*16;
            float mx = -1e30f;
#pragma unroll
            for (int k = 0; k < KNN; k++)
                mx = fmaxf(mx, attn_s[(mrow+k)*132 + c]);
            float w[KNN]; float s = 0.f;
#pragma unroll
            for (int k = 0; k < KNN; k++) {
                w[k] = __expf(attn_s[(mrow+k)*132 + c] - mx);
                s += w[k];
            }
            float inv = 1.0f / s;
#pragma unroll
            for (int k = 0; k < KNN; k++)
                attn_s[(mrow+k)*132 + c] = w[k] * inv;
        }
        __syncthreads();

        // ---- pass 1: pos GEMM + fused (v+pos)*w aggregation
        {
            float acc[8][4] = {};
            for (int k0 = 0; k0 < 64; k0 += 16) {
                __syncthreads();
#pragma unroll
                for (int i = 0; i < 8; i++) {
                    int idx = tid + i*256;
                    int r = idx >> 7, c = idx & 127;
                    float x = Wp2[(size_t)(k0+r)*D + c0 + c];
                    uint32_t hi = f2tf(x);
                    Bh[r*136 + c] = __uint_as_float(hi);
                    Bl[r*136 + c] = __uint_as_float(f2tf(x - __uint_as_float(hi)));
                }
                __syncthreads();
#pragma unroll
                for (int ks = 0; ks < 16; ks += 8) {
                    uint32_t ah[4], al[4];
                    {
                        float x0 = Apr[(mw+g  )*68 + k0+ks+tg  ];
                        float x1 = Apr[(mw+g+8)*68 + k0+ks+tg  ];
                        float x2 = Apr[(mw+g  )*68 + k0+ks+tg+4];
                        float x3 = Apr[(mw+g+8)*68 + k0+ks+tg+4];
                        ah[0] = f2tf(x0); al[0] = f2tf(x0 - __uint_as_float(ah[0]));
                        ah[1] = f2tf(x1); al[1] = f2tf(x1 - __uint_as_float(ah[1]));
                        ah[2] = f2tf(x2); al[2] = f2tf(x2 - __uint_as_float(ah[2]));
                        ah[3] = f2tf(x3); al[3] = f2tf(x3 - __uint_as_float(ah[3]));
                    }
#pragma unroll
                    for (int ni = 0; ni < 8; ni++) {
                        uint32_t bhf[2], blf[2];
                        bhf[0] = __float_as_uint(Bh[(ks+tg  )*136 + nw + ni*8 + g]);
                        bhf[1] = __float_as_uint(Bh[(ks+tg+4)*136 + nw + ni*8 + g]);
                        blf[0] = __float_as_uint(Bl[(ks+tg  )*136 + nw + ni*8 + g]);
                        blf[1] = __float_as_uint(Bl[(ks+tg+4)*136 + nw + ni*8 + g]);
                        mma8(acc[ni], ah, bhf);
                        mma8(acc[ni], ah, blf);
                        mma8(acc[ni], al, bhf);
                    }
                }
            }
            // epilogue: x[qg, c] = sum_16 (pos + bias + v) * w, via butterfly over g
            int j1 = sj[r1], j2 = sj[r2];
            const float* v1p = &g_v[(((size_t)bb<<11) + j1)*D + c0];
            const float* v2p = &g_v[(((size_t)bb<<11) + j2)*D + c0];
#pragma unroll
            for (int ni = 0; ni < 8; ni++) {
                int c = nw + ni*8 + 2*tg;
                float b0 = bp2[c0 + c], b1 = bp2[c0 + c + 1];
                float2 v1 = *(const float2*)&v1p[c];
                float2 v2 = *(const float2*)&v2p[c];
                float w1a = attn_s[r1*132 + c], w1b = attn_s[r1*132 + c + 1];
                float w2a = attn_s[r2*132 + c], w2b = attn_s[r2*132 + c + 1];
                float sA = (acc[ni][0] + b0 + v1.x)*w1a + (acc[ni][2] + b0 + v2.x)*w2a;
                float sB = (acc[ni][1] + b1 + v1.y)*w1b + (acc[ni][3] + b1 + v2.y)*w2b;
#pragma unroll
                for (int msk = 4; msk <= 16; msk <<= 1) {
                    sA += __shfl_xor_sync(0xffffffffu, sA, msk);
                    sB += __shfl_xor_sync(0xffffffffu, sB, msk);
                }
                if (g == 0)
                    *(float2*)&g_x[(size_t)qg*D + c0 + c] = make_float2(sA, sB);
            }
        }
        __syncthreads();
    }
}

// =================================================================================
extern "C" void kernel_launch(void* const* d_in, const int* in_sizes, int n_in,
                              void* d_out, int out_size)
{
    const float* dec_x   = (const float*)d_in[0];
    const float* dec_pc  = (const float*)d_in[1];
    const float* enc_x   = (const float*)d_in[2];
    const float* enc_pc  = (const float*)d_in[3];
    const float* W_pre1  = (const float*)d_in[4];
    const float* b_pre1  = (const float*)d_in[5];
    const float* W_pre2  = (const float*)d_in[6];
    const float* b_pre2  = (const float*)d_in[7];
    const float* Wq      = (const float*)d_in[8];
    const float* bq      = (const float*)d_in[9];
    const float* Wk      = (const float*)d_in[10];
    const float* bk      = (const float*)d_in[11];
    const float* Wv      = (const float*)d_in[12];
    const float* bv      = (const float*)d_in[13];
    const float* Wp1     = (const float*)d_in[14];
    const float* bp1     = (const float*)d_in[15];
    const float* gp      = (const float*)d_in[16];
    const float* betap   = (const float*)d_in[17];
    const float* Wp2     = (const float*)d_in[18];
    const float* bp2     = (const float*)d_in[19];
    const float* Wa1     = (const float*)d_in[20];
    const float* ba1     = (const float*)d_in[21];
    const float* ga      = (const float*)d_in[22];
    const float* betaa   = (const float*)d_in[23];
    const float* Wa2     = (const float*)d_in[24];
    const float* ba2     = (const float*)d_in[25];
    const float* W_post1 = (const float*)d_in[26];
    const float* b_post1 = (const float*)d_in[27];
    const float* W_post2 = (const float*)d_in[28];
    const float* b_post2 = (const float*)d_in[29];
    float* out = (float*)d_out;

    float *p_x;
    cudaGetSymbolAddress((void**)&p_x, g_x);

    const int M8 = B*N1;                         // 8192
    const int PH1_SMEM  = TF32_SMEM_FLOATS*4;                 // 71680 (>= FPS 49152)
    const int PH2_SMEM  = 8192*4 + 512*KNN*8;                 // 98304
    const int ATTN_SMEM = (64*68*2 + 64*132 + 16*136*2 + 256)*4 + 64*4;
    const int POST_SMEM = TF32_SMEM_FLOATS*4;

    // 1) phase-1: FPS || pre-projections || weight precomputes || cvec || zero
    cudaFuncSetAttribute(phase1_kernel, cudaFuncAttributeMaxDynamicSharedMemorySize, PH1_SMEM);
    phase1_kernel<<<271, 512, PH1_SMEM>>>(dec_pc, enc_pc, dec_x, enc_x,
                                          W_pre1, b_pre1, W_pre2, b_pre2,
                                          Wk, Wq, Wa1, Wp2, bk, bq, bp2, ba1);

    // 2) gather sampled features + coords
    gather_kernel<<<M8/4, 256>>>(dec_pc, enc_pc);

    // 3) phase-2: KNN || qa/ka || v
    cudaFuncSetAttribute(phase2_kernel, cudaFuncAttributeMaxDynamicSharedMemorySize, PH2_SMEM);
    phase2_kernel<<<288, 512, PH2_SMEM>>>(dec_pc, Wv, bv);

    // 4) hpos + fused pos-BN stats
    hpos_kernel<<<512, 256>>>(dec_pc, Wp1, bp1);

    // 5) hattn (inline pos-BN finalize) + fused attn-BN stats
    hattn_kernel<<<MROW/64, 256>>>(gp, betap);

    // 6) fused attn GEMM + softmax + pos GEMM + aggregation
    cudaFuncSetAttribute(attnout_kernel, cudaFuncAttributeMaxDynamicSharedMemorySize, ATTN_SMEM);
    attnout_kernel<<<MROW/64, 256, ATTN_SMEM>>>(Wa2, ba2, Wp2, bp2, gp, betap, ga, betaa);

    // 7) outputs (both post GEMMs in one launch)
    float* out1 = out;                                   // [B,N1,256]
    float* opc1 = out + (size_t)M8*D;                    // [B,N1,3]
    float* out2 = opc1 + (size_t)M8*3;                   // [B,N1,256]
    float* opc2 = out2 + (size_t)M8*D;                   // [B,N2,3]
    cudaFuncSetAttribute(gemm_post_kernel, cudaFuncAttributeMaxDynamicSharedMemorySize, POST_SMEM);
    gemm_post_kernel<<<dim3(2, M8/128, 2), 512, POST_SMEM>>>(p_x, W_post1, b_post1, dec_x, out1,
                                                             W_post2, b_post2, out2);
    cudaMemcpyAsync(opc1, dec_pc, (size_t)M8*3*sizeof(float), cudaMemcpyDeviceToDevice);
    cudaMemcpyAsync(opc2, enc_pc, (size_t)B*N2*3*sizeof(float), cudaMemcpyDeviceToDevice);
}

// round 10
// speedup vs baseline: 1.0957x; 1.0957x over previous
#include <cuda_runtime.h>
#include <cuda_bf16.h>
#include <math.h>
#include <stdint.h>

// Problem constants
#define B    4
#define N1   2048
#define N2   2048
#define NC   4096           // N1+N2
#define D    256
#define HP   64
#define HA   64
#define KNN  16
#define MROW (B*N1*KNN)     // 131072
#define INV_MROW (1.0f/131072.0f)

// ---------------- scratch (device globals; no allocation allowed) -------------
__device__ float g_dx  [B*N1*D];
__device__ float g_ex  [B*N2*D];
__device__ float g_sx  [B*N1*D];
__device__ float g_spc [B*N1*3];
__device__ int   g_fidx[B*N1];
__device__ float g_qa  [B*N1*HA];
__device__ float g_ka  [B*N1*HA];
__device__ float g_v   [B*N1*D];
__device__ int   g_nidx[B*N1*KNN];
__device__ float g_hpos [MROW*HP];
__device__ float g_hattn[MROW*HA];
__device__ float g_x   [B*N1*D];
__device__ float g_WkWa1[D*HA];
__device__ float g_WqWa1[D*HA];
__device__ float g_Wp2a [HP*HA];
__device__ float g_cvec [HA];
__device__ float g_Wa2hl[HA*D*2];   // interleaved tf32 hi/lo planes of Wa2
__device__ float g_Wp2hl[HP*D*2];   // interleaved tf32 hi/lo planes of Wp2
// [0:64) psum [64:128) psq [128:192) asum [192:256) asq
__device__ float g_stats[256];

// ================= tf32 mma helpers ===========================================
__device__ __forceinline__ uint32_t f2tf(float x) {
    uint32_t r; asm("cvt.rna.tf32.f32 %0, %1;" : "=r"(r) : "f"(x)); return r;
}
__device__ __forceinline__ void mma8(float* d, const uint32_t* a, const uint32_t* b) {
    asm volatile("mma.sync.aligned.m16n8k8.row.col.f32.tf32.tf32.f32 "
        "{%0,%1,%2,%3}, {%4,%5,%6,%7}, {%8,%9}, {%0,%1,%2,%3};"
        : "+f"(d[0]), "+f"(d[1]), "+f"(d[2]), "+f"(d[3])
        : "r"(a[0]), "r"(a[1]), "r"(a[2]), "r"(a[3]), "r"(b[0]), "r"(b[1]));
}

// ------ tf32x2 GEMM body: 128x128 tile, 512 threads, hi/lo planes, 3-mma ------
#define APITCH 36
#define BPITCH 136
#define TF32_SMEM_FLOATS (2*128*APITCH + 2*32*BPITCH)

__device__ __forceinline__ void gemm_tf32_body(
    const float* __restrict__ A, const float* __restrict__ W,
    const float* __restrict__ bias, const float* __restrict__ resid,
    float* __restrict__ C, int bx, int by, int N, int K)
{
    extern __shared__ float smext[];
    float* AHs = smext;
    float* ALs = AHs + 128*APITCH;
    float* BHs = ALs + 128*APITCH;
    float* BLs = BHs + 32*BPITCH;
    int tid = threadIdx.x;
    int row0 = by * 128, col0 = bx * 128;
    int warp = tid >> 5, lane = tid & 31;
    int mw = (warp & 3) * 32, nw = (warp >> 2) * 32;
    int g = lane >> 2, tg = lane & 3;
    float acc[8][4] = {};
    for (int k0 = 0; k0 < K; k0 += 32) {
#pragma unroll
        for (int i = 0; i < 2; i++) {
            int idx = tid + i*512;
            int r = idx >> 3, c4 = (idx & 7) * 4;
            float4 v = *(const float4*)&A[(size_t)(row0+r)*K + k0 + c4];
            float xs[4] = {v.x, v.y, v.z, v.w};
#pragma unroll
            for (int u = 0; u < 4; u++) {
                uint32_t hi = f2tf(xs[u]);
                AHs[r*APITCH + c4+u] = __uint_as_float(hi);
                ALs[r*APITCH + c4+u] = __uint_as_float(f2tf(xs[u] - __uint_as_float(hi)));
            }
        }
#pragma unroll
        for (int i = 0; i < 2; i++) {
            int idx = tid + i*512;
            int r = idx >> 5, c4 = (idx & 31) * 4;
            float4 v = *(const float4*)&W[(size_t)(k0+r)*N + col0 + c4];
            float xs[4] = {v.x, v.y, v.z, v.w};
#pragma unroll
            for (int u = 0; u < 4; u++) {
                uint32_t hi = f2tf(xs[u]);
                BHs[r*BPITCH + c4+u] = __uint_as_float(hi);
                BLs[r*BPITCH + c4+u] = __uint_as_float(f2tf(xs[u] - __uint_as_float(hi)));
            }
        }
        __syncthreads();
#pragma unroll
        for (int ks = 0; ks < 32; ks += 8) {
            uint32_t ah[2][4], al[2][4], bh[4][2], bl[4][2];
#pragma unroll
            for (int mi = 0; mi < 2; mi++) {
                int rb = mw + mi*16;
                ah[mi][0] = __float_as_uint(AHs[(rb+g  )*APITCH + ks+tg  ]);
                ah[mi][1] = __float_as_uint(AHs[(rb+g+8)*APITCH + ks+tg  ]);
                ah[mi][2] = __float_as_uint(AHs[(rb+g  )*APITCH + ks+tg+4]);
                ah[mi][3] = __float_as_uint(AHs[(rb+g+8)*APITCH + ks+tg+4]);
                al[mi][0] = __float_as_uint(ALs[(rb+g  )*APITCH + ks+tg  ]);
                al[mi][1] = __float_as_uint(ALs[(rb+g+8)*APITCH + ks+tg  ]);
                al[mi][2] = __float_as_uint(ALs[(rb+g  )*APITCH + ks+tg+4]);
                al[mi][3] = __float_as_uint(ALs[(rb+g+8)*APITCH + ks+tg+4]);
            }
#pragma unroll
            for (int ni = 0; ni < 4; ni++) {
                bh[ni][0] = __float_as_uint(BHs[(ks+tg  )*BPITCH + nw + ni*8 + g]);
                bh[ni][1] = __float_as_uint(BHs[(ks+tg+4)*BPITCH + nw + ni*8 + g]);
                bl[ni][0] = __float_as_uint(BLs[(ks+tg  )*BPITCH + nw + ni*8 + g]);
                bl[ni][1] = __float_as_uint(BLs[(ks+tg+4)*BPITCH + nw + ni*8 + g]);
            }
#pragma unroll
            for (int mi = 0; mi < 2; mi++)
#pragma unroll
                for (int ni = 0; ni < 4; ni++) {
                    mma8(acc[mi*4+ni], ah[mi], bh[ni]);
                    mma8(acc[mi*4+ni], ah[mi], bl[ni]);
                    mma8(acc[mi*4+ni], al[mi], bh[ni]);
                }
        }
        __syncthreads();
    }
#pragma unroll
    for (int mi = 0; mi < 2; mi++) {
#pragma unroll
        for (int ni = 0; ni < 4; ni++) {
            int c = col0 + nw + ni*8 + 2*tg;
            float b0 = bias ? bias[c]   : 0.f;
            float b1 = bias ? bias[c+1] : 0.f;
            size_t r1 = (size_t)(row0 + mw + mi*16 + g);
            size_t r2 = r1 + 8;
            float v00 = acc[mi*4+ni][0] + b0, v01 = acc[mi*4+ni][1] + b1;
            float v10 = acc[mi*4+ni][2] + b0, v11 = acc[mi*4+ni][3] + b1;
            if (resid) {
                v00 += resid[r1*N+c]; v01 += resid[r1*N+c+1];
                v10 += resid[r2*N+c]; v11 += resid[r2*N+c+1];
            }
            *(float2*)&C[r1*N + c] = make_float2(v00, v01);
            *(float2*)&C[r2*N + c] = make_float2(v10, v11);
        }
    }
}

// ---------------- combined post-GEMMs (z selects output head) ------------------
__global__ void __launch_bounds__(512)
gemm_post_kernel(const float* __restrict__ X,
                 const float* __restrict__ W1, const float* __restrict__ b1,
                 const float* __restrict__ resid1, float* __restrict__ out1,
                 const float* __restrict__ W2, const float* __restrict__ b2,
                 float* __restrict__ out2)
{
    if (blockIdx.z == 0)
        gemm_tf32_body(X, W1, b1, resid1, out1, blockIdx.x, blockIdx.y, D, D);
    else
        gemm_tf32_body(X, W2, b2, nullptr, out2, blockIdx.x, blockIdx.y, D, D);
}

// ---------------- FPS body: 512 threads, register-resident coords (R8) ---------
__device__ void fps_body(int b, const float* __restrict__ decpc,
                         const float* __restrict__ encpc)
{
    extern __shared__ float smext[];
    float* sx = smext;
    float* sy = smext + NC;
    float* sz = smext + 2*NC;
    __shared__ unsigned long long swk[2][16];

    int tid = threadIdx.x;
    int wid = tid >> 5, lid = tid & 31;

    for (int j = tid; j < N1; j += 512) {
        sx[j] = decpc[((size_t)b*N1 + j)*3 + 0];
        sy[j] = decpc[((size_t)b*N1 + j)*3 + 1];
        sz[j] = decpc[((size_t)b*N1 + j)*3 + 2];
        sx[N1+j] = encpc[((size_t)b*N2 + j)*3 + 0];
        sy[N1+j] = encpc[((size_t)b*N2 + j)*3 + 1];
        sz[N1+j] = encpc[((size_t)b*N2 + j)*3 + 2];
    }
    if (tid == 0) g_fidx[b*N1] = 0;
    int cur = 0;
    __syncthreads();

    float X[8], Y[8], Z[8], md[8];
#pragma unroll
    for (int t = 0; t < 8; t++) {
        int j = tid + t*512;
        X[t] = sx[j]; Y[t] = sy[j]; Z[t] = sz[j];
        md[t] = 1e10f;
    }

    for (int i = 1; i < N1; i++) {
        float lx = sx[cur], ly = sy[cur], lz = sz[cur];
        float bestv = -1.0f; int besti = 0x7fffffff;
#pragma unroll
        for (int t = 0; t < 8; t++) {
            float ddx = X[t]-lx, ddy = Y[t]-ly, ddz = Z[t]-lz;
            float d = ddx*ddx + ddy*ddy + ddz*ddz;
            float mm = fminf(md[t], d);
            md[t] = mm;
            if (mm > bestv) { bestv = mm; besti = tid + t*512; }
        }
        unsigned kb = __float_as_uint(bestv);
        kb = ((int)kb < 0) ? ~kb : (kb | 0x80000000u);
        unsigned mk;
        asm("redux.sync.max.u32 %0, %1, 0xffffffff;" : "=r"(mk) : "r"(kb));
        unsigned idxc = (kb == mk) ? (unsigned)besti : 0xffffffffu;
        unsigned mi;
        asm("redux.sync.min.u32 %0, %1, 0xffffffff;" : "=r"(mi) : "r"(idxc));
        int pb = i & 1;
        if (lid == 0)
            swk[pb][wid] = (((unsigned long long)mk) << 32) | (unsigned long long)(0xffffffffu - mi);
        __syncthreads();
        unsigned long long best = swk[pb][0];
#pragma unroll
        for (int w = 1; w < 16; w++) {
            unsigned long long o = swk[pb][w];
            best = (o > best) ? o : best;
        }
        cur = (int)(0xffffffffu - (unsigned)best);
        if (tid == 0) g_fidx[b*N1 + i] = cur;
    }
}

// ---------------- small 64-col GEMM body (weight precomputes), 512 thr --------
#define TBM 64
#define TBK 16
__device__ void gemm64_body(const float* __restrict__ A, const float* __restrict__ W,
                            float* __restrict__ C, int row0, int N, int K)
{
    __shared__ float As64[TBK][TBM];
    __shared__ float Bs64[TBK][64];
    int tid = threadIdx.x;
    for (int k0 = 0; k0 < K; k0 += TBK) {
#pragma unroll
        for (int u = 0; u < 2; u++) {
            int e = tid + u*512;
            int r = e >> 4, c = e & 15;
            As64[c][r] = A[(size_t)(row0 + r)*K + k0 + c];
            int r2 = e >> 6, c2 = e & 63;
            Bs64[r2][c2] = W[(size_t)(k0 + r2)*N + c2];
        }
        __syncthreads();
        if (tid < 256) {
            int tx = tid & 15, ty = tid >> 4;
            float acc[4][4] = {};
#pragma unroll
            for (int kk = 0; kk < TBK; kk++) {
                float a[4], bb[4];
#pragma unroll
                for (int i = 0; i < 4; i++) a[i] = As64[kk][ty*4+i];
#pragma unroll
                for (int j = 0; j < 4; j++) bb[j] = Bs64[kk][tx*4+j];
#pragma unroll
                for (int i = 0; i < 4; i++)
#pragma unroll
                    for (int j = 0; j < 4; j++)
                        acc[i][j] += a[i]*bb[j];
            }
#pragma unroll
            for (int i = 0; i < 4; i++)
#pragma unroll
                for (int j = 0; j < 4; j++) {
                    size_t off = (size_t)(row0 + ty*4 + i)*N + tx*4 + j;
                    if (k0 == 0) C[off] = acc[i][j];
                    else         C[off] += acc[i][j];
                }
        }
        __syncthreads();
    }
}

// ---------------- cvec body: (bk - bq + bp2) @ Wa1 + ba1, 512 thr --------------
__device__ void cvec_body(const float* __restrict__ bk, const float* __restrict__ bq,
                          const float* __restrict__ bp2, const float* __restrict__ Wa1,
                          const float* __restrict__ ba1)
{
    __shared__ float shc[512];
    int c = threadIdx.x & 63;
    int part = threadIdx.x >> 6;     // 0..7
    float s = 0.f;
    for (int i = part*32; i < part*32 + 32; i++)
        s += (bk[i] - bq[i] + bp2[i]) * Wa1[(size_t)i*HA + c];
    shc[threadIdx.x] = s;
    __syncthreads();
    if (part == 0) {
        float t = ba1[c];
#pragma unroll
        for (int p = 0; p < 8; p++) t += shc[p*64 + c];
        g_cvec[c] = t;
    }
}

// ---------------- weight hi/lo split body (once per launch) -------------------
__device__ void wsplit_body(const float* __restrict__ W, float* __restrict__ out, int n)
{
    for (int i = threadIdx.x; i < n; i += 512) {
        float x = W[i];
        uint32_t hi = f2tf(x);
        out[2*i]   = __uint_as_float(hi);
        out[2*i+1] = __uint_as_float(f2tf(x - __uint_as_float(hi)));
    }
}

// ---------------- phase-1 mega-kernel -----------------------------------------
// [0,4)=FPS [4,132)=pre1 [132,260)=pre2 [260,264)=WkWa1 [264,268)=WqWa1
// [268]=Wp2a [269]=cvec [270]=zero_stats [271]=split Wa2 [272]=split Wp2
__global__ void __launch_bounds__(512)
phase1_kernel(const float* __restrict__ dec_pc, const float* __restrict__ enc_pc,
              const float* __restrict__ dec_x,  const float* __restrict__ enc_x,
              const float* __restrict__ W_pre1, const float* __restrict__ b_pre1,
              const float* __restrict__ W_pre2, const float* __restrict__ b_pre2,
              const float* __restrict__ Wk, const float* __restrict__ Wq,
              const float* __restrict__ Wa1, const float* __restrict__ Wp2,
              const float* __restrict__ bk, const float* __restrict__ bq,
              const float* __restrict__ bp2, const float* __restrict__ ba1,
              const float* __restrict__ Wa2)
{
    int bid = blockIdx.x;
    if (bid < 4) {
        fps_body(bid, dec_pc, enc_pc);
    } else if (bid < 132) {
        int t = bid - 4;
        gemm_tf32_body(dec_x, W_pre1, b_pre1, nullptr, g_dx, t & 1, t >> 1, D, D);
    } else if (bid < 260) {
        int t = bid - 132;
        gemm_tf32_body(enc_x, W_pre2, b_pre2, nullptr, g_ex, t & 1, t >> 1, D, D);
    } else if (bid < 264) {
        gemm64_body(Wk, Wa1, g_WkWa1, (bid-260)*64, HA, D);
    } else if (bid < 268) {
        gemm64_body(Wq, Wa1, g_WqWa1, (bid-264)*64, HA, D);
    } else if (bid == 268) {
        gemm64_body(Wp2, Wa1, g_Wp2a, 0, HA, D);
    } else if (bid == 269) {
        cvec_body(bk, bq, bp2, Wa1, ba1);
    } else if (bid == 270) {
        if (threadIdx.x < 256) g_stats[threadIdx.x] = 0.0f;
    } else if (bid == 271) {
        wsplit_body(Wa2, g_Wa2hl, HA*D);
    } else {
        wsplit_body(Wp2, g_Wp2hl, HP*D);
    }
}

// ---------------- gather sampled features + coords ----------------------------
__global__ void gather_kernel(const float* __restrict__ decpc,
                              const float* __restrict__ encpc)
{
    int row = blockIdx.x*4 + (threadIdx.x >> 6);
    int c4  = (threadIdx.x & 63) * 4;
    int b = row >> 11;
    int j = g_fidx[row];
    const float* src = (j < N1) ? &g_dx[((size_t)b*N1 + j)*D]
                                : &g_ex[((size_t)b*N2 + (j - N1))*D];
    *(float4*)&g_sx[(size_t)row*D + c4] = *(const float4*)&src[c4];
    if ((threadIdx.x & 63) < 3) {
        int cc = threadIdx.x & 63;
        const float* ps = (j < N1) ? &decpc[((size_t)b*N1 + j)*3]
                                   : &encpc[((size_t)b*N2 + (j - N1))*3];
        g_spc[(size_t)row*3 + cc] = ps[cc];
    }
}

// ---------------- N=64 GEMM body for 512 threads (qa/ka) -----------------------
__device__ void n64_body_512(const float* __restrict__ A, const float* __restrict__ W,
                             float* __restrict__ C, int row0)
{
    __shared__ float Asq[16][132];
    __shared__ float Bsq[16][64];
    int tid = threadIdx.x;
    int tx = tid & 15, ty = tid >> 4;          // ty 0..31
    float acc[4][4] = {};
    for (int k0 = 0; k0 < D; k0 += 16) {
        {
            int r = tid >> 2, kq = (tid & 3) * 4;
            float4 va = *(const float4*)&A[(size_t)(row0 + r)*D + k0 + kq];
            Asq[kq+0][r] = va.x; Asq[kq+1][r] = va.y;
            Asq[kq+2][r] = va.z; Asq[kq+3][r] = va.w;
        }
        if (tid < 256) {
            int r = tid >> 4, cq = (tid & 15) * 4;
            *(float4*)&Bsq[r][cq] = *(const float4*)&W[(size_t)(k0 + r)*HA + cq];
        }
        __syncthreads();
#pragma unroll
        for (int kk = 0; kk < 16; kk++) {
            float a[4], bb[4];
#pragma unroll
            for (int i = 0; i < 4; i++) a[i] = Asq[kk][ty*4+i];
#pragma unroll
            for (int j = 0; j < 4; j++) bb[j] = Bsq[kk][tx*4+j];
#pragma unroll
            for (int i = 0; i < 4; i++)
#pragma unroll
                for (int j = 0; j < 4; j++)
                    acc[i][j] += a[i]*bb[j];
        }
        __syncthreads();
    }
#pragma unroll
    for (int i = 0; i < 4; i++)
#pragma unroll
        for (int j = 0; j < 4; j++)
            C[(size_t)(row0 + ty*4 + i)*HA + tx*4 + j] = acc[i][j];
}

// ---------------- phase-2 mega-kernel: KNN + qa/ka + v -------------------------
__global__ void __launch_bounds__(512)
phase2_kernel(const float* __restrict__ decpc,
              const float* __restrict__ Wv, const float* __restrict__ bv)
{
    int bid = blockIdx.x;
    if (bid < 32) {
        extern __shared__ float s2[];
        float* px = s2; float* py = px + 2048; float* pz = py + 2048; float* s2s = pz + 2048;
        unsigned long long* buf = (unsigned long long*)(s2 + 8192);
        int tid = threadIdx.x;
        int b = bid >> 3, qb = bid & 7;
        for (int m = tid; m < 2048; m += 512) {
            float x = g_spc[((size_t)b*N1 + m)*3 + 0];
            float y = g_spc[((size_t)b*N1 + m)*3 + 1];
            float z = g_spc[((size_t)b*N1 + m)*3 + 2];
            px[m] = x; py[m] = y; pz[m] = z;
            s2s[m] = x*x + y*y + z*z;
        }
        __syncthreads();
        int qi = tid & 255, h = tid >> 8;
        int q = qb*256 + qi;
        float qx = decpc[((size_t)b*N1 + q)*3 + 0];
        float qy = decpc[((size_t)b*N1 + q)*3 + 1];
        float qz = decpc[((size_t)b*N1 + q)*3 + 2];
        float s1 = qx*qx + qy*qy + qz*qz;
        float bd[KNN]; int bi[KNN];
#pragma unroll
        for (int t = 0; t < KNN; t++) { bd[t] = 1e30f; bi[t] = 0; }
        int mbase = h * 1024;
        for (int mm = 0; mm < 1024; mm++) {
            int m = mbase + mm;
            float d = s1 + s2s[m] - 2.0f*(qx*px[m] + qy*py[m] + qz*pz[m]);
            if (d < bd[KNN-1]) {
                bd[KNN-1] = d; bi[KNN-1] = m;
#pragma unroll
                for (int t = KNN-1; t > 0; t--) {
                    if (bd[t] < bd[t-1]) {
                        float td = bd[t]; bd[t] = bd[t-1]; bd[t-1] = td;
                        int   ti = bi[t]; bi[t] = bi[t-1]; bi[t-1] = ti;
                    }
                }
            }
        }
#pragma unroll
        for (int t = 0; t < KNN; t++) {
            unsigned u = __float_as_uint(bd[t]);
            u = ((int)u < 0) ? ~u : (u | 0x80000000u);
            buf[(size_t)tid*KNN + t] = (((unsigned long long)u) << 32) | (unsigned)bi[t];
        }
        __syncthreads();
        if (h == 0) {
            const unsigned long long* A_ = &buf[(size_t)qi*KNN];
            const unsigned long long* B_ = &buf[(size_t)(qi+256)*KNN];
            int* outp = &g_nidx[((size_t)b*N1 + q)*KNN];
            int ia = 0, ib = 0;
#pragma unroll
            for (int o = 0; o < KNN; o++) {
                unsigned long long av = A_[ia], bv_ = B_[ib];
                if ((av >> 32) <= (bv_ >> 32)) { outp[o] = (int)(unsigned)av; ia++; }
                else                           { outp[o] = (int)(unsigned)bv_; ib++; }
            }
        }
    } else if (bid < 160) {
        int t = bid - 32;
        int sel = t >> 6, tile = t & 63;
        n64_body_512(sel ? g_sx : g_dx, sel ? g_WkWa1 : g_WqWa1,
                     sel ? g_ka : g_qa, tile*128);
    } else {
        int t = bid - 160;
        gemm_tf32_body(g_sx, Wv, bv, nullptr, g_v, t & 1, t >> 1, D, D);
    }
}

// ---------------- hpos + fused BN stats ----------------------------------------
__global__ void __launch_bounds__(256)
hpos_kernel(const float* __restrict__ decpc,
            const float* __restrict__ Wp1,
            const float* __restrict__ bp1)
{
    int tid = threadIdx.x;
    int c = tid & 63;
    int rg = tid >> 6;
    float w0 = Wp1[c], w1 = Wp1[64+c], w2 = Wp1[128+c], bb = bp1[c];
    float s = 0.f, s2 = 0.f;
    int base = blockIdx.x * 256;
    for (int it = 0; it < 64; it++) {
        int m = base + it*4 + rg;
        int b = m >> 15;
        int n = (m >> 4) & 2047;
        int j = g_nidx[m];
        const float* pp = &g_spc[((size_t)b*N1 + j)*3];
        const float* qq = &decpc[((size_t)b*N1 + n)*3];
        float p0 = pp[0]-qq[0], p1 = pp[1]-qq[1], p2 = pp[2]-qq[2];
        float h = p0*w0 + p1*w1 + p2*w2 + bb;
        g_hpos[(size_t)m*HP + c] = h;
        s += h; s2 += h*h;
    }
    __shared__ float sh[256], sh2[256];
    sh[tid] = s; sh2[tid] = s2;
    __syncthreads();
    if (rg == 0) {
        atomicAdd(&g_stats[c],    sh[c] + sh[64+c] + sh[128+c] + sh[192+c]);
        atomicAdd(&g_stats[64+c], sh2[c] + sh2[64+c] + sh2[128+c] + sh2[192+c]);
    }
}

// ---- hattn = relu(bn_pos(hp)) @ Wp2a + ka[gather] - qa + cvec + stats --------
__global__ void __launch_bounds__(256)
hattn_kernel(const float* __restrict__ gp, const float* __restrict__ betap)
{
    __shared__ float Aw[64][65];
    __shared__ float Bw[64*64];
    __shared__ float psc[64], psh[64];
    __shared__ float rs[16][64], rs2[16][64];
    int tid = threadIdx.x;
    int m0 = blockIdx.x * 64;
    if (tid < 64) {
        float mean = g_stats[tid] * INV_MROW;
        float var  = g_stats[64+tid] * INV_MROW - mean*mean;
        float sc = gp[tid]*rsqrtf(var + 1e-5f);
        psc[tid] = sc;
        psh[tid] = betap[tid] - mean*sc;
    }
    __syncthreads();
#pragma unroll
    for (int i = 0; i < 16; i++) {
        int idx = tid + i*256;
        int r = idx >> 6, k = idx & 63;
        float h = g_hpos[(size_t)(m0+r)*64 + k];
        Aw[r][k] = fmaxf(h*psc[k] + psh[k], 0.0f);
        Bw[idx] = g_Wp2a[idx];
    }
    __syncthreads();
    int tx = tid & 15, ty = tid >> 4;
    float acc[4][4] = {};
#pragma unroll 4
    for (int kk = 0; kk < 64; kk++) {
        float a[4], bb[4];
#pragma unroll
        for (int i = 0; i < 4; i++) a[i] = Aw[ty*4+i][kk];
#pragma unroll
        for (int j = 0; j < 4; j++) bb[j] = Bw[kk*64 + tx*4 + j];
#pragma unroll
        for (int i = 0; i < 4; i++)
#pragma unroll
            for (int j = 0; j < 4; j++)
                acc[i][j] += a[i]*bb[j];
    }
    float ps[4] = {0,0,0,0}, ps2[4] = {0,0,0,0};
#pragma unroll
    for (int i = 0; i < 4; i++) {
        int m = m0 + ty*4 + i;
        int b = m >> 15;
        int n = (m >> 4) & 2047;
        int jj = g_nidx[m];
        const float* kar = &g_ka[(((size_t)b<<11) + jj)*HA];
        const float* qar = &g_qa[(((size_t)b<<11) + n )*HA];
#pragma unroll
        for (int j = 0; j < 4; j++) {
            int c = tx*4 + j;
            float v = acc[i][j] + kar[c] - qar[c] + g_cvec[c];
            g_hattn[(size_t)m*HA + c] = v;
            ps[j] += v; ps2[j] += v*v;
        }
    }
#pragma unroll
    for (int j = 0; j < 4; j++) {
        rs[ty][tx*4+j] = ps[j];
        rs2[ty][tx*4+j] = ps2[j];
    }
    __syncthreads();
    if (tid < 64) {
        float s = 0.f, s2 = 0.f;
#pragma unroll
        for (int t = 0; t < 16; t++) { s += rs[t][tid]; s2 += rs2[t][tid]; }
        atomicAdd(&g_stats[128+tid], s);
        atomicAdd(&g_stats[192+tid], s2);
    }
}

// ---- fused: attn/pos GEMMs via tf32x2 mma + softmax(K) + agg -> g_x ----------
// grid 2048; block handles 64 rows x 256 cols (two 128-col halves, A reused)
// B planes come pre-split from g_Wa2hl / g_Wp2hl (interleaved hi/lo).
__global__ void __launch_bounds__(256)
attnout_kernel(const float* __restrict__ ba2,
               const float* __restrict__ bp2,
               const float* __restrict__ gp, const float* __restrict__ betap,
               const float* __restrict__ ga, const float* __restrict__ betaa)
{
    extern __shared__ float sm[];
    float* Ahr    = sm;                 // [64][68]
    float* Apr    = Ahr + 64*68;        // [64][68]
    float* attn_s = Apr + 64*68;        // [64][132]
    float* pos_s  = attn_s + 64*132;    // [64][132]
    float* Bh     = pos_s + 64*132;     // [16][136]
    float* Bl     = Bh + 16*136;        // [16][136]
    float* scbuf  = Bl + 16*136;        // psc,psh,asc,ash [4][64]
    int*   sj     = (int*)(scbuf + 256);// [64]

    int tid = threadIdx.x;
    int m0 = blockIdx.x * 64;
    int warp = tid >> 5, lane = tid & 31;
    int mw = (warp & 3) * 16, nw = (warp >> 2) * 64;
    int g = lane >> 2, tg = lane & 3;

    if (tid < 64) {
        float mean = g_stats[tid] * INV_MROW;
        float var  = g_stats[64+tid] * INV_MROW - mean*mean;
        float sc = gp[tid]*rsqrtf(var + 1e-5f);
        scbuf[tid] = sc;
        scbuf[64+tid] = betap[tid] - mean*sc;
        mean = g_stats[128+tid] * INV_MROW;
        var  = g_stats[192+tid] * INV_MROW - mean*mean;
        sc = ga[tid]*rsqrtf(var + 1e-5f);
        scbuf[128+tid] = sc;
        scbuf[192+tid] = betaa[tid] - mean*sc;
        sj[tid] = g_nidx[m0 + tid];
    }
    __syncthreads();

#pragma unroll
    for (int i = 0; i < 16; i++) {
        int idx = tid + i*256;
        int r = idx >> 6, k = idx & 63;
        float ha = g_hattn[(size_t)(m0+r)*64 + k];
        Ahr[r*68 + k] = fmaxf(ha*scbuf[128+k] + scbuf[192+k], 0.0f);
        float hp = g_hpos[(size_t)(m0+r)*64 + k];
        Apr[r*68 + k] = fmaxf(hp*scbuf[k] + scbuf[64+k], 0.0f);
    }

    for (int half = 0; half < 2; half++) {
        int c0 = half * 128;
#pragma unroll
        for (int pass = 0; pass < 2; pass++) {
            const float* Whl  = pass ? g_Wp2hl : g_Wa2hl;
            const float* bsrc = pass ? bp2 : ba2;
            const float* Asm  = pass ? Apr : Ahr;
            float* Out = pass ? pos_s : attn_s;
            float acc[8][4] = {};
            for (int k0 = 0; k0 < 64; k0 += 16) {
                __syncthreads();
#pragma unroll
                for (int i = 0; i < 8; i++) {
                    int idx = tid + i*256;
                    int r = idx >> 7, c = idx & 127;
                    float2 hl = *(const float2*)&Whl[((size_t)(k0+r)*D + c0 + c)*2];
                    Bh[r*136 + c] = hl.x;
                    Bl[r*136 + c] = hl.y;
                }
                __syncthreads();
#pragma unroll
                for (int ks = 0; ks < 16; ks += 8) {
                    uint32_t ah[4], al[4];
                    {
                        float x0 = Asm[(mw+g  )*68 + k0+ks+tg  ];
                        float x1 = Asm[(mw+g+8)*68 + k0+ks+tg  ];
                        float x2 = Asm[(mw+g  )*68 + k0+ks+tg+4];
                        float x3 = Asm[(mw+g+8)*68 + k0+ks+tg+4];
                        ah[0] = f2tf(x0); al[0] = f2tf(x0 - __uint_as_float(ah[0]));
                        ah[1] = f2tf(x1); al[1] = f2tf(x1 - __uint_as_float(ah[1]));
                        ah[2] = f2tf(x2); al[2] = f2tf(x2 - __uint_as_float(ah[2]));
                        ah[3] = f2tf(x3); al[3] = f2tf(x3 - __uint_as_float(ah[3]));
                    }
#pragma unroll
                    for (int ni = 0; ni < 8; ni++) {
                        uint32_t bhf[2], blf[2];
                        bhf[0] = __float_as_uint(Bh[(ks+tg  )*136 + nw + ni*8 + g]);
                        bhf[1] = __float_as_uint(Bh[(ks+tg+4)*136 + nw + ni*8 + g]);
                        blf[0] = __float_as_uint(Bl[(ks+tg  )*136 + nw + ni*8 + g]);
                        blf[1] = __float_as_uint(Bl[(ks+tg+4)*136 + nw + ni*8 + g]);
                        mma8(acc[ni], ah, bhf);
                        mma8(acc[ni], ah, blf);
                        mma8(acc[ni], al, bhf);
                    }
                }
            }
#pragma unroll
            for (int ni = 0; ni < 8; ni++) {
                int c = nw + ni*8 + 2*tg;
                float b0 = bsrc[c0 + c], b1 = bsrc[c0 + c + 1];
                Out[(mw+g  )*132 + c]     = acc[ni][0] + b0;
                Out[(mw+g  )*132 + c + 1] = acc[ni][1] + b1;
                Out[(mw+g+8)*132 + c]     = acc[ni][2] + b0;
                Out[(mw+g+8)*132 + c + 1] = acc[ni][3] + b1;
            }
        }
        __syncthreads();

        // softmax over 16 neighbors + aggregation for this 128-col half
#pragma unroll
        for (int e = tid; e < 512; e += 256) {
            int q = e >> 7;            // 0..3
            int c = e & 127;
            int mrow = q*16;
            float mx = -1e30f;
#pragma unroll
            for (int k = 0; k < KNN; k++)
                mx = fmaxf(mx, attn_s[(mrow+k)*132 + c]);
            float w[KNN]; float s = 0.f;
#pragma unroll
            for (int k = 0; k < KNN; k++) {
                w[k] = __expf(attn_s[(mrow+k)*132 + c] - mx);
                s += w[k];
            }
            float inv = 1.0f / s;
            int qg = (m0 >> 4) + q;
            int b = qg >> 11;
            float x = 0.f;
#pragma unroll
            for (int k = 0; k < KNN; k++) {
                int j = sj[mrow + k];
                float vv = g_v[(((size_t)b<<11) + j)*D + c0 + c] + pos_s[(mrow+k)*132 + c];
                x += vv * w[k];
            }
            g_x[(size_t)qg*D + c0 + c] = x * inv;
        }
        __syncthreads();
    }
}

// =================================================================================
extern "C" void kernel_launch(void* const* d_in, const int* in_sizes, int n_in,
                              void* d_out, int out_size)
{
    const float* dec_x   = (const float*)d_in[0];
    const float* dec_pc  = (const float*)d_in[1];
    const float* enc_x   = (const float*)d_in[2];
    const float* enc_pc  = (const float*)d_in[3];
    const float* W_pre1  = (const float*)d_in[4];
    const float* b_pre1  = (const float*)d_in[5];
    const float* W_pre2  = (const float*)d_in[6];
    const float* b_pre2  = (const float*)d_in[7];
    const float* Wq      = (const float*)d_in[8];
    const float* bq      = (const float*)d_in[9];
    const float* Wk      = (const float*)d_in[10];
    const float* bk      = (const float*)d_in[11];
    const float* Wv      = (const float*)d_in[12];
    const float* bv      = (const float*)d_in[13];
    const float* Wp1     = (const float*)d_in[14];
    const float* bp1     = (const float*)d_in[15];
    const float* gp      = (const float*)d_in[16];
    const float* betap   = (const float*)d_in[17];
    const float* Wp2     = (const float*)d_in[18];
    const float* bp2     = (const float*)d_in[19];
    const float* Wa1     = (const float*)d_in[20];
    const float* ba1     = (const float*)d_in[21];
    const float* ga      = (const float*)d_in[22];
    const float* betaa   = (const float*)d_in[23];
    const float* Wa2     = (const float*)d_in[24];
    const float* ba2     = (const float*)d_in[25];
    const float* W_post1 = (const float*)d_in[26];
    const float* b_post1 = (const float*)d_in[27];
    const float* W_post2 = (const float*)d_in[28];
    const float* b_post2 = (const float*)d_in[29];
    float* out = (float*)d_out;

    float *p_x;
    cudaGetSymbolAddress((void**)&p_x, g_x);

    const int M8 = B*N1;                         // 8192
    const int PH1_SMEM  = TF32_SMEM_FLOATS*4;                 // 71680 (>= FPS 49152)
    const int PH2_SMEM  = 8192*4 + 512*KNN*8;                 // 98304
    const int ATTN_SMEM = (64*68*2 + 64*132*2 + 16*136*2 + 256)*4 + 64*4;
    const int POST_SMEM = TF32_SMEM_FLOATS*4;

    // 1) phase-1: FPS || pre-projections || weight precomputes || splits || zero
    cudaFuncSetAttribute(phase1_kernel, cudaFuncAttributeMaxDynamicSharedMemorySize, PH1_SMEM);
    phase1_kernel<<<273, 512, PH1_SMEM>>>(dec_pc, enc_pc, dec_x, enc_x,
                                          W_pre1, b_pre1, W_pre2, b_pre2,
                                          Wk, Wq, Wa1, Wp2, bk, bq, bp2, ba1, Wa2);

    // 2) gather sampled features + coords
    gather_kernel<<<M8/4, 256>>>(dec_pc, enc_pc);

    // 3) phase-2: KNN || qa/ka || v
    cudaFuncSetAttribute(phase2_kernel, cudaFuncAttributeMaxDynamicSharedMemorySize, PH2_SMEM);
    phase2_kernel<<<288, 512, PH2_SMEM>>>(dec_pc, Wv, bv);

    // 4) hpos + fused pos-BN stats
    hpos_kernel<<<512, 256>>>(dec_pc, Wp1, bp1);

    // 5) hattn (inline pos-BN finalize) + fused attn-BN stats
    hattn_kernel<<<MROW/64, 256>>>(gp, betap);

    // 6) fused attn/pos mma GEMMs + softmax + aggregation (pre-split weights)
    cudaFuncSetAttribute(attnout_kernel, cudaFuncAttributeMaxDynamicSharedMemorySize, ATTN_SMEM);
    attnout_kernel<<<MROW/64, 256, ATTN_SMEM>>>(ba2, bp2, gp, betap, ga, betaa);

    // 7) outputs (both post GEMMs in one launch)
    float* out1 = out;                                   // [B,N1,256]
    float* opc1 = out + (size_t)M8*D;                    // [B,N1,3]
    float* out2 = opc1 + (size_t)M8*3;                   // [B,N1,256]
    float* opc2 = out2 + (size_t)M8*D;                   // [B,N2,3]
    cudaFuncSetAttribute(gemm_post_kernel, cudaFuncAttributeMaxDynamicSharedMemorySize, POST_SMEM);
    gemm_post_kernel<<<dim3(2, M8/128, 2), 512, POST_SMEM>>>(p_x, W_post1, b_post1, dec_x, out1,
                                                             W_post2, b_post2, out2);
    cudaMemcpyAsync(opc1, dec_pc, (size_t)M8*3*sizeof(float), cudaMemcpyDeviceToDevice);
    cudaMemcpyAsync(opc2, enc_pc, (size_t)B*N2*3*sizeof(float), cudaMemcpyDeviceToDevice);
}

// round 13
// speedup vs baseline: 1.2732x; 1.1620x over previous
#include <cuda_runtime.h>
#include <cuda_bf16.h>
#include <math.h>
#include <stdint.h>

// Problem constants
#define B    4
#define N1   2048
#define N2   2048
#define NC   4096           // N1+N2
#define D    256
#define HP   64
#define HA   64
#define KNN  16
#define MROW (B*N1*KNN)     // 131072
#define INV_MROW (1.0f/131072.0f)

// ---------------- scratch (device globals; no allocation allowed) -------------
__device__ float g_dx  [B*N1*D];
__device__ float g_ex  [B*N2*D];
__device__ float g_sx  [B*N1*D];
__device__ float g_spc [B*N1*3];
__device__ int   g_fidx[B*N1];
__device__ float g_qa  [B*N1*HA];
__device__ float g_ka  [B*N1*HA];
__device__ float g_v   [B*N1*D];
__device__ int   g_nidx[B*N1*KNN];
__device__ float g_hpos [MROW*HP];
__device__ float g_hattn[MROW*HA];
__device__ float g_x   [B*N1*D];
__device__ float g_WkWa1[D*HA];
__device__ float g_WqWa1[D*HA];
__device__ float g_Wp2a [HP*HA];
__device__ float g_cvec [HA];
__device__ float g_Wa2hl[HA*D*2];   // interleaved tf32 hi/lo planes of Wa2
__device__ float g_Wp2hl[HP*D*2];   // interleaved tf32 hi/lo planes of Wp2
// [0:64) psum [64:128) psq [128:192) asum [192:256) asq
__device__ float g_stats[256];

// ================= packed f32x2 helpers (sm_103a FFMA2 path) ==================
#define ADD2(o,a,b)   asm("add.rn.f32x2 %0, %1, %2;" : "=l"(o) : "l"(a), "l"(b))
#define MUL2(o,a,b)   asm("mul.rn.f32x2 %0, %1, %2;" : "=l"(o) : "l"(a), "l"(b))
#define FMA2(o,a,b,c) asm("fma.rn.f32x2 %0, %1, %2, %3;" : "=l"(o) : "l"(a), "l"(b), "l"(c))
__device__ __forceinline__ unsigned long long pack2(float lo, float hi) {
    unsigned long long o;
    asm("mov.b64 %0, {%1, %2};" : "=l"(o) : "r"(__float_as_uint(lo)), "r"(__float_as_uint(hi)));
    return o;
}
__device__ __forceinline__ void unpack2(unsigned long long v, float& lo, float& hi) {
    uint32_t a, b;
    asm("mov.b64 {%0, %1}, %2;" : "=r"(a), "=r"(b) : "l"(v));
    lo = __uint_as_float(a); hi = __uint_as_float(b);
}

// ================= tf32 mma helpers ===========================================
__device__ __forceinline__ uint32_t f2tf(float x) {
    uint32_t r; asm("cvt.rna.tf32.f32 %0, %1;" : "=r"(r) : "f"(x)); return r;
}
__device__ __forceinline__ void mma8(float* d, const uint32_t* a, const uint32_t* b) {
    asm volatile("mma.sync.aligned.m16n8k8.row.col.f32.tf32.tf32.f32 "
        "{%0,%1,%2,%3}, {%4,%5,%6,%7}, {%8,%9}, {%0,%1,%2,%3};"
        : "+f"(d[0]), "+f"(d[1]), "+f"(d[2]), "+f"(d[3])
        : "r"(a[0]), "r"(a[1]), "r"(a[2]), "r"(a[3]), "r"(b[0]), "r"(b[1]));
}

// ------ tf32x2 GEMM body: 128x128 tile, 512 threads, hi/lo planes, 3-mma ------
#define APITCH 36
#define BPITCH 136
#define TF32_SMEM_FLOATS (2*128*APITCH + 2*32*BPITCH)

__device__ __forceinline__ void gemm_tf32_body(
    const float* __restrict__ A, const float* __restrict__ W,
    const float* __restrict__ bias, const float* __restrict__ resid,
    float* __restrict__ C, int bx, int by, int N, int K)
{
    extern __shared__ float smext[];
    float* AHs = smext;
    float* ALs = AHs + 128*APITCH;
    float* BHs = ALs + 128*APITCH;
    float* BLs = BHs + 32*BPITCH;
    int tid = threadIdx.x;
    int row0 = by * 128, col0 = bx * 128;
    int warp = tid >> 5, lane = tid & 31;
    int mw = (warp & 3) * 32, nw = (warp >> 2) * 32;
    int g = lane >> 2, tg = lane & 3;
    float acc[8][4] = {};
    for (int k0 = 0; k0 < K; k0 += 32) {
#pragma unroll
        for (int i = 0; i < 2; i++) {
            int idx = tid + i*512;
            int r = idx >> 3, c4 = (idx & 7) * 4;
            float4 v = *(const float4*)&A[(size_t)(row0+r)*K + k0 + c4];
            float xs[4] = {v.x, v.y, v.z, v.w};
#pragma unroll
            for (int u = 0; u < 4; u++) {
                uint32_t hi = f2tf(xs[u]);
                AHs[r*APITCH + c4+u] = __uint_as_float(hi);
                ALs[r*APITCH + c4+u] = __uint_as_float(f2tf(xs[u] - __uint_as_float(hi)));
            }
        }
#pragma unroll
        for (int i = 0; i < 2; i++) {
            int idx = tid + i*512;
            int r = idx >> 5, c4 = (idx & 31) * 4;
            float4 v = *(const float4*)&W[(size_t)(k0+r)*N + col0 + c4];
            float xs[4] = {v.x, v.y, v.z, v.w};
#pragma unroll
            for (int u = 0; u < 4; u++) {
                uint32_t hi = f2tf(xs[u]);
                BHs[r*BPITCH + c4+u] = __uint_as_float(hi);
                BLs[r*BPITCH + c4+u] = __uint_as_float(f2tf(xs[u] - __uint_as_float(hi)));
            }
        }
        __syncthreads();
#pragma unroll
        for (int ks = 0; ks < 32; ks += 8) {
            uint32_t ah[2][4], al[2][4], bh[4][2], bl[4][2];
#pragma unroll
            for (int mi = 0; mi < 2; mi++) {
                int rb = mw + mi*16;
                ah[mi][0] = __float_as_uint(AHs[(rb+g  )*APITCH + ks+tg  ]);
                ah[mi][1] = __float_as_uint(AHs[(rb+g+8)*APITCH + ks+tg  ]);
                ah[mi][2] = __float_as_uint(AHs[(rb+g  )*APITCH + ks+tg+4]);
                ah[mi][3] = __float_as_uint(AHs[(rb+g+8)*APITCH + ks+tg+4]);
                al[mi][0] = __float_as_uint(ALs[(rb+g  )*APITCH + ks+tg  ]);
                al[mi][1] = __float_as_uint(ALs[(rb+g+8)*APITCH + ks+tg  ]);
                al[mi][2] = __float_as_uint(ALs[(rb+g  )*APITCH + ks+tg+4]);
                al[mi][3] = __float_as_uint(ALs[(rb+g+8)*APITCH + ks+tg+4]);
            }
#pragma unroll
            for (int ni = 0; ni < 4; ni++) {
                bh[ni][0] = __float_as_uint(BHs[(ks+tg  )*BPITCH + nw + ni*8 + g]);
                bh[ni][1] = __float_as_uint(BHs[(ks+tg+4)*BPITCH + nw + ni*8 + g]);
                bl[ni][0] = __float_as_uint(BLs[(ks+tg  )*BPITCH + nw + ni*8 + g]);
                bl[ni][1] = __float_as_uint(BLs[(ks+tg+4)*BPITCH + nw + ni*8 + g]);
            }
#pragma unroll
            for (int mi = 0; mi < 2; mi++)
#pragma unroll
                for (int ni = 0; ni < 4; ni++) {
                    mma8(acc[mi*4+ni], ah[mi], bh[ni]);
                    mma8(acc[mi*4+ni], ah[mi], bl[ni]);
                    mma8(acc[mi*4+ni], al[mi], bh[ni]);
                }
        }
        __syncthreads();
    }
#pragma unroll
    for (int mi = 0; mi < 2; mi++) {
#pragma unroll
        for (int ni = 0; ni < 4; ni++) {
            int c = col0 + nw + ni*8 + 2*tg;
            float b0 = bias ? bias[c]   : 0.f;
            float b1 = bias ? bias[c+1] : 0.f;
            size_t r1 = (size_t)(row0 + mw + mi*16 + g);
            size_t r2 = r1 + 8;
            float v00 = acc[mi*4+ni][0] + b0, v01 = acc[mi*4+ni][1] + b1;
            float v10 = acc[mi*4+ni][2] + b0, v11 = acc[mi*4+ni][3] + b1;
            if (resid) {
                v00 += resid[r1*N+c]; v01 += resid[r1*N+c+1];
                v10 += resid[r2*N+c]; v11 += resid[r2*N+c+1];
            }
            *(float2*)&C[r1*N + c] = make_float2(v00, v01);
            *(float2*)&C[r2*N + c] = make_float2(v10, v11);
        }
    }
}

// ---------------- combined post-GEMMs (z selects output head) ------------------
__global__ void __launch_bounds__(512)
gemm_post_kernel(const float* __restrict__ X,
                 const float* __restrict__ W1, const float* __restrict__ b1,
                 const float* __restrict__ resid1, float* __restrict__ out1,
                 const float* __restrict__ W2, const float* __restrict__ b2,
                 float* __restrict__ out2)
{
    if (blockIdx.z == 0)
        gemm_tf32_body(X, W1, b1, resid1, out1, blockIdx.x, blockIdx.y, D, D);
    else
        gemm_tf32_body(X, W2, b2, nullptr, out2, blockIdx.x, blockIdx.y, D, D);
}

// ---------------- FPS v2: packed distances + thread-0 cross-warp reduce --------
__device__ void fps_body(int b, const float* __restrict__ decpc,
                         const float* __restrict__ encpc)
{
    extern __shared__ float smext[];
    float* sx = smext;
    float* sy = smext + NC;
    float* sz = smext + 2*NC;
    __shared__ unsigned long long swk[2][16];
    __shared__ int scur[2];

    int tid = threadIdx.x;
    int wid = tid >> 5, lid = tid & 31;

    for (int j = tid; j < N1; j += 512) {
        sx[j] = decpc[((size_t)b*N1 + j)*3 + 0];
        sy[j] = decpc[((size_t)b*N1 + j)*3 + 1];
        sz[j] = decpc[((size_t)b*N1 + j)*3 + 2];
        sx[N1+j] = encpc[((size_t)b*N2 + j)*3 + 0];
        sy[N1+j] = encpc[((size_t)b*N2 + j)*3 + 1];
        sz[N1+j] = encpc[((size_t)b*N2 + j)*3 + 2];
    }
    if (tid == 0) g_fidx[b*N1] = 0;
    int cur = 0;
    __syncthreads();

    // coords packed in registers (2 points per 64-bit); t = 2p (lo), 2p+1 (hi)
    unsigned long long PX[4], PY[4], PZ[4];
    float md[8];
#pragma unroll
    for (int p = 0; p < 4; p++) {
        int j0 = tid + (2*p)*512, j1 = tid + (2*p+1)*512;
        PX[p] = pack2(sx[j0], sx[j1]);
        PY[p] = pack2(sy[j0], sy[j1]);
        PZ[p] = pack2(sz[j0], sz[j1]);
        md[2*p] = 1e10f; md[2*p+1] = 1e10f;
    }

    for (int i = 1; i < N1; i++) {
        float lx = sx[cur], ly = sy[cur], lz = sz[cur];
        unsigned long long NLX = pack2(-lx, -lx);
        unsigned long long NLY = pack2(-ly, -ly);
        unsigned long long NLZ = pack2(-lz, -lz);
#pragma unroll
        for (int p = 0; p < 4; p++) {
            unsigned long long dx, dy, dz, dd;
            ADD2(dx, PX[p], NLX);
            ADD2(dy, PY[p], NLY);
            ADD2(dz, PZ[p], NLZ);
            MUL2(dd, dx, dx);
            FMA2(dd, dy, dy, dd);
            FMA2(dd, dz, dz, dd);
            float d0, d1; unpack2(dd, d0, d1);
            md[2*p]   = fminf(md[2*p],   d0);
            md[2*p+1] = fminf(md[2*p+1], d1);
        }
        // max over 8 (all >= 0), then smallest t with md[t]==bv
        float bv = fmaxf(fmaxf(fmaxf(md[0],md[1]), fmaxf(md[2],md[3])),
                         fmaxf(fmaxf(md[4],md[5]), fmaxf(md[6],md[7])));
        int bt = 0;
#pragma unroll
        for (int t = 7; t >= 0; t--) if (md[t] == bv) bt = t;
        int besti = tid + bt*512;

        // distances are >= 0, so raw float bits are unsigned-monotone
        unsigned kb = __float_as_uint(bv);
        unsigned mk;
        asm("redux.sync.max.u32 %0, %1, 0xffffffff;" : "=r"(mk) : "r"(kb));
        unsigned idxc = (kb == mk) ? (unsigned)besti : 0xffffffffu;
        unsigned mi;
        asm("redux.sync.min.u32 %0, %1, 0xffffffff;" : "=r"(mi) : "r"(idxc));
        int pb = i & 1;
        if (lid == 0)
            swk[pb][wid] = (((unsigned long long)mk) << 32) | (unsigned long long)(0xffffffffu - mi);
        __syncthreads();
        if (tid == 0) {
            unsigned long long best = swk[pb][0];
#pragma unroll
            for (int w = 1; w < 16; w++) {
                unsigned long long o = swk[pb][w];
                best = (o > best) ? o : best;
            }
            int c = (int)(0xffffffffu - (unsigned)best);
            scur[pb] = c;
            g_fidx[b*N1 + i] = c;
        }
        __syncthreads();
        cur = scur[pb];
    }
}

// ---------------- small 64-col GEMM body (weight precomputes), 512 thr --------
#define TBM 64
#define TBK 16
__device__ void gemm64_body(const float* __restrict__ A, const float* __restrict__ W,
                            float* __restrict__ C, int row0, int N, int K)
{
    __shared__ float As64[TBK][TBM];
    __shared__ float Bs64[TBK][64];
    int tid = threadIdx.x;
    for (int k0 = 0; k0 < K; k0 += TBK) {
#pragma unroll
        for (int u = 0; u < 2; u++) {
            int e = tid + u*512;
            int r = e >> 4, c = e & 15;
            As64[c][r] = A[(size_t)(row0 + r)*K + k0 + c];
            int r2 = e >> 6, c2 = e & 63;
            Bs64[r2][c2] = W[(size_t)(k0 + r2)*N + c2];
        }
        __syncthreads();
        if (tid < 256) {
            int tx = tid & 15, ty = tid >> 4;
            float acc[4][4] = {};
#pragma unroll
            for (int kk = 0; kk < TBK; kk++) {
                float a[4], bb[4];
#pragma unroll
                for (int i = 0; i < 4; i++) a[i] = As64[kk][ty*4+i];
#pragma unroll
                for (int j = 0; j < 4; j++) bb[j] = Bs64[kk][tx*4+j];
#pragma unroll
                for (int i = 0; i < 4; i++)
#pragma unroll
                    for (int j = 0; j < 4; j++)
                        acc[i][j] += a[i]*bb[j];
            }
#pragma unroll
            for (int i = 0; i < 4; i++)
#pragma unroll
                for (int j = 0; j < 4; j++) {
                    size_t off = (size_t)(row0 + ty*4 + i)*N + tx*4 + j;
                    if (k0 == 0) C[off] = acc[i][j];
                    else         C[off] += acc[i][j];
                }
        }
        __syncthreads();
    }
}

// ---------------- cvec body: (bk - bq + bp2) @ Wa1 + ba1, 512 thr --------------
__device__ void cvec_body(const float* __restrict__ bk, const float* __restrict__ bq,
                          const float* __restrict__ bp2, const float* __restrict__ Wa1,
                          const float* __restrict__ ba1)
{
    __shared__ float shc[512];
    int c = threadIdx.x & 63;
    int part = threadIdx.x >> 6;     // 0..7
    float s = 0.f;
    for (int i = part*32; i < part*32 + 32; i++)
        s += (bk[i] - bq[i] + bp2[i]) * Wa1[(size_t)i*HA + c];
    shc[threadIdx.x] = s;
    __syncthreads();
    if (part == 0) {
        float t = ba1[c];
#pragma unroll
        for (int p = 0; p < 8; p++) t += shc[p*64 + c];
        g_cvec[c] = t;
    }
}

// ---------------- weight hi/lo split body (once per launch) -------------------
__device__ void wsplit_body(const float* __restrict__ W, float* __restrict__ out, int n)
{
    for (int i = threadIdx.x; i < n; i += 512) {
        float x = W[i];
        uint32_t hi = f2tf(x);
        out[2*i]   = __uint_as_float(hi);
        out[2*i+1] = __uint_as_float(f2tf(x - __uint_as_float(hi)));
    }
}

// ---------------- phase-1 mega-kernel -----------------------------------------
// [0,4)=FPS [4,132)=pre1 [132,260)=pre2 [260,264)=WkWa1 [264,268)=WqWa1
// [268]=Wp2a [269]=cvec [270]=zero_stats [271]=split Wa2 [272]=split Wp2
__global__ void __launch_bounds__(512)
phase1_kernel(const float* __restrict__ dec_pc, const float* __restrict__ enc_pc,
              const float* __restrict__ dec_x,  const float* __restrict__ enc_x,
              const float* __restrict__ W_pre1, const float* __restrict__ b_pre1,
              const float* __restrict__ W_pre2, const float* __restrict__ b_pre2,
              const float* __restrict__ Wk, const float* __restrict__ Wq,
              const float* __restrict__ Wa1, const float* __restrict__ Wp2,
              const float* __restrict__ bk, const float* __restrict__ bq,
              const float* __restrict__ bp2, const float* __restrict__ ba1,
              const float* __restrict__ Wa2)
{
    int bid = blockIdx.x;
    if (bid < 4) {
        fps_body(bid, dec_pc, enc_pc);
    } else if (bid < 132) {
        int t = bid - 4;
        gemm_tf32_body(dec_x, W_pre1, b_pre1, nullptr, g_dx, t & 1, t >> 1, D, D);
    } else if (bid < 260) {
        int t = bid - 132;
        gemm_tf32_body(enc_x, W_pre2, b_pre2, nullptr, g_ex, t & 1, t >> 1, D, D);
    } else if (bid < 264) {
        gemm64_body(Wk, Wa1, g_WkWa1, (bid-260)*64, HA, D);
    } else if (bid < 268) {
        gemm64_body(Wq, Wa1, g_WqWa1, (bid-264)*64, HA, D);
    } else if (bid == 268) {
        gemm64_body(Wp2, Wa1, g_Wp2a, 0, HA, D);
    } else if (bid == 269) {
        cvec_body(bk, bq, bp2, Wa1, ba1);
    } else if (bid == 270) {
        if (threadIdx.x < 256) g_stats[threadIdx.x] = 0.0f;
    } else if (bid == 271) {
        wsplit_body(Wa2, g_Wa2hl, HA*D);
    } else {
        wsplit_body(Wp2, g_Wp2hl, HP*D);
    }
}

// ---------------- gather sampled features + coords ----------------------------
__global__ void gather_kernel(const float* __restrict__ decpc,
                              const float* __restrict__ encpc)
{
    int row = blockIdx.x*4 + (threadIdx.x >> 6);
    int c4  = (threadIdx.x & 63) * 4;
    int b = row >> 11;
    int j = g_fidx[row];
    const float* src = (j < N1) ? &g_dx[((size_t)b*N1 + j)*D]
                                : &g_ex[((size_t)b*N2 + (j - N1))*D];
    *(float4*)&g_sx[(size_t)row*D + c4] = *(const float4*)&src[c4];
    if ((threadIdx.x & 63) < 3) {
        int cc = threadIdx.x & 63;
        const float* ps = (j < N1) ? &decpc[((size_t)b*N1 + j)*3]
                                   : &encpc[((size_t)b*N2 + (j - N1))*3];
        g_spc[(size_t)row*3 + cc] = ps[cc];
    }
}

// ---------------- N=64 GEMM body for 512 threads (qa/ka) -----------------------
__device__ void n64_body_512(const float* __restrict__ A, const float* __restrict__ W,
                             float* __restrict__ C, int row0)
{
    __shared__ float Asq[16][132];
    __shared__ float Bsq[16][64];
    int tid = threadIdx.x;
    int tx = tid & 15, ty = tid >> 4;          // ty 0..31
    float acc[4][4] = {};
    for (int k0 = 0; k0 < D; k0 += 16) {
        {
            int r = tid >> 2, kq = (tid & 3) * 4;
            float4 va = *(const float4*)&A[(size_t)(row0 + r)*D + k0 + kq];
            Asq[kq+0][r] = va.x; Asq[kq+1][r] = va.y;
            Asq[kq+2][r] = va.z; Asq[kq+3][r] = va.w;
        }
        if (tid < 256) {
            int r = tid >> 4, cq = (tid & 15) * 4;
            *(float4*)&Bsq[r][cq] = *(const float4*)&W[(size_t)(k0 + r)*HA + cq];
        }
        __syncthreads();
#pragma unroll
        for (int kk = 0; kk < 16; kk++) {
            float a[4], bb[4];
#pragma unroll
            for (int i = 0; i < 4; i++) a[i] = Asq[kk][ty*4+i];
#pragma unroll
            for (int j = 0; j < 4; j++) bb[j] = Bsq[kk][tx*4+j];
#pragma unroll
            for (int i = 0; i < 4; i++)
#pragma unroll
                for (int j = 0; j < 4; j++)
                    acc[i][j] += a[i]*bb[j];
        }
        __syncthreads();
    }
#pragma unroll
    for (int i = 0; i < 4; i++)
#pragma unroll
        for (int j = 0; j < 4; j++)
            C[(size_t)(row0 + ty*4 + i)*HA + tx*4 + j] = acc[i][j];
}

// ---------------- phase-2 mega-kernel: KNN + qa/ka + v -------------------------
__global__ void __launch_bounds__(512)
phase2_kernel(const float* __restrict__ decpc,
              const float* __restrict__ Wv, const float* __restrict__ bv)
{
    int bid = blockIdx.x;
    if (bid < 32) {
        extern __shared__ float s2[];
        float* px = s2; float* py = px + 2048; float* pz = py + 2048; float* s2s = pz + 2048;
        unsigned long long* buf = (unsigned long long*)(s2 + 8192);
        int tid = threadIdx.x;
        int b = bid >> 3, qb = bid & 7;
        for (int m = tid; m < 2048; m += 512) {
            float x = g_spc[((size_t)b*N1 + m)*3 + 0];
            float y = g_spc[((size_t)b*N1 + m)*3 + 1];
            float z = g_spc[((size_t)b*N1 + m)*3 + 2];
            px[m] = x; py[m] = y; pz[m] = z;
            s2s[m] = x*x + y*y + z*z;
        }
        __syncthreads();
        int qi = tid & 255, h = tid >> 8;
        int q = qb*256 + qi;
        float qx = decpc[((size_t)b*N1 + q)*3 + 0];
        float qy = decpc[((size_t)b*N1 + q)*3 + 1];
        float qz = decpc[((size_t)b*N1 + q)*3 + 2];
        float s1 = qx*qx + qy*qy + qz*qz;
        float bd[KNN]; int bi[KNN];
#pragma unroll
        for (int t = 0; t < KNN; t++) { bd[t] = 1e30f; bi[t] = 0; }
        int mbase = h * 1024;
        for (int mm = 0; mm < 1024; mm++) {
            int m = mbase + mm;
            float d = s1 + s2s[m] - 2.0f*(qx*px[m] + qy*py[m] + qz*pz[m]);
            if (d < bd[KNN-1]) {
                bd[KNN-1] = d; bi[KNN-1] = m;
#pragma unroll
                for (int t = KNN-1; t > 0; t--) {
                    if (bd[t] < bd[t-1]) {
                        float td = bd[t]; bd[t] = bd[t-1]; bd[t-1] = td;
                        int   ti = bi[t]; bi[t] = bi[t-1]; bi[t-1] = ti;
                    }
                }
            }
        }
#pragma unroll
        for (int t = 0; t < KNN; t++) {
            unsigned u = __float_as_uint(bd[t]);
            u = ((int)u < 0) ? ~u : (u | 0x80000000u);
            buf[(size_t)tid*KNN + t] = (((unsigned long long)u) << 32) | (unsigned)bi[t];
        }
        __syncthreads();
        if (h == 0) {
            const unsigned long long* A_ = &buf[(size_t)qi*KNN];
            const unsigned long long* B_ = &buf[(size_t)(qi+256)*KNN];
            int* outp = &g_nidx[((size_t)b*N1 + q)*KNN];
            int ia = 0, ib = 0;
#pragma unroll
            for (int o = 0; o < KNN; o++) {
                unsigned long long av = A_[ia], bv_ = B_[ib];
                if ((av >> 32) <= (bv_ >> 32)) { outp[o] = (int)(unsigned)av; ia++; }
                else                           { outp[o] = (int)(unsigned)bv_; ib++; }
            }
        }
    } else if (bid < 160) {
        int t = bid - 32;
        int sel = t >> 6, tile = t & 63;
        n64_body_512(sel ? g_sx : g_dx, sel ? g_WkWa1 : g_WqWa1,
                     sel ? g_ka : g_qa, tile*128);
    } else {
        int t = bid - 160;
        gemm_tf32_body(g_sx, Wv, bv, nullptr, g_v, t & 1, t >> 1, D, D);
    }
}

// ---------------- hpos + fused BN stats ----------------------------------------
__global__ void __launch_bounds__(256)
hpos_kernel(const float* __restrict__ decpc,
            const float* __restrict__ Wp1,
            const float* __restrict__ bp1)
{
    int tid = threadIdx.x;
    int c = tid & 63;
    int rg = tid >> 6;
    float w0 = Wp1[c], w1 = Wp1[64+c], w2 = Wp1[128+c], bb = bp1[c];
    float s = 0.f, s2 = 0.f;
    int base = blockIdx.x * 256;
    for (int it = 0; it < 64; it++) {
        int m = base + it*4 + rg;
        int b = m >> 15;
        int n = (m >> 4) & 2047;
        int j = g_nidx[m];
        const float* pp = &g_spc[((size_t)b*N1 + j)*3];
        const float* qq = &decpc[((size_t)b*N1 + n)*3];
        float p0 = pp[0]-qq[0], p1 = pp[1]-qq[1], p2 = pp[2]-qq[2];
        float h = p0*w0 + p1*w1 + p2*w2 + bb;
        g_hpos[(size_t)m*HP + c] = h;
        s += h; s2 += h*h;
    }
    __shared__ float sh[256], sh2[256];
    sh[tid] = s; sh2[tid] = s2;
    __syncthreads();
    if (rg == 0) {
        atomicAdd(&g_stats[c],    sh[c] + sh[64+c] + sh[128+c] + sh[192+c]);
        atomicAdd(&g_stats[64+c], sh2[c] + sh2[64+c] + sh2[128+c] + sh2[192+c]);
    }
}

// ---- hattn = relu(bn_pos(hp)) @ Wp2a + ka[gather] - qa + cvec + stats --------
__global__ void __launch_bounds__(256)
hattn_kernel(const float* __restrict__ gp, const float* __restrict__ betap)
{
    __shared__ float Aw[64][65];
    __shared__ float Bw[64*64];
    __shared__ float psc[64], psh[64];
    __shared__ float rs[16][64], rs2[16][64];
    int tid = threadIdx.x;
    int m0 = blockIdx.x * 64;
    if (tid < 64) {
        float mean = g_stats[tid] * INV_MROW;
        float var  = g_stats[64+tid] * INV_MROW - mean*mean;
        float sc = gp[tid]*rsqrtf(var + 1e-5f);
        psc[tid] = sc;
        psh[tid] = betap[tid] - mean*sc;
    }
    __syncthreads();
#pragma unroll
    for (int i = 0; i < 16; i++) {
        int idx = tid + i*256;
        int r = idx >> 6, k = idx & 63;
        float h = g_hpos[(size_t)(m0+r)*64 + k];
        Aw[r][k] = fmaxf(h*psc[k] + psh[k], 0.0f);
        Bw[idx] = g_Wp2a[idx];
    }
    __syncthreads();
    int tx = tid & 15, ty = tid >> 4;
    float acc[4][4] = {};
#pragma unroll 4
    for (int kk = 0; kk < 64; kk++) {
        float a[4], bb[4];
#pragma unroll
        for (int i = 0; i < 4; i++) a[i] = Aw[ty*4+i][kk];
#pragma unroll
        for (int j = 0; j < 4; j++) bb[j] = Bw[kk*64 + tx*4 + j];
#pragma unroll
        for (int i = 0; i < 4; i++)
#pragma unroll
            for (int j = 0; j < 4; j++)
                acc[i][j] += a[i]*bb[j];
    }
    float ps[4] = {0,0,0,0}, ps2[4] = {0,0,0,0};
#pragma unroll
    for (int i = 0; i < 4; i++) {
        int m = m0 + ty*4 + i;
        int b = m >> 15;
        int n = (m >> 4) & 2047;
        int jj = g_nidx[m];
        const float* kar = &g_ka[(((size_t)b<<11) + jj)*HA];
        const float* qar = &g_qa[(((size_t)b<<11) + n )*HA];
#pragma unroll
        for (int j = 0; j < 4; j++) {
            int c = tx*4 + j;
            float v = acc[i][j] + kar[c] - qar[c] + g_cvec[c];
            g_hattn[(size_t)m*HA + c] = v;
            ps[j] += v; ps2[j] += v*v;
        }
    }
#pragma unroll
    for (int j = 0; j < 4; j++) {
        rs[ty][tx*4+j] = ps[j];
        rs2[ty][tx*4+j] = ps2[j];
    }
    __syncthreads();
    if (tid < 64) {
        float s = 0.f, s2 = 0.f;
#pragma unroll
        for (int t = 0; t < 16; t++) { s += rs[t][tid]; s2 += rs2[t][tid]; }
        atomicAdd(&g_stats[128+tid], s);
        atomicAdd(&g_stats[192+tid], s2);
    }
}

// ---- fused: attn/pos GEMMs via tf32x2 mma + softmax(K) + agg -> g_x ----------
// grid 2048; block handles 64 rows x 256 cols (two 128-col halves, A reused)
// B planes come pre-split from g_Wa2hl / g_Wp2hl (interleaved hi/lo).
__global__ void __launch_bounds__(256)
attnout_kernel(const float* __restrict__ ba2,
               const float* __restrict__ bp2,
               const float* __restrict__ gp, const float* __restrict__ betap,
               const float* __restrict__ ga, const float* __restrict__ betaa)
{
    extern __shared__ float sm[];
    float* Ahr    = sm;                 // [64][68]
    float* Apr    = Ahr + 64*68;        // [64][68]
    float* attn_s = Apr + 64*68;        // [64][132]
    float* pos_s  = attn_s + 64*132;    // [64][132]
    float* Bh     = pos_s + 64*132;     // [16][136]
    float* Bl     = Bh + 16*136;        // [16][136]
    float* scbuf  = Bl + 16*136;        // psc,psh,asc,ash [4][64]
    int*   sj     = (int*)(scbuf + 256);// [64]

    int tid = threadIdx.x;
    int m0 = blockIdx.x * 64;
    int warp = tid >> 5, lane = tid & 31;
    int mw = (warp & 3) * 16, nw = (warp >> 2) * 64;
    int g = lane >> 2, tg = lane & 3;

    if (tid < 64) {
        float mean = g_stats[tid] * INV_MROW;
        float var  = g_stats[64+tid] * INV_MROW - mean*mean;
        float sc = gp[tid]*rsqrtf(var + 1e-5f);
        scbuf[tid] = sc;
        scbuf[64+tid] = betap[tid] - mean*sc;
        mean = g_stats[128+tid] * INV_MROW;
        var  = g_stats[192+tid] * INV_MROW - mean*mean;
        sc = ga[tid]*rsqrtf(var + 1e-5f);
        scbuf[128+tid] = sc;
        scbuf[192+tid] = betaa[tid] - mean*sc;
        sj[tid] = g_nidx[m0 + tid];
    }
    __syncthreads();

#pragma unroll
    for (int i = 0; i < 16; i++) {
        int idx = tid + i*256;
        int r = idx >> 6, k = idx & 63;
        float ha = g_hattn[(size_t)(m0+r)*64 + k];
        Ahr[r*68 + k] = fmaxf(ha*scbuf[128+k] + scbuf[192+k], 0.0f);
        float hp = g_hpos[(size_t)(m0+r)*64 + k];
        Apr[r*68 + k] = fmaxf(hp*scbuf[k] + scbuf[64+k], 0.0f);
    }

    for (int half = 0; half < 2; half++) {
        int c0 = half * 128;
#pragma unroll
        for (int pass = 0; pass < 2; pass++) {
            const float* Whl  = pass ? g_Wp2hl : g_Wa2hl;
            const float* bsrc = pass ? bp2 : ba2;
            const float* Asm  = pass ? Apr : Ahr;
            float* Out = pass ? pos_s : attn_s;
            float acc[8][4] = {};
            for (int k0 = 0; k0 < 64; k0 += 16) {
                __syncthreads();
#pragma unroll
                for (int i = 0; i < 8; i++) {
                    int idx = tid + i*256;
                    int r = idx >> 7, c = idx & 127;
                    float2 hl = *(const float2*)&Whl[((size_t)(k0+r)*D + c0 + c)*2];
                    Bh[r*136 + c] = hl.x;
                    Bl[r*136 + c] = hl.y;
                }
                __syncthreads();
#pragma unroll
                for (int ks = 0; ks < 16; ks += 8) {
                    uint32_t ah[4], al[4];
                    {
                        float x0 = Asm[(mw+g  )*68 + k0+ks+tg  ];
                        float x1 = Asm[(mw+g+8)*68 + k0+ks+tg  ];
                        float x2 = Asm[(mw+g  )*68 + k0+ks+tg+4];
                        float x3 = Asm[(mw+g+8)*68 + k0+ks+tg+4];
                        ah[0] = f2tf(x0); al[0] = f2tf(x0 - __uint_as_float(ah[0]));
                        ah[1] = f2tf(x1); al[1] = f2tf(x1 - __uint_as_float(ah[1]));
                        ah[2] = f2tf(x2); al[2] = f2tf(x2 - __uint_as_float(ah[2]));
                        ah[3] = f2tf(x3); al[3] = f2tf(x3 - __uint_as_float(ah[3]));
                    }
#pragma unroll
                    for (int ni = 0; ni < 8; ni++) {
                        uint32_t bhf[2], blf[2];
                        bhf[0] = __float_as_uint(Bh[(ks+tg  )*136 + nw + ni*8 + g]);
                        bhf[1] = __float_as_uint(Bh[(ks+tg+4)*136 + nw + ni*8 + g]);
                        blf[0] = __float_as_uint(Bl[(ks+tg  )*136 + nw + ni*8 + g]);
                        blf[1] = __float_as_uint(Bl[(ks+tg+4)*136 + nw + ni*8 + g]);
                        mma8(acc[ni], ah, bhf);
                        mma8(acc[ni], ah, blf);
                        mma8(acc[ni], al, bhf);
                    }
                }
            }
#pragma unroll
            for (int ni = 0; ni < 8; ni++) {
                int c = nw + ni*8 + 2*tg;
                float b0 = bsrc[c0 + c], b1 = bsrc[c0 + c + 1];
                Out[(mw+g  )*132 + c]     = acc[ni][0] + b0;
                Out[(mw+g  )*132 + c + 1] = acc[ni][1] + b1;
                Out[(mw+g+8)*132 + c]     = acc[ni][2] + b0;
                Out[(mw+g+8)*132 + c + 1] = acc[ni][3] + b1;
            }
        }
        __syncthreads();

        // softmax over 16 neighbors + aggregation for this 128-col half
#pragma unroll
        for (int e = tid; e < 512; e += 256) {
            int q = e >> 7;            // 0..3
            int c = e & 127;
            int mrow = q*16;
            float mx = -1e30f;
#pragma unroll
            for (int k = 0; k < KNN; k++)
                mx = fmaxf(mx, attn_s[(mrow+k)*132 + c]);
            float w[KNN]; float s = 0.f;
#pragma unroll
            for (int k = 0; k < KNN; k++) {
                w[k] = __expf(attn_s[(mrow+k)*132 + c] - mx);
                s += w[k];
            }
            float inv = 1.0f / s;
            int qg = (m0 >> 4) + q;
            int b = qg >> 11;
            float x = 0.f;
#pragma unroll
            for (int k = 0; k < KNN; k++) {
                int j = sj[mrow + k];
                float vv = g_v[(((size_t)b<<11) + j)*D + c0 + c] + pos_s[(mrow+k)*132 + c];
                x += vv * w[k];
            }
            g_x[(size_t)qg*D + c0 + c] = x * inv;
        }
        __syncthreads();
    }
}

// =================================================================================
extern "C" void kernel_launch(void* const* d_in, const int* in_sizes, int n_in,
                              void* d_out, int out_size)
{
    const float* dec_x   = (const float*)d_in[0];
    const float* dec_pc  = (const float*)d_in[1];
    const float* enc_x   = (const float*)d_in[2];
    const float* enc_pc  = (const float*)d_in[3];
    const float* W_pre1  = (const float*)d_in[4];
    const float* b_pre1  = (const float*)d_in[5];
    const float* W_pre2  = (const float*)d_in[6];
    const float* b_pre2  = (const float*)d_in[7];
    const float* Wq      = (const float*)d_in[8];
    const float* bq      = (const float*)d_in[9];
    const float* Wk      = (const float*)d_in[10];
    const float* bk      = (const float*)d_in[11];
    const float* Wv      = (const float*)d_in[12];
    const float* bv      = (const float*)d_in[13];
    const float* Wp1     = (const float*)d_in[14];
    const float* bp1     = (const float*)d_in[15];
    const float* gp      = (const float*)d_in[16];
    const float* betap   = (const float*)d_in[17];
    const float* Wp2     = (const float*)d_in[18];
    const float* bp2     = (const float*)d_in[19];
    const float* Wa1     = (const float*)d_in[20];
    const float* ba1     = (const float*)d_in[21];
    const float* ga      = (const float*)d_in[22];
    const float* betaa   = (const float*)d_in[23];
    const float* Wa2     = (const float*)d_in[24];
    const float* ba2     = (const float*)d_in[25];
    const float* W_post1 = (const float*)d_in[26];
    const float* b_post1 = (const float*)d_in[27];
    const float* W_post2 = (const float*)d_in[28];
    const float* b_post2 = (const float*)d_in[29];
    float* out = (float*)d_out;

    float *p_x;
    cudaGetSymbolAddress((void**)&p_x, g_x);

    const int M8 = B*N1;                         // 8192
    const int PH1_SMEM  = TF32_SMEM_FLOATS*4;                 // 71680 (>= FPS 49152)
    const int PH2_SMEM  = 8192*4 + 512*KNN*8;                 // 98304
    const int ATTN_SMEM = (64*68*2 + 64*132*2 + 16*136*2 + 256)*4 + 64*4;
    const int POST_SMEM = TF32_SMEM_FLOATS*4;

    // 1) phase-1: FPS || pre-projections || weight precomputes || splits || zero
    cudaFuncSetAttribute(phase1_kernel, cudaFuncAttributeMaxDynamicSharedMemorySize, PH1_SMEM);
    phase1_kernel<<<273, 512, PH1_SMEM>>>(dec_pc, enc_pc, dec_x, enc_x,
                                          W_pre1, b_pre1, W_pre2, b_pre2,
                                          Wk, Wq, Wa1, Wp2, bk, bq, bp2, ba1, Wa2);

    // 2) gather sampled features + coords
    gather_kernel<<<M8/4, 256>>>(dec_pc, enc_pc);

    // 3) phase-2: KNN || qa/ka || v
    cudaFuncSetAttribute(phase2_kernel, cudaFuncAttributeMaxDynamicSharedMemorySize, PH2_SMEM);
    phase2_kernel<<<288, 512, PH2_SMEM>>>(dec_pc, Wv, bv);

    // 4) hpos + fused pos-BN stats
    hpos_kernel<<<512, 256>>>(dec_pc, Wp1, bp1);

    // 5) hattn (inline pos-BN finalize) + fused attn-BN stats
    hattn_kernel<<<MROW/64, 256>>>(gp, betap);

    // 6) fused attn/pos mma GEMMs + softmax + aggregation (pre-split weights)
    cudaFuncSetAttribute(attnout_kernel, cudaFuncAttributeMaxDynamicSharedMemorySize, ATTN_SMEM);
    attnout_kernel<<<MROW/64, 256, ATTN_SMEM>>>(ba2, bp2, gp, betap, ga, betaa);

    // 7) outputs (both post GEMMs in one launch)
    float* out1 = out;                                   // [B,N1,256]
    float* opc1 = out + (size_t)M8*D;                    // [B,N1,3]
    float* out2 = opc1 + (size_t)M8*3;                   // [B,N1,256]
    float* opc2 = out2 + (size_t)M8*D;                   // [B,N2,3]
    cudaFuncSetAttribute(gemm_post_kernel, cudaFuncAttributeMaxDynamicSharedMemorySize, POST_SMEM);
    gemm_post_kernel<<<dim3(2, M8/128, 2), 512, POST_SMEM>>>(p_x, W_post1, b_post1, dec_x, out1,
                                                             W_post2, b_post2, out2);
    cudaMemcpyAsync(opc1, dec_pc, (size_t)M8*3*sizeof(float), cudaMemcpyDeviceToDevice);
    cudaMemcpyAsync(opc2, enc_pc, (size_t)B*N2*3*sizeof(float), cudaMemcpyDeviceToDevice);
}

// round 15
// speedup vs baseline: 1.5131x; 1.1884x over previous
#include <cuda_runtime.h>
#include <cuda_bf16.h>
#include <math.h>
#include <stdint.h>

// Problem constants
#define B    4
#define N1   2048
#define N2   2048
#define NC   4096           // N1+N2
#define D    256
#define HP   64
#define HA   64
#define KNN  16
#define MROW (B*N1*KNN)     // 131072
#define INV_MROW (1.0f/131072.0f)

// ---------------- scratch (device globals; no allocation allowed) -------------
__device__ float g_dx  [B*N1*D];
__device__ float g_ex  [B*N2*D];
__device__ float g_sx  [B*N1*D];
__device__ float g_spc [B*N1*3];
__device__ int   g_fidx[B*N1];
__device__ float g_qa  [B*N1*HA];
__device__ float g_ka  [B*N1*HA];
__device__ float g_v   [B*N1*D];
__device__ int   g_nidx[B*N1*KNN];
__device__ float g_hpos [MROW*HP];
__device__ float g_hattn[MROW*HA];
__device__ float g_x   [B*N1*D];
__device__ float g_WkWa1[D*HA];
__device__ float g_WqWa1[D*HA];
__device__ float g_Wp2a [HP*HA];
__device__ float g_cvec [HA];
__device__ float g_Wa2hl[HA*D*2];   // interleaved tf32 hi/lo planes of Wa2
__device__ float g_Wp2hl[HP*D*2];   // interleaved tf32 hi/lo planes of Wp2
// [0:64) psum [64:128) psq [128:192) asum [192:256) asq
__device__ float g_stats[256];

// ================= packed f32x2 helpers (sm_103a FFMA2 path) ==================
#define ADD2(o,a,b)   asm("add.rn.f32x2 %0, %1, %2;" : "=l"(o) : "l"(a), "l"(b))
#define MUL2(o,a,b)   asm("mul.rn.f32x2 %0, %1, %2;" : "=l"(o) : "l"(a), "l"(b))
#define FMA2(o,a,b,c) asm("fma.rn.f32x2 %0, %1, %2, %3;" : "=l"(o) : "l"(a), "l"(b), "l"(c))
__device__ __forceinline__ unsigned long long pack2(float lo, float hi) {
    unsigned long long o;
    asm("mov.b64 %0, {%1, %2};" : "=l"(o) : "r"(__float_as_uint(lo)), "r"(__float_as_uint(hi)));
    return o;
}
__device__ __forceinline__ void unpack2(unsigned long long v, float& lo, float& hi) {
    uint32_t a, b;
    asm("mov.b64 {%0, %1}, %2;" : "=r"(a), "=r"(b) : "l"(v));
    lo = __uint_as_float(a); hi = __uint_as_float(b);
}

// ================= tf32 mma helpers ===========================================
__device__ __forceinline__ uint32_t f2tf(float x) {
    uint32_t r; asm("cvt.rna.tf32.f32 %0, %1;" : "=r"(r) : "f"(x)); return r;
}
__device__ __forceinline__ void mma8(float* d, const uint32_t* a, const uint32_t* b) {
    asm volatile("mma.sync.aligned.m16n8k8.row.col.f32.tf32.tf32.f32 "
        "{%0,%1,%2,%3}, {%4,%5,%6,%7}, {%8,%9}, {%0,%1,%2,%3};"
        : "+f"(d[0]), "+f"(d[1]), "+f"(d[2]), "+f"(d[3])
        : "r"(a[0]), "r"(a[1]), "r"(a[2]), "r"(a[3]), "r"(b[0]), "r"(b[1]));
}

// ------ tf32x2 GEMM body: 128x128 tile, 512 threads, hi/lo planes, 3-mma ------
#define APITCH 36
#define BPITCH 136
#define TF32_SMEM_FLOATS (2*128*APITCH + 2*32*BPITCH)

__device__ __forceinline__ void gemm_tf32_body(
    const float* __restrict__ A, const float* __restrict__ W,
    const float* __restrict__ bias, const float* __restrict__ resid,
    float* __restrict__ C, int bx, int by, int N, int K)
{
    extern __shared__ float smext[];
    float* AHs = smext;
    float* ALs = AHs + 128*APITCH;
    float* BHs = ALs + 128*APITCH;
    float* BLs = BHs + 32*BPITCH;
    int tid = threadIdx.x;
    int row0 = by * 128, col0 = bx * 128;
    int warp = tid >> 5, lane = tid & 31;
    int mw = (warp & 3) * 32, nw = (warp >> 2) * 32;
    int g = lane >> 2, tg = lane & 3;
    float acc[8][4] = {};
    for (int k0 = 0; k0 < K; k0 += 32) {
#pragma unroll
        for (int i = 0; i < 2; i++) {
            int idx = tid + i*512;
            int r = idx >> 3, c4 = (idx & 7) * 4;
            float4 v = *(const float4*)&A[(size_t)(row0+r)*K + k0 + c4];
            float xs[4] = {v.x, v.y, v.z, v.w};
#pragma unroll
            for (int u = 0; u < 4; u++) {
                uint32_t hi = f2tf(xs[u]);
                AHs[r*APITCH + c4+u] = __uint_as_float(hi);
                ALs[r*APITCH + c4+u] = __uint_as_float(f2tf(xs[u] - __uint_as_float(hi)));
            }
        }
#pragma unroll
        for (int i = 0; i < 2; i++) {
            int idx = tid + i*512;
            int r = idx >> 5, c4 = (idx & 31) * 4;
            float4 v = *(const float4*)&W[(size_t)(k0+r)*N + col0 + c4];
            float xs[4] = {v.x, v.y, v.z, v.w};
#pragma unroll
            for (int u = 0; u < 4; u++) {
                uint32_t hi = f2tf(xs[u]);
                BHs[r*BPITCH + c4+u] = __uint_as_float(hi);
                BLs[r*BPITCH + c4+u] = __uint_as_float(f2tf(xs[u] - __uint_as_float(hi)));
            }
        }
        __syncthreads();
#pragma unroll
        for (int ks = 0; ks < 32; ks += 8) {
            uint32_t ah[2][4], al[2][4], bh[4][2], bl[4][2];
#pragma unroll
            for (int mi = 0; mi < 2; mi++) {
                int rb = mw + mi*16;
                ah[mi][0] = __float_as_uint(AHs[(rb+g  )*APITCH + ks+tg  ]);
                ah[mi][1] = __float_as_uint(AHs[(rb+g+8)*APITCH + ks+tg  ]);
                ah[mi][2] = __float_as_uint(AHs[(rb+g  )*APITCH + ks+tg+4]);
                ah[mi][3] = __float_as_uint(AHs[(rb+g+8)*APITCH + ks+tg+4]);
                al[mi][0] = __float_as_uint(ALs[(rb+g  )*APITCH + ks+tg  ]);
                al[mi][1] = __float_as_uint(ALs[(rb+g+8)*APITCH + ks+tg  ]);
                al[mi][2] = __float_as_uint(ALs[(rb+g  )*APITCH + ks+tg+4]);
                al[mi][3] = __float_as_uint(ALs[(rb+g+8)*APITCH + ks+tg+4]);
            }
#pragma unroll
            for (int ni = 0; ni < 4; ni++) {
                bh[ni][0] = __float_as_uint(BHs[(ks+tg  )*BPITCH + nw + ni*8 + g]);
                bh[ni][1] = __float_as_uint(BHs[(ks+tg+4)*BPITCH + nw + ni*8 + g]);
                bl[ni][0] = __float_as_uint(BLs[(ks+tg  )*BPITCH + nw + ni*8 + g]);
                bl[ni][1] = __float_as_uint(BLs[(ks+tg+4)*BPITCH + nw + ni*8 + g]);
            }
#pragma unroll
            for (int mi = 0; mi < 2; mi++)
#pragma unroll
                for (int ni = 0; ni < 4; ni++) {
                    mma8(acc[mi*4+ni], ah[mi], bh[ni]);
                    mma8(acc[mi*4+ni], ah[mi], bl[ni]);
                    mma8(acc[mi*4+ni], al[mi], bh[ni]);
                }
        }
        __syncthreads();
    }
#pragma unroll
    for (int mi = 0; mi < 2; mi++) {
#pragma unroll
        for (int ni = 0; ni < 4; ni++) {
            int c = col0 + nw + ni*8 + 2*tg;
            float b0 = bias ? bias[c]   : 0.f;
            float b1 = bias ? bias[c+1] : 0.f;
            size_t r1 = (size_t)(row0 + mw + mi*16 + g);
            size_t r2 = r1 + 8;
            float v00 = acc[mi*4+ni][0] + b0, v01 = acc[mi*4+ni][1] + b1;
            float v10 = acc[mi*4+ni][2] + b0, v11 = acc[mi*4+ni][3] + b1;
            if (resid) {
                v00 += resid[r1*N+c]; v01 += resid[r1*N+c+1];
                v10 += resid[r2*N+c]; v11 += resid[r2*N+c+1];
            }
            *(float2*)&C[r1*N + c] = make_float2(v00, v01);
            *(float2*)&C[r2*N + c] = make_float2(v10, v11);
        }
    }
}

// ---------------- combined post-GEMMs (z selects output head) ------------------
__global__ void __launch_bounds__(512)
gemm_post_kernel(const float* __restrict__ X,
                 const float* __restrict__ W1, const float* __restrict__ b1,
                 const float* __restrict__ resid1, float* __restrict__ out1,
                 const float* __restrict__ W2, const float* __restrict__ b2,
                 float* __restrict__ out2)
{
    if (blockIdx.z == 0)
        gemm_tf32_body(X, W1, b1, resid1, out1, blockIdx.x, blockIdx.y, D, D);
    else
        gemm_tf32_body(X, W2, b2, nullptr, out2, blockIdx.x, blockIdx.y, D, D);
}

// ---- FPS v3: packed distances + warp-parallel cross reduce, 1 barrier/iter ----
__device__ void fps_body(int b, const float* __restrict__ decpc,
                         const float* __restrict__ encpc)
{
    extern __shared__ float smext[];
    float* sx = smext;
    float* sy = smext + NC;
    float* sz = smext + 2*NC;
    __shared__ unsigned long long swk[2][16];

    int tid = threadIdx.x;
    int wid = tid >> 5, lid = tid & 31;

    for (int j = tid; j < N1; j += 512) {
        sx[j] = decpc[((size_t)b*N1 + j)*3 + 0];
        sy[j] = decpc[((size_t)b*N1 + j)*3 + 1];
        sz[j] = decpc[((size_t)b*N1 + j)*3 + 2];
        sx[N1+j] = encpc[((size_t)b*N2 + j)*3 + 0];
        sy[N1+j] = encpc[((size_t)b*N2 + j)*3 + 1];
        sz[N1+j] = encpc[((size_t)b*N2 + j)*3 + 2];
    }
    if (tid == 0) g_fidx[b*N1] = 0;
    int cur = 0;
    __syncthreads();

    // coords packed in registers (2 points per 64-bit); t = 2p (lo), 2p+1 (hi)
    unsigned long long PX[4], PY[4], PZ[4];
    float md[8];
#pragma unroll
    for (int p = 0; p < 4; p++) {
        int j0 = tid + (2*p)*512, j1 = tid + (2*p+1)*512;
        PX[p] = pack2(sx[j0], sx[j1]);
        PY[p] = pack2(sy[j0], sy[j1]);
        PZ[p] = pack2(sz[j0], sz[j1]);
        md[2*p] = 1e10f; md[2*p+1] = 1e10f;
    }

    for (int i = 1; i < N1; i++) {
        float lx = sx[cur], ly = sy[cur], lz = sz[cur];
        unsigned long long NLX = pack2(-lx, -lx);
        unsigned long long NLY = pack2(-ly, -ly);
        unsigned long long NLZ = pack2(-lz, -lz);
#pragma unroll
        for (int p = 0; p < 4; p++) {
            unsigned long long dx, dy, dz, dd;
            ADD2(dx, PX[p], NLX);
            ADD2(dy, PY[p], NLY);
            ADD2(dz, PZ[p], NLZ);
            MUL2(dd, dx, dx);
            FMA2(dd, dy, dy, dd);
            FMA2(dd, dz, dz, dd);
            float d0, d1; unpack2(dd, d0, d1);
            md[2*p]   = fminf(md[2*p],   d0);
            md[2*p+1] = fminf(md[2*p+1], d1);
        }
        // max over 8 (all >= 0), then smallest t with md[t]==bv
        float bv = fmaxf(fmaxf(fmaxf(md[0],md[1]), fmaxf(md[2],md[3])),
                         fmaxf(fmaxf(md[4],md[5]), fmaxf(md[6],md[7])));
        int bt = 0;
#pragma unroll
        for (int t = 7; t >= 0; t--) if (md[t] == bv) bt = t;
        int besti = tid + bt*512;

        // distances are >= 0, so raw float bits are unsigned-monotone
        unsigned kb = __float_as_uint(bv);
        unsigned mk;
        asm("redux.sync.max.u32 %0, %1, 0xffffffff;" : "=r"(mk) : "r"(kb));
        unsigned idxc = (kb == mk) ? (0xffffffffu - (unsigned)besti) : 0u;
        unsigned mi;
        asm("redux.sync.max.u32 %0, %1, 0xffffffff;" : "=r"(mi) : "r"(idxc));
        int pb = i & 1;
        if (lid == 0)
            swk[pb][wid] = (((unsigned long long)mk) << 32) | (unsigned long long)mi;
        __syncthreads();
        // warp-parallel cross-warp reduce (every warp computes identical result)
        unsigned long long kv = swk[pb][lid & 15];
        unsigned hi32 = (unsigned)(kv >> 32);
        unsigned lo32 = (unsigned)kv;
        unsigned mh;
        asm("redux.sync.max.u32 %0, %1, 0xffffffff;" : "=r"(mh) : "r"(hi32));
        unsigned lc = (hi32 == mh) ? lo32 : 0u;
        unsigned ml;
        asm("redux.sync.max.u32 %0, %1, 0xffffffff;" : "=r"(ml) : "r"(lc));
        cur = (int)(0xffffffffu - ml);
        if (tid == 0) g_fidx[b*N1 + i] = cur;
    }
}

// ---------------- small 64-col GEMM body (weight precomputes), 512 thr --------
#define TBM 64
#define TBK 16
__device__ void gemm64_body(const float* __restrict__ A, const float* __restrict__ W,
                            float* __restrict__ C, int row0, int N, int K)
{
    __shared__ float As64[TBK][TBM];
    __shared__ float Bs64[TBK][64];
    int tid = threadIdx.x;
    for (int k0 = 0; k0 < K; k0 += TBK) {
#pragma unroll
        for (int u = 0; u < 2; u++) {
            int e = tid + u*512;
            int r = e >> 4, c = e & 15;
            As64[c][r] = A[(size_t)(row0 + r)*K + k0 + c];
            int r2 = e >> 6, c2 = e & 63;
            Bs64[r2][c2] = W[(size_t)(k0 + r2)*N + c2];
        }
        __syncthreads();
        if (tid < 256) {
            int tx = tid & 15, ty = tid >> 4;
            float acc[4][4] = {};
#pragma unroll
            for (int kk = 0; kk < TBK; kk++) {
                float a[4], bb[4];
#pragma unroll
                for (int i = 0; i < 4; i++) a[i] = As64[kk][ty*4+i];
#pragma unroll
                for (int j = 0; j < 4; j++) bb[j] = Bs64[kk][tx*4+j];
#pragma unroll
                for (int i = 0; i < 4; i++)
#pragma unroll
                    for (int j = 0; j < 4; j++)
                        acc[i][j] += a[i]*bb[j];
            }
#pragma unroll
            for (int i = 0; i < 4; i++)
#pragma unroll
                for (int j = 0; j < 4; j++) {
                    size_t off = (size_t)(row0 + ty*4 + i)*N + tx*4 + j;
                    if (k0 == 0) C[off] = acc[i][j];
                    else         C[off] += acc[i][j];
                }
        }
        __syncthreads();
    }
}

// ---------------- cvec body: (bk - bq + bp2) @ Wa1 + ba1, 512 thr --------------
__device__ void cvec_body(const float* __restrict__ bk, const float* __restrict__ bq,
                          const float* __restrict__ bp2, const float* __restrict__ Wa1,
                          const float* __restrict__ ba1)
{
    __shared__ float shc[512];
    int c = threadIdx.x & 63;
    int part = threadIdx.x >> 6;     // 0..7
    float s = 0.f;
    for (int i = part*32; i < part*32 + 32; i++)
        s += (bk[i] - bq[i] + bp2[i]) * Wa1[(size_t)i*HA + c];
    shc[threadIdx.x] = s;
    __syncthreads();
    if (part == 0) {
        float t = ba1[c];
#pragma unroll
        for (int p = 0; p < 8; p++) t += shc[p*64 + c];
        g_cvec[c] = t;
    }
}

// ---------------- weight hi/lo split body (once per launch) -------------------
__device__ void wsplit_body(const float* __restrict__ W, float* __restrict__ out, int n)
{
    for (int i = threadIdx.x; i < n; i += 512) {
        float x = W[i];
        uint32_t hi = f2tf(x);
        out[2*i]   = __uint_as_float(hi);
        out[2*i+1] = __uint_as_float(f2tf(x - __uint_as_float(hi)));
    }
}

// ---------------- phase-1 mega-kernel -----------------------------------------
// [0,4)=FPS [4,132)=pre1 [132,260)=pre2 [260,264)=WkWa1 [264,268)=WqWa1
// [268]=Wp2a [269]=cvec [270]=zero_stats [271]=split Wa2 [272]=split Wp2
__global__ void __launch_bounds__(512)
phase1_kernel(const float* __restrict__ dec_pc, const float* __restrict__ enc_pc,
              const float* __restrict__ dec_x,  const float* __restrict__ enc_x,
              const float* __restrict__ W_pre1, const float* __restrict__ b_pre1,
              const float* __restrict__ W_pre2, const float* __restrict__ b_pre2,
              const float* __restrict__ Wk, const float* __restrict__ Wq,
              const float* __restrict__ Wa1, const float* __restrict__ Wp2,
              const float* __restrict__ bk, const float* __restrict__ bq,
              const float* __restrict__ bp2, const float* __restrict__ ba1,
              const float* __restrict__ Wa2)
{
    int bid = blockIdx.x;
    if (bid < 4) {
        fps_body(bid, dec_pc, enc_pc);
    } else if (bid < 132) {
        int t = bid - 4;
        gemm_tf32_body(dec_x, W_pre1, b_pre1, nullptr, g_dx, t & 1, t >> 1, D, D);
    } else if (bid < 260) {
        int t = bid - 132;
        gemm_tf32_body(enc_x, W_pre2, b_pre2, nullptr, g_ex, t & 1, t >> 1, D, D);
    } else if (bid < 264) {
        gemm64_body(Wk, Wa1, g_WkWa1, (bid-260)*64, HA, D);
    } else if (bid < 268) {
        gemm64_body(Wq, Wa1, g_WqWa1, (bid-264)*64, HA, D);
    } else if (bid == 268) {
        gemm64_body(Wp2, Wa1, g_Wp2a, 0, HA, D);
    } else if (bid == 269) {
        cvec_body(bk, bq, bp2, Wa1, ba1);
    } else if (bid == 270) {
        if (threadIdx.x < 256) g_stats[threadIdx.x] = 0.0f;
    } else if (bid == 271) {
        wsplit_body(Wa2, g_Wa2hl, HA*D);
    } else {
        wsplit_body(Wp2, g_Wp2hl, HP*D);
    }
}

// ---------------- gather sampled features + coords ----------------------------
__global__ void gather_kernel(const float* __restrict__ decpc,
                              const float* __restrict__ encpc)
{
    int row = blockIdx.x*4 + (threadIdx.x >> 6);
    int c4  = (threadIdx.x & 63) * 4;
    int b = row >> 11;
    int j = g_fidx[row];
    const float* src = (j < N1) ? &g_dx[((size_t)b*N1 + j)*D]
                                : &g_ex[((size_t)b*N2 + (j - N1))*D];
    *(float4*)&g_sx[(size_t)row*D + c4] = *(const float4*)&src[c4];
    if ((threadIdx.x & 63) < 3) {
        int cc = threadIdx.x & 63;
        const float* ps = (j < N1) ? &decpc[((size_t)b*N1 + j)*3]
                                   : &encpc[((size_t)b*N2 + (j - N1))*3];
        g_spc[(size_t)row*3 + cc] = ps[cc];
    }
}

// ---------------- N=64 GEMM body for 512 threads (qa/ka) -----------------------
__device__ void n64_body_512(const float* __restrict__ A, const float* __restrict__ W,
                             float* __restrict__ C, int row0)
{
    __shared__ float Asq[16][132];
    __shared__ float Bsq[16][64];
    int tid = threadIdx.x;
    int tx = tid & 15, ty = tid >> 4;          // ty 0..31
    float acc[4][4] = {};
    for (int k0 = 0; k0 < D; k0 += 16) {
        {
            int r = tid >> 2, kq = (tid & 3) * 4;
            float4 va = *(const float4*)&A[(size_t)(row0 + r)*D + k0 + kq];
            Asq[kq+0][r] = va.x; Asq[kq+1][r] = va.y;
            Asq[kq+2][r] = va.z; Asq[kq+3][r] = va.w;
        }
        if (tid < 256) {
            int r = tid >> 4, cq = (tid & 15) * 4;
            *(float4*)&Bsq[r][cq] = *(const float4*)&W[(size_t)(k0 + r)*HA + cq];
        }
        __syncthreads();
#pragma unroll
        for (int kk = 0; kk < 16; kk++) {
            float a[4], bb[4];
#pragma unroll
            for (int i = 0; i < 4; i++) a[i] = Asq[kk][ty*4+i];
#pragma unroll
            for (int j = 0; j < 4; j++) bb[j] = Bsq[kk][tx*4+j];
#pragma unroll
            for (int i = 0; i < 4; i++)
#pragma unroll
                for (int j = 0; j < 4; j++)
                    acc[i][j] += a[i]*bb[j];
        }
        __syncthreads();
    }
#pragma unroll
    for (int i = 0; i < 4; i++)
#pragma unroll
        for (int j = 0; j < 4; j++)
            C[(size_t)(row0 + ty*4 + i)*HA + tx*4 + j] = acc[i][j];
}

// ---------------- phase-2 mega-kernel: KNN + qa/ka + v -------------------------
__global__ void __launch_bounds__(512)
phase2_kernel(const float* __restrict__ decpc,
              const float* __restrict__ Wv, const float* __restrict__ bv)
{
    int bid = blockIdx.x;
    if (bid < 32) {
        extern __shared__ float s2[];
        float* px = s2; float* py = px + 2048; float* pz = py + 2048; float* s2s = pz + 2048;
        unsigned long long* buf = (unsigned long long*)(s2 + 8192);
        int tid = threadIdx.x;
        int b = bid >> 3, qb = bid & 7;
        for (int m = tid; m < 2048; m += 512) {
            float x = g_spc[((size_t)b*N1 + m)*3 + 0];
            float y = g_spc[((size_t)b*N1 + m)*3 + 1];
            float z = g_spc[((size_t)b*N1 + m)*3 + 2];
            px[m] = x; py[m] = y; pz[m] = z;
            s2s[m] = x*x + y*y + z*z;
        }
        __syncthreads();
        int qi = tid & 255, h = tid >> 8;
        int q = qb*256 + qi;
        float qx = decpc[((size_t)b*N1 + q)*3 + 0];
        float qy = decpc[((size_t)b*N1 + q)*3 + 1];
        float qz = decpc[((size_t)b*N1 + q)*3 + 2];
        float s1 = qx*qx + qy*qy + qz*qz;
        float bd[KNN]; int bi[KNN];
#pragma unroll
        for (int t = 0; t < KNN; t++) { bd[t] = 1e30f; bi[t] = 0; }
        int mbase = h * 1024;
        for (int mm = 0; mm < 1024; mm++) {
            int m = mbase + mm;
            float d = s1 + s2s[m] - 2.0f*(qx*px[m] + qy*py[m] + qz*pz[m]);
            if (d < bd[KNN-1]) {
                bd[KNN-1] = d; bi[KNN-1] = m;
#pragma unroll
                for (int t = KNN-1; t > 0; t--) {
                    if (bd[t] < bd[t-1]) {
                        float td = bd[t]; bd[t] = bd[t-1]; bd[t-1] = td;
                        int   ti = bi[t]; bi[t] = bi[t-1]; bi[t-1] = ti;
                    }
                }
            }
        }
#pragma unroll
        for (int t = 0; t < KNN; t++) {
            unsigned u = __float_as_uint(bd[t]);
            u = ((int)u < 0) ? ~u : (u | 0x80000000u);
            buf[(size_t)tid*KNN + t] = (((unsigned long long)u) << 32) | (unsigned)bi[t];
        }
        __syncthreads();
        if (h == 0) {
            const unsigned long long* A_ = &buf[(size_t)qi*KNN];
            const unsigned long long* B_ = &buf[(size_t)(qi+256)*KNN];
            int* outp = &g_nidx[((size_t)b*N1 + q)*KNN];
            int ia = 0, ib = 0;
#pragma unroll
            for (int o = 0; o < KNN; o++) {
                unsigned long long av = A_[ia], bv_ = B_[ib];
                if ((av >> 32) <= (bv_ >> 32)) { outp[o] = (int)(unsigned)av; ia++; }
                else                           { outp[o] = (int)(unsigned)bv_; ib++; }
            }
        }
    } else if (bid < 160) {
        int t = bid - 32;
        int sel = t >> 6, tile = t & 63;
        n64_body_512(sel ? g_sx : g_dx, sel ? g_WkWa1 : g_WqWa1,
                     sel ? g_ka : g_qa, tile*128);
    } else {
        int t = bid - 160;
        gemm_tf32_body(g_sx, Wv, bv, nullptr, g_v, t & 1, t >> 1, D, D);
    }
}

// ---------------- hpos + fused BN stats ----------------------------------------
__global__ void __launch_bounds__(256)
hpos_kernel(const float* __restrict__ decpc,
            const float* __restrict__ Wp1,
            const float* __restrict__ bp1)
{
    int tid = threadIdx.x;
    int c = tid & 63;
    int rg = tid >> 6;
    float w0 = Wp1[c], w1 = Wp1[64+c], w2 = Wp1[128+c], bb = bp1[c];
    float s = 0.f, s2 = 0.f;
    int base = blockIdx.x * 256;
    for (int it = 0; it < 64; it++) {
        int m = base + it*4 + rg;
        int b = m >> 15;
        int n = (m >> 4) & 2047;
        int j = g_nidx[m];
        const float* pp = &g_spc[((size_t)b*N1 + j)*3];
        const float* qq = &decpc[((size_t)b*N1 + n)*3];
        float p0 = pp[0]-qq[0], p1 = pp[1]-qq[1], p2 = pp[2]-qq[2];
        float h = p0*w0 + p1*w1 + p2*w2 + bb;
        g_hpos[(size_t)m*HP + c] = h;
        s += h; s2 += h*h;
    }
    __shared__ float sh[256], sh2[256];
    sh[tid] = s; sh2[tid] = s2;
    __syncthreads();
    if (rg == 0) {
        atomicAdd(&g_stats[c],    sh[c] + sh[64+c] + sh[128+c] + sh[192+c]);
        atomicAdd(&g_stats[64+c], sh2[c] + sh2[64+c] + sh2[128+c] + sh2[192+c]);
    }
}

// ---- hattn = relu(bn_pos(hp)) @ Wp2a + ka[gather] - qa + cvec + stats --------
__global__ void __launch_bounds__(256)
hattn_kernel(const float* __restrict__ gp, const float* __restrict__ betap)
{
    __shared__ float Aw[64][65];
    __shared__ float Bw[64*64];
    __shared__ float psc[64], psh[64];
    __shared__ float rs[16][64], rs2[16][64];
    int tid = threadIdx.x;
    int m0 = blockIdx.x * 64;
    if (tid < 64) {
        float mean = g_stats[tid] * INV_MROW;
        float var  = g_stats[64+tid] * INV_MROW - mean*mean;
        float sc = gp[tid]*rsqrtf(var + 1e-5f);
        psc[tid] = sc;
        psh[tid] = betap[tid] - mean*sc;
    }
    __syncthreads();
#pragma unroll
    for (int i = 0; i < 16; i++) {
        int idx = tid + i*256;
        int r = idx >> 6, k = idx & 63;
        float h = g_hpos[(size_t)(m0+r)*64 + k];
        Aw[r][k] = fmaxf(h*psc[k] + psh[k], 0.0f);
        Bw[idx] = g_Wp2a[idx];
    }
    __syncthreads();
    int tx = tid & 15, ty = tid >> 4;
    float acc[4][4] = {};
#pragma unroll 4
    for (int kk = 0; kk < 64; kk++) {
        float a[4], bb[4];
#pragma unroll
        for (int i = 0; i < 4; i++) a[i] = Aw[ty*4+i][kk];
#pragma unroll
        for (int j = 0; j < 4; j++) bb[j] = Bw[kk*64 + tx*4 + j];
#pragma unroll
        for (int i = 0; i < 4; i++)
#pragma unroll
            for (int j = 0; j < 4; j++)
                acc[i][j] += a[i]*bb[j];
    }
    float ps[4] = {0,0,0,0}, ps2[4] = {0,0,0,0};
#pragma unroll
    for (int i = 0; i < 4; i++) {
        int m = m0 + ty*4 + i;
        int b = m >> 15;
        int n = (m >> 4) & 2047;
        int jj = g_nidx[m];
        const float* kar = &g_ka[(((size_t)b<<11) + jj)*HA];
        const float* qar = &g_qa[(((size_t)b<<11) + n )*HA];
#pragma unroll
        for (int j = 0; j < 4; j++) {
            int c = tx*4 + j;
            float v = acc[i][j] + kar[c] - qar[c] + g_cvec[c];
            g_hattn[(size_t)m*HA + c] = v;
            ps[j] += v; ps2[j] += v*v;
        }
    }
#pragma unroll
    for (int j = 0; j < 4; j++) {
        rs[ty][tx*4+j] = ps[j];
        rs2[ty][tx*4+j] = ps2[j];
    }
    __syncthreads();
    if (tid < 64) {
        float s = 0.f, s2 = 0.f;
#pragma unroll
        for (int t = 0; t < 16; t++) { s += rs[t][tid]; s2 += rs2[t][tid]; }
        atomicAdd(&g_stats[128+tid], s);
        atomicAdd(&g_stats[192+tid], s2);
    }
}

// ---- fused: attn/pos GEMMs via tf32x2 mma + softmax(K) + agg -> g_x ----------
// grid 2048; block handles 64 rows x 256 cols (two 128-col halves, A reused)
// B planes come pre-split from g_Wa2hl / g_Wp2hl (interleaved hi/lo).
__global__ void __launch_bounds__(256)
attnout_kernel(const float* __restrict__ ba2,
               const float* __restrict__ bp2,
               const float* __restrict__ gp, const float* __restrict__ betap,
               const float* __restrict__ ga, const float* __restrict__ betaa)
{
    extern __shared__ float sm[];
    float* Ahr    = sm;                 // [64][68]
    float* Apr    = Ahr + 64*68;        // [64][68]
    float* attn_s = Apr + 64*68;        // [64][132]
    float* pos_s  = attn_s + 64*132;    // [64][132]
    float* Bh     = pos_s + 64*132;     // [16][136]
    float* Bl     = Bh + 16*136;        // [16][136]
    float* scbuf  = Bl + 16*136;        // psc,psh,asc,ash [4][64]
    int*   sj     = (int*)(scbuf + 256);// [64]

    int tid = threadIdx.x;
    int m0 = blockIdx.x * 64;
    int warp = tid >> 5, lane = tid & 31;
    int mw = (warp & 3) * 16, nw = (warp >> 2) * 64;
    int g = lane >> 2, tg = lane & 3;

    if (tid < 64) {
        float mean = g_stats[tid] * INV_MROW;
        float var  = g_stats[64+tid] * INV_MROW - mean*mean;
        float sc = gp[tid]*rsqrtf(var + 1e-5f);
        scbuf[tid] = sc;
        scbuf[64+tid] = betap[tid] - mean*sc;
        mean = g_stats[128+tid] * INV_MROW;
        var  = g_stats[192+tid] * INV_MROW - mean*mean;
        sc = ga[tid]*rsqrtf(var + 1e-5f);
        scbuf[128+tid] = sc;
        scbuf[192+tid] = betaa[tid] - mean*sc;
        sj[tid] = g_nidx[m0 + tid];
    }
    __syncthreads();

#pragma unroll
    for (int i = 0; i < 16; i++) {
        int idx = tid + i*256;
        int r = idx >> 6, k = idx & 63;
        float ha = g_hattn[(size_t)(m0+r)*64 + k];
        Ahr[r*68 + k] = fmaxf(ha*scbuf[128+k] + scbuf[192+k], 0.0f);
        float hp = g_hpos[(size_t)(m0+r)*64 + k];
        Apr[r*68 + k] = fmaxf(hp*scbuf[k] + scbuf[64+k], 0.0f);
    }

    for (int half = 0; half < 2; half++) {
        int c0 = half * 128;
#pragma unroll
        for (int pass = 0; pass < 2; pass++) {
            const float* Whl  = pass ? g_Wp2hl : g_Wa2hl;
            const float* bsrc = pass ? bp2 : ba2;
            const float* Asm  = pass ? Apr : Ahr;
            float* Out = pass ? pos_s : attn_s;
            float acc[8][4] = {};
            for (int k0 = 0; k0 < 64; k0 += 16) {
                __syncthreads();
#pragma unroll
                for (int i = 0; i < 8; i++) {
                    int idx = tid + i*256;
                    int r = idx >> 7, c = idx & 127;
                    float2 hl = *(const float2*)&Whl[((size_t)(k0+r)*D + c0 + c)*2];
                    Bh[r*136 + c] = hl.x;
                    Bl[r*136 + c] = hl.y;
                }
                __syncthreads();
#pragma unroll
                for (int ks = 0; ks < 16; ks += 8) {
                    uint32_t ah[4], al[4];
                    {
                        float x0 = Asm[(mw+g  )*68 + k0+ks+tg  ];
                        float x1 = Asm[(mw+g+8)*68 + k0+ks+tg  ];
                        float x2 = Asm[(mw+g  )*68 + k0+ks+tg+4];
                        float x3 = Asm[(mw+g+8)*68 + k0+ks+tg+4];
                        ah[0] = f2tf(x0); al[0] = f2tf(x0 - __uint_as_float(ah[0]));
                        ah[1] = f2tf(x1); al[1] = f2tf(x1 - __uint_as_float(ah[1]));
                        ah[2] = f2tf(x2); al[2] = f2tf(x2 - __uint_as_float(ah[2]));
                        ah[3] = f2tf(x3); al[3] = f2tf(x3 - __uint_as_float(ah[3]));
                    }
#pragma unroll
                    for (int ni = 0; ni < 8; ni++) {
                        uint32_t bhf[2], blf[2];
                        bhf[0] = __float_as_uint(Bh[(ks+tg  )*136 + nw + ni*8 + g]);
                        bhf[1] = __float_as_uint(Bh[(ks+tg+4)*136 + nw + ni*8 + g]);
                        blf[0] = __float_as_uint(Bl[(ks+tg  )*136 + nw + ni*8 + g]);
                        blf[1] = __float_as_uint(Bl[(ks+tg+4)*136 + nw + ni*8 + g]);
                        mma8(acc[ni], ah, bhf);
                        mma8(acc[ni], ah, blf);
                        mma8(acc[ni], al, bhf);
                    }
                }
            }
#pragma unroll
            for (int ni = 0; ni < 8; ni++) {
                int c = nw + ni*8 + 2*tg;
                float b0 = bsrc[c0 + c], b1 = bsrc[c0 + c + 1];
                Out[(mw+g  )*132 + c]     = acc[ni][0] + b0;
                Out[(mw+g  )*132 + c + 1] = acc[ni][1] + b1;
                Out[(mw+g+8)*132 + c]     = acc[ni][2] + b0;
                Out[(mw+g+8)*132 + c + 1] = acc[ni][3] + b1;
            }
        }
        __syncthreads();

        // softmax over 16 neighbors + aggregation for this 128-col half
#pragma unroll
        for (int e = tid; e < 512; e += 256) {
            int q = e >> 7;            // 0..3
            int c = e & 127;
            int mrow = q*16;
            float mx = -1e30f;
#pragma unroll
            for (int k = 0; k < KNN; k++)
                mx = fmaxf(mx, attn_s[(mrow+k)*132 + c]);
            float w[KNN]; float s = 0.f;
#pragma unroll
            for (int k = 0; k < KNN; k++) {
                w[k] = __expf(attn_s[(mrow+k)*132 + c] - mx);
                s += w[k];
            }
            float inv = 1.0f / s;
            int qg = (m0 >> 4) + q;
            int b = qg >> 11;
            float x = 0.f;
#pragma unroll
            for (int k = 0; k < KNN; k++) {
                int j = sj[mrow + k];
                float vv = g_v[(((size_t)b<<11) + j)*D + c0 + c] + pos_s[(mrow+k)*132 + c];
                x += vv * w[k];
            }
            g_x[(size_t)qg*D + c0 + c] = x * inv;
        }
        __syncthreads();
    }
}

// =================================================================================
extern "C" void kernel_launch(void* const* d_in, const int* in_sizes, int n_in,
                              void* d_out, int out_size)
{
    const float* dec_x   = (const float*)d_in[0];
    const float* dec_pc  = (const float*)d_in[1];
    const float* enc_x   = (const float*)d_in[2];
    const float* enc_pc  = (const float*)d_in[3];
    const float* W_pre1  = (const float*)d_in[4];
    const float* b_pre1  = (const float*)d_in[5];
    const float* W_pre2  = (const float*)d_in[6];
    const float* b_pre2  = (const float*)d_in[7];
    const float* Wq      = (const float*)d_in[8];
    const float* bq      = (const float*)d_in[9];
    const float* Wk      = (const float*)d_in[10];
    const float* bk      = (const float*)d_in[11];
    const float* Wv      = (const float*)d_in[12];
    const float* bv      = (const float*)d_in[13];
    const float* Wp1     = (const float*)d_in[14];
    const float* bp1     = (const float*)d_in[15];
    const float* gp      = (const float*)d_in[16];
    const float* betap   = (const float*)d_in[17];
    const float* Wp2     = (const float*)d_in[18];
    const float* bp2     = (const float*)d_in[19];
    const float* Wa1     = (const float*)d_in[20];
    const float* ba1     = (const float*)d_in[21];
    const float* ga      = (const float*)d_in[22];
    const float* betaa   = (const float*)d_in[23];
    const float* Wa2     = (const float*)d_in[24];
    const float* ba2     = (const float*)d_in[25];
    const float* W_post1 = (const float*)d_in[26];
    const float* b_post1 = (const float*)d_in[27];
    const float* W_post2 = (const float*)d_in[28];
    const float* b_post2 = (const float*)d_in[29];
    float* out = (float*)d_out;

    float *p_x;
    cudaGetSymbolAddress((void**)&p_x, g_x);

    const int M8 = B*N1;                         // 8192
    const int PH1_SMEM  = TF32_SMEM_FLOATS*4;                 // 71680 (>= FPS 49152)
    const int PH2_SMEM  = 8192*4 + 512*KNN*8;                 // 98304
    const int ATTN_SMEM = (64*68*2 + 64*132*2 + 16*136*2 + 256)*4 + 64*4;
    const int POST_SMEM = TF32_SMEM_FLOATS*4;

    // 1) phase-1: FPS || pre-projections || weight precomputes || splits || zero
    cudaFuncSetAttribute(phase1_kernel, cudaFuncAttributeMaxDynamicSharedMemorySize, PH1_SMEM);
    phase1_kernel<<<273, 512, PH1_SMEM>>>(dec_pc, enc_pc, dec_x, enc_x,
                                          W_pre1, b_pre1, W_pre2, b_pre2,
                                          Wk, Wq, Wa1, Wp2, bk, bq, bp2, ba1, Wa2);

    // 2) gather sampled features + coords
    gather_kernel<<<M8/4, 256>>>(dec_pc, enc_pc);

    // 3) phase-2: KNN || qa/ka || v
    cudaFuncSetAttribute(phase2_kernel, cudaFuncAttributeMaxDynamicSharedMemorySize, PH2_SMEM);
    phase2_kernel<<<288, 512, PH2_SMEM>>>(dec_pc, Wv, bv);

    // 4) hpos + fused pos-BN stats
    hpos_kernel<<<512, 256>>>(dec_pc, Wp1, bp1);

    // 5) hattn (inline pos-BN finalize) + fused attn-BN stats
    hattn_kernel<<<MROW/64, 256>>>(gp, betap);

    // 6) fused attn/pos mma GEMMs + softmax + aggregation (pre-split weights)
    cudaFuncSetAttribute(attnout_kernel, cudaFuncAttributeMaxDynamicSharedMemorySize, ATTN_SMEM);
    attnout_kernel<<<MROW/64, 256, ATTN_SMEM>>>(ba2, bp2, gp, betap, ga, betaa);

    // 7) outputs (both post GEMMs in one launch)
    float* out1 = out;                                   // [B,N1,256]
    float* opc1 = out + (size_t)M8*D;                    // [B,N1,3]
    float* out2 = opc1 + (size_t)M8*3;                   // [B,N1,256]
    float* opc2 = out2 + (size_t)M8*D;                   // [B,N2,3]
    cudaFuncSetAttribute(gemm_post_kernel, cudaFuncAttributeMaxDynamicSharedMemorySize, POST_SMEM);
    gemm_post_kernel<<<dim3(2, M8/128, 2), 512, POST_SMEM>>>(p_x, W_post1, b_post1, dec_x, out1,
                                                             W_post2, b_post2, out2);
    cudaMemcpyAsync(opc1, dec_pc, (size_t)M8*3*sizeof(float), cudaMemcpyDeviceToDevice);
    cudaMemcpyAsync(opc2, enc_pc, (size_t)B*N2*3*sizeof(float), cudaMemcpyDeviceToDevice);
}

// round 16
// speedup vs baseline: 1.5341x; 1.0139x over previous
#include <cuda_runtime.h>
#include <cuda_bf16.h>
#include <math.h>
#include <stdint.h>

// Problem constants
#define B    4
#define N1   2048
#define N2   2048
#define NC   4096           // N1+N2
#define D    256
#define HP   64
#define HA   64
#define KNN  16
#define MROW (B*N1*KNN)     // 131072
#define INV_MROW (1.0f/131072.0f)

// ---------------- scratch (device globals; no allocation allowed) -------------
__device__ float g_dx  [B*N1*D];
__device__ float g_ex  [B*N2*D];
__device__ float g_sx  [B*N1*D];
__device__ float g_spc [B*N1*3];
__device__ int   g_fidx[B*N1];
__device__ float g_qa  [B*N1*HA];
__device__ float g_ka  [B*N1*HA];
__device__ float g_v   [B*N1*D];
__device__ int   g_nidx[B*N1*KNN];
__device__ float g_hpos [MROW*HP];
__device__ float g_hattn[MROW*HA];
__device__ float g_x   [B*N1*D];
__device__ float g_WkWa1[D*HA];
__device__ float g_WqWa1[D*HA];
__device__ float g_Wp2a [HP*HA];
__device__ float g_cvec [HA];
__device__ float g_Wa2hl[HA*D*2];   // interleaved tf32 hi/lo planes of Wa2
__device__ float g_Wp2hl[HP*D*2];   // interleaved tf32 hi/lo planes of Wp2
// [0:64) psum [64:128) psq [128:192) asum [192:256) asq
__device__ float g_stats[256];

// ================= packed f32x2 helpers (sm_103a FFMA2 path) ==================
#define ADD2(o,a,b)   asm("add.rn.f32x2 %0, %1, %2;" : "=l"(o) : "l"(a), "l"(b))
#define MUL2(o,a,b)   asm("mul.rn.f32x2 %0, %1, %2;" : "=l"(o) : "l"(a), "l"(b))
#define FMA2(o,a,b,c) asm("fma.rn.f32x2 %0, %1, %2, %3;" : "=l"(o) : "l"(a), "l"(b), "l"(c))
__device__ __forceinline__ unsigned long long pack2(float lo, float hi) {
    unsigned long long o;
    asm("mov.b64 %0, {%1, %2};" : "=l"(o) : "r"(__float_as_uint(lo)), "r"(__float_as_uint(hi)));
    return o;
}
__device__ __forceinline__ void unpack2(unsigned long long v, float& lo, float& hi) {
    uint32_t a, b;
    asm("mov.b64 {%0, %1}, %2;" : "=r"(a), "=r"(b) : "l"(v));
    lo = __uint_as_float(a); hi = __uint_as_float(b);
}

// ================= tf32 mma helpers ===========================================
__device__ __forceinline__ uint32_t f2tf(float x) {
    uint32_t r; asm("cvt.rna.tf32.f32 %0, %1;" : "=r"(r) : "f"(x)); return r;
}
__device__ __forceinline__ void mma8(float* d, const uint32_t* a, const uint32_t* b) {
    asm volatile("mma.sync.aligned.m16n8k8.row.col.f32.tf32.tf32.f32 "
        "{%0,%1,%2,%3}, {%4,%5,%6,%7}, {%8,%9}, {%0,%1,%2,%3};"
        : "+f"(d[0]), "+f"(d[1]), "+f"(d[2]), "+f"(d[3])
        : "r"(a[0]), "r"(a[1]), "r"(a[2]), "r"(a[3]), "r"(b[0]), "r"(b[1]));
}

// ------ tf32x2 GEMM body: 128x128 tile, 512 threads, hi/lo planes, 3-mma ------
#define APITCH 36
#define BPITCH 136
#define TF32_SMEM_FLOATS (2*128*APITCH + 2*32*BPITCH)

__device__ __forceinline__ void gemm_tf32_body(
    const float* __restrict__ A, const float* __restrict__ W,
    const float* __restrict__ bias, const float* __restrict__ resid,
    float* __restrict__ C, int bx, int by, int N, int K)
{
    extern __shared__ float smext[];
    float* AHs = smext;
    float* ALs = AHs + 128*APITCH;
    float* BHs = ALs + 128*APITCH;
    float* BLs = BHs + 32*BPITCH;
    int tid = threadIdx.x;
    int row0 = by * 128, col0 = bx * 128;
    int warp = tid >> 5, lane = tid & 31;
    int mw = (warp & 3) * 32, nw = (warp >> 2) * 32;
    int g = lane >> 2, tg = lane & 3;
    float acc[8][4] = {};
    for (int k0 = 0; k0 < K; k0 += 32) {
#pragma unroll
        for (int i = 0; i < 2; i++) {
            int idx = tid + i*512;
            int r = idx >> 3, c4 = (idx & 7) * 4;
            float4 v = *(const float4*)&A[(size_t)(row0+r)*K + k0 + c4];
            float xs[4] = {v.x, v.y, v.z, v.w};
#pragma unroll
            for (int u = 0; u < 4; u++) {
                uint32_t hi = f2tf(xs[u]);
                AHs[r*APITCH + c4+u] = __uint_as_float(hi);
                ALs[r*APITCH + c4+u] = __uint_as_float(f2tf(xs[u] - __uint_as_float(hi)));
            }
        }
#pragma unroll
        for (int i = 0; i < 2; i++) {
            int idx = tid + i*512;
            int r = idx >> 5, c4 = (idx & 31) * 4;
            float4 v = *(const float4*)&W[(size_t)(k0+r)*N + col0 + c4];
            float xs[4] = {v.x, v.y, v.z, v.w};
#pragma unroll
            for (int u = 0; u < 4; u++) {
                uint32_t hi = f2tf(xs[u]);
                BHs[r*BPITCH + c4+u] = __uint_as_float(hi);
                BLs[r*BPITCH + c4+u] = __uint_as_float(f2tf(xs[u] - __uint_as_float(hi)));
            }
        }
        __syncthreads();
#pragma unroll
        for (int ks = 0; ks < 32; ks += 8) {
            uint32_t ah[2][4], al[2][4], bh[4][2], bl[4][2];
#pragma unroll
            for (int mi = 0; mi < 2; mi++) {
                int rb = mw + mi*16;
                ah[mi][0] = __float_as_uint(AHs[(rb+g  )*APITCH + ks+tg  ]);
                ah[mi][1] = __float_as_uint(AHs[(rb+g+8)*APITCH + ks+tg  ]);
                ah[mi][2] = __float_as_uint(AHs[(rb+g  )*APITCH + ks+tg+4]);
                ah[mi][3] = __float_as_uint(AHs[(rb+g+8)*APITCH + ks+tg+4]);
                al[mi][0] = __float_as_uint(ALs[(rb+g  )*APITCH + ks+tg  ]);
                al[mi][1] = __float_as_uint(ALs[(rb+g+8)*APITCH + ks+tg  ]);
                al[mi][2] = __float_as_uint(ALs[(rb+g  )*APITCH + ks+tg+4]);
                al[mi][3] = __float_as_uint(ALs[(rb+g+8)*APITCH + ks+tg+4]);
            }
#pragma unroll
            for (int ni = 0; ni < 4; ni++) {
                bh[ni][0] = __float_as_uint(BHs[(ks+tg  )*BPITCH + nw + ni*8 + g]);
                bh[ni][1] = __float_as_uint(BHs[(ks+tg+4)*BPITCH + nw + ni*8 + g]);
                bl[ni][0] = __float_as_uint(BLs[(ks+tg  )*BPITCH + nw + ni*8 + g]);
                bl[ni][1] = __float_as_uint(BLs[(ks+tg+4)*BPITCH + nw + ni*8 + g]);
            }
#pragma unroll
            for (int mi = 0; mi < 2; mi++)
#pragma unroll
                for (int ni = 0; ni < 4; ni++) {
                    mma8(acc[mi*4+ni], ah[mi], bh[ni]);
                    mma8(acc[mi*4+ni], ah[mi], bl[ni]);
                    mma8(acc[mi*4+ni], al[mi], bh[ni]);
                }
        }
        __syncthreads();
    }
#pragma unroll
    for (int mi = 0; mi < 2; mi++) {
#pragma unroll
        for (int ni = 0; ni < 4; ni++) {
            int c = col0 + nw + ni*8 + 2*tg;
            float b0 = bias ? bias[c]   : 0.f;
            float b1 = bias ? bias[c+1] : 0.f;
            size_t r1 = (size_t)(row0 + mw + mi*16 + g);
            size_t r2 = r1 + 8;
            float v00 = acc[mi*4+ni][0] + b0, v01 = acc[mi*4+ni][1] + b1;
            float v10 = acc[mi*4+ni][2] + b0, v11 = acc[mi*4+ni][3] + b1;
            if (resid) {
                v00 += resid[r1*N+c]; v01 += resid[r1*N+c+1];
                v10 += resid[r2*N+c]; v11 += resid[r2*N+c+1];
            }
            *(float2*)&C[r1*N + c] = make_float2(v00, v01);
            *(float2*)&C[r2*N + c] = make_float2(v10, v11);
        }
    }
}

// ---------------- combined post-GEMMs (z selects output head) ------------------
__global__ void __launch_bounds__(512)
gemm_post_kernel(const float* __restrict__ X,
                 const float* __restrict__ W1, const float* __restrict__ b1,
                 const float* __restrict__ resid1, float* __restrict__ out1,
                 const float* __restrict__ W2, const float* __restrict__ b2,
                 float* __restrict__ out2)
{
    if (blockIdx.z == 0)
        gemm_tf32_body(X, W1, b1, resid1, out1, blockIdx.x, blockIdx.y, D, D);
    else
        gemm_tf32_body(X, W2, b2, nullptr, out2, blockIdx.x, blockIdx.y, D, D);
}

// ---- FPS v3: packed distances + warp-parallel cross reduce, 1 barrier/iter ----
__device__ void fps_body(int b, const float* __restrict__ decpc,
                         const float* __restrict__ encpc)
{
    extern __shared__ float smext[];
    float* sx = smext;
    float* sy = smext + NC;
    float* sz = smext + 2*NC;
    __shared__ unsigned long long swk[2][16];

    int tid = threadIdx.x;
    int wid = tid >> 5, lid = tid & 31;

    for (int j = tid; j < N1; j += 512) {
        sx[j] = decpc[((size_t)b*N1 + j)*3 + 0];
        sy[j] = decpc[((size_t)b*N1 + j)*3 + 1];
        sz[j] = decpc[((size_t)b*N1 + j)*3 + 2];
        sx[N1+j] = encpc[((size_t)b*N2 + j)*3 + 0];
        sy[N1+j] = encpc[((size_t)b*N2 + j)*3 + 1];
        sz[N1+j] = encpc[((size_t)b*N2 + j)*3 + 2];
    }
    if (tid == 0) g_fidx[b*N1] = 0;
    int cur = 0;
    __syncthreads();

    unsigned long long PX[4], PY[4], PZ[4];
    float md[8];
#pragma unroll
    for (int p = 0; p < 4; p++) {
        int j0 = tid + (2*p)*512, j1 = tid + (2*p+1)*512;
        PX[p] = pack2(sx[j0], sx[j1]);
        PY[p] = pack2(sy[j0], sy[j1]);
        PZ[p] = pack2(sz[j0], sz[j1]);
        md[2*p] = 1e10f; md[2*p+1] = 1e10f;
    }

    for (int i = 1; i < N1; i++) {
        float lx = sx[cur], ly = sy[cur], lz = sz[cur];
        unsigned long long NLX = pack2(-lx, -lx);
        unsigned long long NLY = pack2(-ly, -ly);
        unsigned long long NLZ = pack2(-lz, -lz);
#pragma unroll
        for (int p = 0; p < 4; p++) {
            unsigned long long dx, dy, dz, dd;
            ADD2(dx, PX[p], NLX);
            ADD2(dy, PY[p], NLY);
            ADD2(dz, PZ[p], NLZ);
            MUL2(dd, dx, dx);
            FMA2(dd, dy, dy, dd);
            FMA2(dd, dz, dz, dd);
            float d0, d1; unpack2(dd, d0, d1);
            md[2*p]   = fminf(md[2*p],   d0);
            md[2*p+1] = fminf(md[2*p+1], d1);
        }
        float bv = fmaxf(fmaxf(fmaxf(md[0],md[1]), fmaxf(md[2],md[3])),
                         fmaxf(fmaxf(md[4],md[5]), fmaxf(md[6],md[7])));
        int bt = 0;
#pragma unroll
        for (int t = 7; t >= 0; t--) if (md[t] == bv) bt = t;
        int besti = tid + bt*512;

        unsigned kb = __float_as_uint(bv);
        unsigned mk;
        asm("redux.sync.max.u32 %0, %1, 0xffffffff;" : "=r"(mk) : "r"(kb));
        unsigned idxc = (kb == mk) ? (0xffffffffu - (unsigned)besti) : 0u;
        unsigned mi;
        asm("redux.sync.max.u32 %0, %1, 0xffffffff;" : "=r"(mi) : "r"(idxc));
        int pb = i & 1;
        if (lid == 0)
            swk[pb][wid] = (((unsigned long long)mk) << 32) | (unsigned long long)mi;
        __syncthreads();
        unsigned long long kv = swk[pb][lid & 15];
        unsigned hi32 = (unsigned)(kv >> 32);
        unsigned lo32 = (unsigned)kv;
        unsigned mh;
        asm("redux.sync.max.u32 %0, %1, 0xffffffff;" : "=r"(mh) : "r"(hi32));
        unsigned lc = (hi32 == mh) ? lo32 : 0u;
        unsigned ml;
        asm("redux.sync.max.u32 %0, %1, 0xffffffff;" : "=r"(ml) : "r"(lc));
        cur = (int)(0xffffffffu - ml);
        if (tid == 0) g_fidx[b*N1 + i] = cur;
    }
}

// ---------------- small 64-col GEMM body (weight precomputes), 512 thr --------
#define TBM 64
#define TBK 16
__device__ void gemm64_body(const float* __restrict__ A, const float* __restrict__ W,
                            float* __restrict__ C, int row0, int N, int K)
{
    __shared__ float As64[TBK][TBM];
    __shared__ float Bs64[TBK][64];
    int tid = threadIdx.x;
    for (int k0 = 0; k0 < K; k0 += TBK) {
#pragma unroll
        for (int u = 0; u < 2; u++) {
            int e = tid + u*512;
            int r = e >> 4, c = e & 15;
            As64[c][r] = A[(size_t)(row0 + r)*K + k0 + c];
            int r2 = e >> 6, c2 = e & 63;
            Bs64[r2][c2] = W[(size_t)(k0 + r2)*N + c2];
        }
        __syncthreads();
        if (tid < 256) {
            int tx = tid & 15, ty = tid >> 4;
            float acc[4][4] = {};
#pragma unroll
            for (int kk = 0; kk < TBK; kk++) {
                float a[4], bb[4];
#pragma unroll
                for (int i = 0; i < 4; i++) a[i] = As64[kk][ty*4+i];
#pragma unroll
                for (int j = 0; j < 4; j++) bb[j] = Bs64[kk][tx*4+j];
#pragma unroll
                for (int i = 0; i < 4; i++)
#pragma unroll
                    for (int j = 0; j < 4; j++)
                        acc[i][j] += a[i]*bb[j];
            }
#pragma unroll
            for (int i = 0; i < 4; i++)
#pragma unroll
                for (int j = 0; j < 4; j++) {
                    size_t off = (size_t)(row0 + ty*4 + i)*N + tx*4 + j;
                    if (k0 == 0) C[off] = acc[i][j];
                    else         C[off] += acc[i][j];
                }
        }
        __syncthreads();
    }
}

// ---------------- cvec body: (bk - bq + bp2) @ Wa1 + ba1, 512 thr --------------
__device__ void cvec_body(const float* __restrict__ bk, const float* __restrict__ bq,
                          const float* __restrict__ bp2, const float* __restrict__ Wa1,
                          const float* __restrict__ ba1)
{
    __shared__ float shc[512];
    int c = threadIdx.x & 63;
    int part = threadIdx.x >> 6;     // 0..7
    float s = 0.f;
    for (int i = part*32; i < part*32 + 32; i++)
        s += (bk[i] - bq[i] + bp2[i]) * Wa1[(size_t)i*HA + c];
    shc[threadIdx.x] = s;
    __syncthreads();
    if (part == 0) {
        float t = ba1[c];
#pragma unroll
        for (int p = 0; p < 8; p++) t += shc[p*64 + c];
        g_cvec[c] = t;
    }
}

// ---------------- weight hi/lo split body (once per launch) -------------------
__device__ void wsplit_body(const float* __restrict__ W, float* __restrict__ out, int n)
{
    for (int i = threadIdx.x; i < n; i += 512) {
        float x = W[i];
        uint32_t hi = f2tf(x);
        out[2*i]   = __uint_as_float(hi);
        out[2*i+1] = __uint_as_float(f2tf(x - __uint_as_float(hi)));
    }
}

// ---------------- phase-1 mega-kernel -----------------------------------------
// [0,4)=FPS [4,132)=pre1 [132,260)=pre2 [260,264)=WkWa1 [264,268)=WqWa1
// [268]=Wp2a [269]=cvec [270]=zero_stats [271]=split Wa2 [272]=split Wp2
__global__ void __launch_bounds__(512)
phase1_kernel(const float* __restrict__ dec_pc, const float* __restrict__ enc_pc,
              const float* __restrict__ dec_x,  const float* __restrict__ enc_x,
              const float* __restrict__ W_pre1, const float* __restrict__ b_pre1,
              const float* __restrict__ W_pre2, const float* __restrict__ b_pre2,
              const float* __restrict__ Wk, const float* __restrict__ Wq,
              const float* __restrict__ Wa1, const float* __restrict__ Wp2,
              const float* __restrict__ bk, const float* __restrict__ bq,
              const float* __restrict__ bp2, const float* __restrict__ ba1,
              const float* __restrict__ Wa2)
{
    int bid = blockIdx.x;
    if (bid < 4) {
        fps_body(bid, dec_pc, enc_pc);
    } else if (bid < 132) {
        int t = bid - 4;
        gemm_tf32_body(dec_x, W_pre1, b_pre1, nullptr, g_dx, t & 1, t >> 1, D, D);
    } else if (bid < 260) {
        int t = bid - 132;
        gemm_tf32_body(enc_x, W_pre2, b_pre2, nullptr, g_ex, t & 1, t >> 1, D, D);
    } else if (bid < 264) {
        gemm64_body(Wk, Wa1, g_WkWa1, (bid-260)*64, HA, D);
    } else if (bid < 268) {
        gemm64_body(Wq, Wa1, g_WqWa1, (bid-264)*64, HA, D);
    } else if (bid == 268) {
        gemm64_body(Wp2, Wa1, g_Wp2a, 0, HA, D);
    } else if (bid == 269) {
        cvec_body(bk, bq, bp2, Wa1, ba1);
    } else if (bid == 270) {
        if (threadIdx.x < 256) g_stats[threadIdx.x] = 0.0f;
    } else if (bid == 271) {
        wsplit_body(Wa2, g_Wa2hl, HA*D);
    } else {
        wsplit_body(Wp2, g_Wp2hl, HP*D);
    }
}

// ---------------- gather sampled features + coords ----------------------------
__global__ void gather_kernel(const float* __restrict__ decpc,
                              const float* __restrict__ encpc)
{
    int row = blockIdx.x*4 + (threadIdx.x >> 6);
    int c4  = (threadIdx.x & 63) * 4;
    int b = row >> 11;
    int j = g_fidx[row];
    const float* src = (j < N1) ? &g_dx[((size_t)b*N1 + j)*D]
                                : &g_ex[((size_t)b*N2 + (j - N1))*D];
    *(float4*)&g_sx[(size_t)row*D + c4] = *(const float4*)&src[c4];
    if ((threadIdx.x & 63) < 3) {
        int cc = threadIdx.x & 63;
        const float* ps = (j < N1) ? &decpc[((size_t)b*N1 + j)*3]
                                   : &encpc[((size_t)b*N2 + (j - N1))*3];
        g_spc[(size_t)row*3 + cc] = ps[cc];
    }
}

// ---------------- N=64 GEMM body for 512 threads (qa/ka) -----------------------
__device__ void n64_body_512(const float* __restrict__ A, const float* __restrict__ W,
                             float* __restrict__ C, int row0)
{
    __shared__ float Asq[16][132];
    __shared__ float Bsq[16][64];
    int tid = threadIdx.x;
    int tx = tid & 15, ty = tid >> 4;          // ty 0..31
    float acc[4][4] = {};
    for (int k0 = 0; k0 < D; k0 += 16) {
        {
            int r = tid >> 2, kq = (tid & 3) * 4;
            float4 va = *(const float4*)&A[(size_t)(row0 + r)*D + k0 + kq];
            Asq[kq+0][r] = va.x; Asq[kq+1][r] = va.y;
            Asq[kq+2][r] = va.z; Asq[kq+3][r] = va.w;
        }
        if (tid < 256) {
            int r = tid >> 4, cq = (tid & 15) * 4;
            *(float4*)&Bsq[r][cq] = *(const float4*)&W[(size_t)(k0 + r)*HA + cq];
        }
        __syncthreads();
#pragma unroll
        for (int kk = 0; kk < 16; kk++) {
            float a[4], bb[4];
#pragma unroll
            for (int i = 0; i < 4; i++) a[i] = Asq[kk][ty*4+i];
#pragma unroll
            for (int j = 0; j < 4; j++) bb[j] = Bsq[kk][tx*4+j];
#pragma unroll
            for (int i = 0; i < 4; i++)
#pragma unroll
                for (int j = 0; j < 4; j++)
                    acc[i][j] += a[i]*bb[j];
        }
        __syncthreads();
    }
#pragma unroll
    for (int i = 0; i < 4; i++)
#pragma unroll
        for (int j = 0; j < 4; j++)
            C[(size_t)(row0 + ty*4 + i)*HA + tx*4 + j] = acc[i][j];
}

// ---------------- phase-2 mega-kernel: KNN + qa/ka + v -------------------------
__global__ void __launch_bounds__(512)
phase2_kernel(const float* __restrict__ decpc,
              const float* __restrict__ Wv, const float* __restrict__ bv)
{
    int bid = blockIdx.x;
    if (bid < 32) {
        extern __shared__ float s2[];
        float* px = s2; float* py = px + 2048; float* pz = py + 2048; float* s2s = pz + 2048;
        unsigned long long* buf = (unsigned long long*)(s2 + 8192);
        int tid = threadIdx.x;
        int b = bid >> 3, qb = bid & 7;
        for (int m = tid; m < 2048; m += 512) {
            float x = g_spc[((size_t)b*N1 + m)*3 + 0];
            float y = g_spc[((size_t)b*N1 + m)*3 + 1];
            float z = g_spc[((size_t)b*N1 + m)*3 + 2];
            px[m] = x; py[m] = y; pz[m] = z;
            s2s[m] = x*x + y*y + z*z;
        }
        __syncthreads();
        int qi = tid & 255, h = tid >> 8;
        int q = qb*256 + qi;
        float qx = decpc[((size_t)b*N1 + q)*3 + 0];
        float qy = decpc[((size_t)b*N1 + q)*3 + 1];
        float qz = decpc[((size_t)b*N1 + q)*3 + 2];
        float s1 = qx*qx + qy*qy + qz*qz;
        float bd[KNN]; int bi[KNN];
#pragma unroll
        for (int t = 0; t < KNN; t++) { bd[t] = 1e30f; bi[t] = 0; }
        int mbase = h * 1024;
        for (int mm = 0; mm < 1024; mm++) {
            int m = mbase + mm;
            float d = s1 + s2s[m] - 2.0f*(qx*px[m] + qy*py[m] + qz*pz[m]);
            if (d < bd[KNN-1]) {
                bd[KNN-1] = d; bi[KNN-1] = m;
#pragma unroll
                for (int t = KNN-1; t > 0; t--) {
                    if (bd[t] < bd[t-1]) {
                        float td = bd[t]; bd[t] = bd[t-1]; bd[t-1] = td;
                        int   ti = bi[t]; bi[t] = bi[t-1]; bi[t-1] = ti;
                    }
                }
            }
        }
#pragma unroll
        for (int t = 0; t < KNN; t++) {
            unsigned u = __float_as_uint(bd[t]);
            u = ((int)u < 0) ? ~u : (u | 0x80000000u);
            buf[(size_t)tid*KNN + t] = (((unsigned long long)u) << 32) | (unsigned)bi[t];
        }
        __syncthreads();
        if (h == 0) {
            const unsigned long long* A_ = &buf[(size_t)qi*KNN];
            const unsigned long long* B_ = &buf[(size_t)(qi+256)*KNN];
            int* outp = &g_nidx[((size_t)b*N1 + q)*KNN];
            int ia = 0, ib = 0;
#pragma unroll
            for (int o = 0; o < KNN; o++) {
                unsigned long long av = A_[ia], bv_ = B_[ib];
                if ((av >> 32) <= (bv_ >> 32)) { outp[o] = (int)(unsigned)av; ia++; }
                else                           { outp[o] = (int)(unsigned)bv_; ib++; }
            }
        }
    } else if (bid < 160) {
        int t = bid - 32;
        int sel = t >> 6, tile = t & 63;
        n64_body_512(sel ? g_sx : g_dx, sel ? g_WkWa1 : g_WqWa1,
                     sel ? g_ka : g_qa, tile*128);
    } else {
        int t = bid - 160;
        gemm_tf32_body(g_sx, Wv, bv, nullptr, g_v, t & 1, t >> 1, D, D);
    }
}

// ---------------- hpos + fused BN stats ----------------------------------------
__global__ void __launch_bounds__(256)
hpos_kernel(const float* __restrict__ decpc,
            const float* __restrict__ Wp1,
            const float* __restrict__ bp1)
{
    int tid = threadIdx.x;
    int c = tid & 63;
    int rg = tid >> 6;
    float w0 = Wp1[c], w1 = Wp1[64+c], w2 = Wp1[128+c], bb = bp1[c];
    float s = 0.f, s2 = 0.f;
    int base = blockIdx.x * 256;
    for (int it = 0; it < 64; it++) {
        int m = base + it*4 + rg;
        int b = m >> 15;
        int n = (m >> 4) & 2047;
        int j = g_nidx[m];
        const float* pp = &g_spc[((size_t)b*N1 + j)*3];
        const float* qq = &decpc[((size_t)b*N1 + n)*3];
        float p0 = pp[0]-qq[0], p1 = pp[1]-qq[1], p2 = pp[2]-qq[2];
        float h = p0*w0 + p1*w1 + p2*w2 + bb;
        g_hpos[(size_t)m*HP + c] = h;
        s += h; s2 += h*h;
    }
    __shared__ float sh[256], sh2[256];
    sh[tid] = s; sh2[tid] = s2;
    __syncthreads();
    if (rg == 0) {
        atomicAdd(&g_stats[c],    sh[c] + sh[64+c] + sh[128+c] + sh[192+c]);
        atomicAdd(&g_stats[64+c], sh2[c] + sh2[64+c] + sh2[128+c] + sh2[192+c]);
    }
}

// ---- hattn = relu(bn_pos(hp)) @ Wp2a + ka[gather] - qa + cvec + stats --------
__global__ void __launch_bounds__(256)
hattn_kernel(const float* __restrict__ gp, const float* __restrict__ betap)
{
    __shared__ float Aw[64][65];
    __shared__ float Bw[64*64];
    __shared__ float psc[64], psh[64];
    __shared__ float rs[16][64], rs2[16][64];
    int tid = threadIdx.x;
    int m0 = blockIdx.x * 64;
    if (tid < 64) {
        float mean = g_stats[tid] * INV_MROW;
        float var  = g_stats[64+tid] * INV_MROW - mean*mean;
        float sc = gp[tid]*rsqrtf(var + 1e-5f);
        psc[tid] = sc;
        psh[tid] = betap[tid] - mean*sc;
    }
    __syncthreads();
#pragma unroll
    for (int i = 0; i < 16; i++) {
        int idx = tid + i*256;
        int r = idx >> 6, k = idx & 63;
        float h = g_hpos[(size_t)(m0+r)*64 + k];
        Aw[r][k] = fmaxf(h*psc[k] + psh[k], 0.0f);
        Bw[idx] = g_Wp2a[idx];
    }
    __syncthreads();
    int tx = tid & 15, ty = tid >> 4;
    float acc[4][4] = {};
#pragma unroll 4
    for (int kk = 0; kk < 64; kk++) {
        float a[4], bb[4];
#pragma unroll
        for (int i = 0; i < 4; i++) a[i] = Aw[ty*4+i][kk];
#pragma unroll
        for (int j = 0; j < 4; j++) bb[j] = Bw[kk*64 + tx*4 + j];
#pragma unroll
        for (int i = 0; i < 4; i++)
#pragma unroll
            for (int j = 0; j < 4; j++)
                acc[i][j] += a[i]*bb[j];
    }
    float ps[4] = {0,0,0,0}, ps2[4] = {0,0,0,0};
#pragma unroll
    for (int i = 0; i < 4; i++) {
        int m = m0 + ty*4 + i;
        int b = m >> 15;
        int n = (m >> 4) & 2047;
        int jj = g_nidx[m];
        const float* kar = &g_ka[(((size_t)b<<11) + jj)*HA];
        const float* qar = &g_qa[(((size_t)b<<11) + n )*HA];
#pragma unroll
        for (int j = 0; j < 4; j++) {
            int c = tx*4 + j;
            float v = acc[i][j] + kar[c] - qar[c] + g_cvec[c];
            g_hattn[(size_t)m*HA + c] = v;
            ps[j] += v; ps2[j] += v*v;
        }
    }
#pragma unroll
    for (int j = 0; j < 4; j++) {
        rs[ty][tx*4+j] = ps[j];
        rs2[ty][tx*4+j] = ps2[j];
    }
    __syncthreads();
    if (tid < 64) {
        float s = 0.f, s2 = 0.f;
#pragma unroll
        for (int t = 0; t < 16; t++) { s += rs[t][tid]; s2 += rs2[t][tid]; }
        atomicAdd(&g_stats[128+tid], s);
        atomicAdd(&g_stats[192+tid], s2);
    }
}

// ---- fused: attn+pos GEMMs (merged k-loop) via tf32x2 mma + softmax + agg ----
// grid 2048; block handles 64 rows x 256 cols (two 128-col halves, A reused)
// Both B chunk pairs staged together; one k-loop feeds accA and accP.
__global__ void __launch_bounds__(256)
attnout_kernel(const float* __restrict__ ba2,
               const float* __restrict__ bp2,
               const float* __restrict__ gp, const float* __restrict__ betap,
               const float* __restrict__ ga, const float* __restrict__ betaa)
{
    extern __shared__ float sm[];
    float* Ahr    = sm;                 // [64][68]
    float* Apr    = Ahr + 64*68;        // [64][68]
    float* attn_s = Apr + 64*68;        // [64][132]
    float* pos_s  = attn_s + 64*132;    // [64][132]
    float* BhA    = pos_s + 64*132;     // [16][136]
    float* BlA    = BhA + 16*136;       // [16][136]
    float* BhP    = BlA + 16*136;       // [16][136]
    float* BlP    = BhP + 16*136;       // [16][136]
    float* scbuf  = BlP + 16*136;       // psc,psh,asc,ash [4][64]
    int*   sj     = (int*)(scbuf + 256);// [64]

    int tid = threadIdx.x;
    int m0 = blockIdx.x * 64;
    int warp = tid >> 5, lane = tid & 31;
    int mw = (warp & 3) * 16, nw = (warp >> 2) * 64;
    int g = lane >> 2, tg = lane & 3;

    if (tid < 64) {
        float mean = g_stats[tid] * INV_MROW;
        float var  = g_stats[64+tid] * INV_MROW - mean*mean;
        float sc = gp[tid]*rsqrtf(var + 1e-5f);
        scbuf[tid] = sc;
        scbuf[64+tid] = betap[tid] - mean*sc;
        mean = g_stats[128+tid] * INV_MROW;
        var  = g_stats[192+tid] * INV_MROW - mean*mean;
        sc = ga[tid]*rsqrtf(var + 1e-5f);
        scbuf[128+tid] = sc;
        scbuf[192+tid] = betaa[tid] - mean*sc;
        sj[tid] = g_nidx[m0 + tid];
    }
    __syncthreads();

#pragma unroll
    for (int i = 0; i < 16; i++) {
        int idx = tid + i*256;
        int r = idx >> 6, k = idx & 63;
        float ha = g_hattn[(size_t)(m0+r)*64 + k];
        Ahr[r*68 + k] = fmaxf(ha*scbuf[128+k] + scbuf[192+k], 0.0f);
        float hp = g_hpos[(size_t)(m0+r)*64 + k];
        Apr[r*68 + k] = fmaxf(hp*scbuf[k] + scbuf[64+k], 0.0f);
    }

    for (int half = 0; half < 2; half++) {
        int c0 = half * 128;
        float accA[8][4] = {};
        float accP[8][4] = {};
        for (int k0 = 0; k0 < 64; k0 += 16) {
            __syncthreads();
#pragma unroll
            for (int i = 0; i < 8; i++) {
                int idx = tid + i*256;
                int r = idx >> 7, c = idx & 127;
                float2 hlA = *(const float2*)&g_Wa2hl[((size_t)(k0+r)*D + c0 + c)*2];
                BhA[r*136 + c] = hlA.x;
                BlA[r*136 + c] = hlA.y;
                float2 hlP = *(const float2*)&g_Wp2hl[((size_t)(k0+r)*D + c0 + c)*2];
                BhP[r*136 + c] = hlP.x;
                BlP[r*136 + c] = hlP.y;
            }
            __syncthreads();
#pragma unroll
            for (int ks = 0; ks < 16; ks += 8) {
                uint32_t ahA[4], alA[4], ahP[4], alP[4];
                {
                    float x0 = Ahr[(mw+g  )*68 + k0+ks+tg  ];
                    float x1 = Ahr[(mw+g+8)*68 + k0+ks+tg  ];
                    float x2 = Ahr[(mw+g  )*68 + k0+ks+tg+4];
                    float x3 = Ahr[(mw+g+8)*68 + k0+ks+tg+4];
                    ahA[0] = f2tf(x0); alA[0] = f2tf(x0 - __uint_as_float(ahA[0]));
                    ahA[1] = f2tf(x1); alA[1] = f2tf(x1 - __uint_as_float(ahA[1]));
                    ahA[2] = f2tf(x2); alA[2] = f2tf(x2 - __uint_as_float(ahA[2]));
                    ahA[3] = f2tf(x3); alA[3] = f2tf(x3 - __uint_as_float(ahA[3]));
                    float y0 = Apr[(mw+g  )*68 + k0+ks+tg  ];
                    float y1 = Apr[(mw+g+8)*68 + k0+ks+tg  ];
                    float y2 = Apr[(mw+g  )*68 + k0+ks+tg+4];
                    float y3 = Apr[(mw+g+8)*68 + k0+ks+tg+4];
                    ahP[0] = f2tf(y0); alP[0] = f2tf(y0 - __uint_as_float(ahP[0]));
                    ahP[1] = f2tf(y1); alP[1] = f2tf(y1 - __uint_as_float(ahP[1]));
                    ahP[2] = f2tf(y2); alP[2] = f2tf(y2 - __uint_as_float(ahP[2]));
                    ahP[3] = f2tf(y3); alP[3] = f2tf(y3 - __uint_as_float(ahP[3]));
                }
#pragma unroll
                for (int ni = 0; ni < 8; ni++) {
                    uint32_t bhf[2], blf[2];
                    bhf[0] = __float_as_uint(BhA[(ks+tg  )*136 + nw + ni*8 + g]);
                    bhf[1] = __float_as_uint(BhA[(ks+tg+4)*136 + nw + ni*8 + g]);
                    blf[0] = __float_as_uint(BlA[(ks+tg  )*136 + nw + ni*8 + g]);
                    blf[1] = __float_as_uint(BlA[(ks+tg+4)*136 + nw + ni*8 + g]);
                    mma8(accA[ni], ahA, bhf);
                    mma8(accA[ni], ahA, blf);
                    mma8(accA[ni], alA, bhf);
                    bhf[0] = __float_as_uint(BhP[(ks+tg  )*136 + nw + ni*8 + g]);
                    bhf[1] = __float_as_uint(BhP[(ks+tg+4)*136 + nw + ni*8 + g]);
                    blf[0] = __float_as_uint(BlP[(ks+tg  )*136 + nw + ni*8 + g]);
                    blf[1] = __float_as_uint(BlP[(ks+tg+4)*136 + nw + ni*8 + g]);
                    mma8(accP[ni], ahP, bhf);
                    mma8(accP[ni], ahP, blf);
                    mma8(accP[ni], alP, bhf);
                }
            }
        }
        __syncthreads();
#pragma unroll
        for (int ni = 0; ni < 8; ni++) {
            int c = nw + ni*8 + 2*tg;
            float a0 = ba2[c0 + c], a1 = ba2[c0 + c + 1];
            float p0 = bp2[c0 + c], p1 = bp2[c0 + c + 1];
            attn_s[(mw+g  )*132 + c]     = accA[ni][0] + a0;
            attn_s[(mw+g  )*132 + c + 1] = accA[ni][1] + a1;
            attn_s[(mw+g+8)*132 + c]     = accA[ni][2] + a0;
            attn_s[(mw+g+8)*132 + c + 1] = accA[ni][3] + a1;
            pos_s [(mw+g  )*132 + c]     = accP[ni][0] + p0;
            pos_s [(mw+g  )*132 + c + 1] = accP[ni][1] + p1;
            pos_s [(mw+g+8)*132 + c]     = accP[ni][2] + p0;
            pos_s [(mw+g+8)*132 + c + 1] = accP[ni][3] + p1;
        }
        __syncthreads();

        // softmax over 16 neighbors + aggregation for this 128-col half
#pragma unroll
        for (int e = tid; e < 512; e += 256) {
            int q = e >> 7;            // 0..3
            int c = e & 127;
            int mrow = q*16;
            float mx = -1e30f;
#pragma unroll
            for (int k = 0; k < KNN; k++)
                mx = fmaxf(mx, attn_s[(mrow+k)*132 + c]);
            float w[KNN]; float s = 0.f;
#pragma unroll
            for (int k = 0; k < KNN; k++) {
                w[k] = __expf(attn_s[(mrow+k)*132 + c] - mx);
                s += w[k];
            }
            float inv = 1.0f / s;
            int qg = (m0 >> 4) + q;
            int b = qg >> 11;
            float x = 0.f;
#pragma unroll
            for (int k = 0; k < KNN; k++) {
                int j = sj[mrow + k];
                float vv = g_v[(((size_t)b<<11) + j)*D + c0 + c] + pos_s[(mrow+k)*132 + c];
                x += vv * w[k];
            }
            g_x[(size_t)qg*D + c0 + c] = x * inv;
        }
        __syncthreads();
    }
}

// =================================================================================
extern "C" void kernel_launch(void* const* d_in, const int* in_sizes, int n_in,
                              void* d_out, int out_size)
{
    const float* dec_x   = (const float*)d_in[0];
    const float* dec_pc  = (const float*)d_in[1];
    const float* enc_x   = (const float*)d_in[2];
    const float* enc_pc  = (const float*)d_in[3];
    const float* W_pre1  = (const float*)d_in[4];
    const float* b_pre1  = (const float*)d_in[5];
    const float* W_pre2  = (const float*)d_in[6];
    const float* b_pre2  = (const float*)d_in[7];
    const float* Wq      = (const float*)d_in[8];
    const float* bq      = (const float*)d_in[9];
    const float* Wk      = (const float*)d_in[10];
    const float* bk      = (const float*)d_in[11];
    const float* Wv      = (const float*)d_in[12];
    const float* bv      = (const float*)d_in[13];
    const float* Wp1     = (const float*)d_in[14];
    const float* bp1     = (const float*)d_in[15];
    const float* gp      = (const float*)d_in[16];
    const float* betap   = (const float*)d_in[17];
    const float* Wp2     = (const float*)d_in[18];
    const float* bp2     = (const float*)d_in[19];
    const float* Wa1     = (const float*)d_in[20];
    const float* ba1     = (const float*)d_in[21];
    const float* ga      = (const float*)d_in[22];
    const float* betaa   = (const float*)d_in[23];
    const float* Wa2     = (const float*)d_in[24];
    const float* ba2     = (const float*)d_in[25];
    const float* W_post1 = (const float*)d_in[26];
    const float* b_post1 = (const float*)d_in[27];
    const float* W_post2 = (const float*)d_in[28];
    const float* b_post2 = (const float*)d_in[29];
    float* out = (float*)d_out;

    float *p_x;
    cudaGetSymbolAddress((void**)&p_x, g_x);

    const int M8 = B*N1;                         // 8192
    const int PH1_SMEM  = TF32_SMEM_FLOATS*4;                 // 71680 (>= FPS 49152)
    const int PH2_SMEM  = 8192*4 + 512*KNN*8;                 // 98304
    const int ATTN_SMEM = (64*68*2 + 64*132*2 + 4*16*136 + 256)*4 + 64*4; // ~139KB
    const int POST_SMEM = TF32_SMEM_FLOATS*4;

    // 1) phase-1: FPS || pre-projections || weight precomputes || splits || zero
    cudaFuncSetAttribute(phase1_kernel, cudaFuncAttributeMaxDynamicSharedMemorySize, PH1_SMEM);
    phase1_kernel<<<273, 512, PH1_SMEM>>>(dec_pc, enc_pc, dec_x, enc_x,
                                          W_pre1, b_pre1, W_pre2, b_pre2,
                                          Wk, Wq, Wa1, Wp2, bk, bq, bp2, ba1, Wa2);

    // 2) gather sampled features + coords
    gather_kernel<<<M8/4, 256>>>(dec_pc, enc_pc);

    // 3) phase-2: KNN || qa/ka || v
    cudaFuncSetAttribute(phase2_kernel, cudaFuncAttributeMaxDynamicSharedMemorySize, PH2_SMEM);
    phase2_kernel<<<288, 512, PH2_SMEM>>>(dec_pc, Wv, bv);

    // 4) hpos + fused pos-BN stats
    hpos_kernel<<<512, 256>>>(dec_pc, Wp1, bp1);

    // 5) hattn (inline pos-BN finalize) + fused attn-BN stats
    hattn_kernel<<<MROW/64, 256>>>(gp, betap);

    // 6) fused attn+pos mma GEMMs (merged k-loop) + softmax + aggregation
    cudaFuncSetAttribute(attnout_kernel, cudaFuncAttributeMaxDynamicSharedMemorySize, ATTN_SMEM);
    attnout_kernel<<<MROW/64, 256, ATTN_SMEM>>>(ba2, bp2, gp, betap, ga, betaa);

    // 7) outputs (both post GEMMs in one launch)
    float* out1 = out;                                   // [B,N1,256]
    float* opc1 = out + (size_t)M8*D;                    // [B,N1,3]
    float* out2 = opc1 + (size_t)M8*3;                   // [B,N1,256]
    float* opc2 = out2 + (size_t)M8*D;                   // [B,N2,3]
    cudaFuncSetAttribute(gemm_post_kernel, cudaFuncAttributeMaxDynamicSharedMemorySize, POST_SMEM);
    gemm_post_kernel<<<dim3(2, M8/128, 2), 512, POST_SMEM>>>(p_x, W_post1, b_post1, dec_x, out1,
                                                             W_post2, b_post2, out2);
    cudaMemcpyAsync(opc1, dec_pc, (size_t)M8*3*sizeof(float), cudaMemcpyDeviceToDevice);
    cudaMemcpyAsync(opc2, enc_pc, (size_t)B*N2*3*sizeof(float), cudaMemcpyDeviceToDevice);
}

// round 17
// speedup vs baseline: 1.5371x; 1.0019x over previous
#include <cuda_runtime.h>
#include <cuda_bf16.h>
#include <math.h>
#include <stdint.h>

// Problem constants
#define B    4
#define N1   2048
#define N2   2048
#define NC   4096           // N1+N2
#define D    256
#define HP   64
#define HA   64
#define KNN  16
#define MROW (B*N1*KNN)     // 131072
#define INV_MROW (1.0f/131072.0f)

// ---------------- scratch (device globals; no allocation allowed) -------------
__device__ float g_dx  [B*N1*D];
__device__ float g_ex  [B*N2*D];
__device__ float g_sx  [B*N1*D];
__device__ float g_spc [B*N1*3];
__device__ int   g_fidx[B*N1];
__device__ float g_qa  [B*N1*HA];
__device__ float g_ka  [B*N1*HA];
__device__ float g_v   [B*N1*D];
__device__ int   g_nidx[B*N1*KNN];
__device__ float g_hpos [MROW*HP];
__device__ float g_hattn[MROW*HA];
__device__ float g_x   [B*N1*D];
__device__ float g_WkWa1[D*HA];
__device__ float g_WqWa1[D*HA];
__device__ float g_Wp2a [HP*HA];
__device__ float g_cvec [HA];
__device__ float g_Wa2hl[HA*D*2];   // interleaved tf32 hi/lo planes of Wa2
__device__ float g_Wp2hl[HP*D*2];   // interleaved tf32 hi/lo planes of Wp2
// [0:64) psum [64:128) psq [128:192) asum [192:256) asq
__device__ float g_stats[256];

// ================= packed f32x2 helpers (sm_103a FFMA2 path) ==================
#define ADD2(o,a,b)   asm("add.rn.f32x2 %0, %1, %2;" : "=l"(o) : "l"(a), "l"(b))
#define MUL2(o,a,b)   asm("mul.rn.f32x2 %0, %1, %2;" : "=l"(o) : "l"(a), "l"(b))
#define FMA2(o,a,b,c) asm("fma.rn.f32x2 %0, %1, %2, %3;" : "=l"(o) : "l"(a), "l"(b), "l"(c))
__device__ __forceinline__ unsigned long long pack2(float lo, float hi) {
    unsigned long long o;
    asm("mov.b64 %0, {%1, %2};" : "=l"(o) : "r"(__float_as_uint(lo)), "r"(__float_as_uint(hi)));
    return o;
}
__device__ __forceinline__ void unpack2(unsigned long long v, float& lo, float& hi) {
    uint32_t a, b;
    asm("mov.b64 {%0, %1}, %2;" : "=r"(a), "=r"(b) : "l"(v));
    lo = __uint_as_float(a); hi = __uint_as_float(b);
}

// ================= tf32 mma helpers ===========================================
__device__ __forceinline__ uint32_t f2tf(float x) {
    uint32_t r; asm("cvt.rna.tf32.f32 %0, %1;" : "=r"(r) : "f"(x)); return r;
}
__device__ __forceinline__ void mma8(float* d, const uint32_t* a, const uint32_t* b) {
    asm volatile("mma.sync.aligned.m16n8k8.row.col.f32.tf32.tf32.f32 "
        "{%0,%1,%2,%3}, {%4,%5,%6,%7}, {%8,%9}, {%0,%1,%2,%3};"
        : "+f"(d[0]), "+f"(d[1]), "+f"(d[2]), "+f"(d[3])
        : "r"(a[0]), "r"(a[1]), "r"(a[2]), "r"(a[3]), "r"(b[0]), "r"(b[1]));
}

// ------ tf32x2 GEMM body: 128x128 tile, 512 threads, hi/lo planes, 3-mma ------
#define APITCH 36
#define BPITCH 136
#define TF32_SMEM_FLOATS (2*128*APITCH + 2*32*BPITCH)

__device__ __forceinline__ void gemm_tf32_body(
    const float* __restrict__ A, const float* __restrict__ W,
    const float* __restrict__ bias, const float* __restrict__ resid,
    float* __restrict__ C, int bx, int by, int N, int K)
{
    extern __shared__ float smext[];
    float* AHs = smext;
    float* ALs = AHs + 128*APITCH;
    float* BHs = ALs + 128*APITCH;
    float* BLs = BHs + 32*BPITCH;
    int tid = threadIdx.x;
    int row0 = by * 128, col0 = bx * 128;
    int warp = tid >> 5, lane = tid & 31;
    int mw = (warp & 3) * 32, nw = (warp >> 2) * 32;
    int g = lane >> 2, tg = lane & 3;
    float acc[8][4] = {};
    for (int k0 = 0; k0 < K; k0 += 32) {
#pragma unroll
        for (int i = 0; i < 2; i++) {
            int idx = tid + i*512;
            int r = idx >> 3, c4 = (idx & 7) * 4;
            float4 v = *(const float4*)&A[(size_t)(row0+r)*K + k0 + c4];
            float xs[4] = {v.x, v.y, v.z, v.w};
#pragma unroll
            for (int u = 0; u < 4; u++) {
                uint32_t hi = f2tf(xs[u]);
                AHs[r*APITCH + c4+u] = __uint_as_float(hi);
                ALs[r*APITCH + c4+u] = __uint_as_float(f2tf(xs[u] - __uint_as_float(hi)));
            }
        }
#pragma unroll
        for (int i = 0; i < 2; i++) {
            int idx = tid + i*512;
            int r = idx >> 5, c4 = (idx & 31) * 4;
            float4 v = *(const float4*)&W[(size_t)(k0+r)*N + col0 + c4];
            float xs[4] = {v.x, v.y, v.z, v.w};
#pragma unroll
            for (int u = 0; u < 4; u++) {
                uint32_t hi = f2tf(xs[u]);
                BHs[r*BPITCH + c4+u] = __uint_as_float(hi);
                BLs[r*BPITCH + c4+u] = __uint_as_float(f2tf(xs[u] - __uint_as_float(hi)));
            }
        }
        __syncthreads();
#pragma unroll
        for (int ks = 0; ks < 32; ks += 8) {
            uint32_t ah[2][4], al[2][4], bh[4][2], bl[4][2];
#pragma unroll
            for (int mi = 0; mi < 2; mi++) {
                int rb = mw + mi*16;
                ah[mi][0] = __float_as_uint(AHs[(rb+g  )*APITCH + ks+tg  ]);
                ah[mi][1] = __float_as_uint(AHs[(rb+g+8)*APITCH + ks+tg  ]);
                ah[mi][2] = __float_as_uint(AHs[(rb+g  )*APITCH + ks+tg+4]);
                ah[mi][3] = __float_as_uint(AHs[(rb+g+8)*APITCH + ks+tg+4]);
                al[mi][0] = __float_as_uint(ALs[(rb+g  )*APITCH + ks+tg  ]);
                al[mi][1] = __float_as_uint(ALs[(rb+g+8)*APITCH + ks+tg  ]);
                al[mi][2] = __float_as_uint(ALs[(rb+g  )*APITCH + ks+tg+4]);
                al[mi][3] = __float_as_uint(ALs[(rb+g+8)*APITCH + ks+tg+4]);
            }
#pragma unroll
            for (int ni = 0; ni < 4; ni++) {
                bh[ni][0] = __float_as_uint(BHs[(ks+tg  )*BPITCH + nw + ni*8 + g]);
                bh[ni][1] = __float_as_uint(BHs[(ks+tg+4)*BPITCH + nw + ni*8 + g]);
                bl[ni][0] = __float_as_uint(BLs[(ks+tg  )*BPITCH + nw + ni*8 + g]);
                bl[ni][1] = __float_as_uint(BLs[(ks+tg+4)*BPITCH + nw + ni*8 + g]);
            }
#pragma unroll
            for (int mi = 0; mi < 2; mi++)
#pragma unroll
                for (int ni = 0; ni < 4; ni++) {
                    mma8(acc[mi*4+ni], ah[mi], bh[ni]);
                    mma8(acc[mi*4+ni], ah[mi], bl[ni]);
                    mma8(acc[mi*4+ni], al[mi], bh[ni]);
                }
        }
        __syncthreads();
    }
#pragma unroll
    for (int mi = 0; mi < 2; mi++) {
#pragma unroll
        for (int ni = 0; ni < 4; ni++) {
            int c = col0 + nw + ni*8 + 2*tg;
            float b0 = bias ? bias[c]   : 0.f;
            float b1 = bias ? bias[c+1] : 0.f;
            size_t r1 = (size_t)(row0 + mw + mi*16 + g);
            size_t r2 = r1 + 8;
            float v00 = acc[mi*4+ni][0] + b0, v01 = acc[mi*4+ni][1] + b1;
            float v10 = acc[mi*4+ni][2] + b0, v11 = acc[mi*4+ni][3] + b1;
            if (resid) {
                v00 += resid[r1*N+c]; v01 += resid[r1*N+c+1];
                v10 += resid[r2*N+c]; v11 += resid[r2*N+c+1];
            }
            *(float2*)&C[r1*N + c] = make_float2(v00, v01);
            *(float2*)&C[r2*N + c] = make_float2(v10, v11);
        }
    }
}

// ---- merged post-GEMM: A staged once, both W_post1/W_post2 computed ----------
// dyn smem floats: AH/AL[128*36]*2 + (BH/BL)[32*136]*2 per weight = 26624
#define POST_SMEM_FLOATS (2*128*APITCH + 4*32*BPITCH)
__global__ void __launch_bounds__(512)
gemm_post_kernel(const float* __restrict__ X,
                 const float* __restrict__ W1, const float* __restrict__ b1,
                 const float* __restrict__ resid1, float* __restrict__ out1,
                 const float* __restrict__ W2, const float* __restrict__ b2,
                 float* __restrict__ out2)
{
    extern __shared__ float smext[];
    float* AHs = smext;
    float* ALs = AHs + 128*APITCH;
    float* BH1 = ALs + 128*APITCH;
    float* BL1 = BH1 + 32*BPITCH;
    float* BH2 = BL1 + 32*BPITCH;
    float* BL2 = BH2 + 32*BPITCH;
    int tid = threadIdx.x;
    int row0 = blockIdx.y * 128, col0 = blockIdx.x * 128;
    int warp = tid >> 5, lane = tid & 31;
    int mw = (warp & 3) * 32, nw = (warp >> 2) * 32;
    int g = lane >> 2, tg = lane & 3;
    float accA[8][4] = {};
    float accB[8][4] = {};
    for (int k0 = 0; k0 < D; k0 += 32) {
#pragma unroll
        for (int i = 0; i < 2; i++) {
            int idx = tid + i*512;
            int r = idx >> 3, c4 = (idx & 7) * 4;
            float4 v = *(const float4*)&X[(size_t)(row0+r)*D + k0 + c4];
            float xs[4] = {v.x, v.y, v.z, v.w};
#pragma unroll
            for (int u = 0; u < 4; u++) {
                uint32_t hi = f2tf(xs[u]);
                AHs[r*APITCH + c4+u] = __uint_as_float(hi);
                ALs[r*APITCH + c4+u] = __uint_as_float(f2tf(xs[u] - __uint_as_float(hi)));
            }
        }
#pragma unroll
        for (int i = 0; i < 2; i++) {
            int idx = tid + i*512;
            int r = idx >> 5, c4 = (idx & 31) * 4;
            float4 v = *(const float4*)&W1[(size_t)(k0+r)*D + col0 + c4];
            float xs[4] = {v.x, v.y, v.z, v.w};
#pragma unroll
            for (int u = 0; u < 4; u++) {
                uint32_t hi = f2tf(xs[u]);
                BH1[r*BPITCH + c4+u] = __uint_as_float(hi);
                BL1[r*BPITCH + c4+u] = __uint_as_float(f2tf(xs[u] - __uint_as_float(hi)));
            }
            v = *(const float4*)&W2[(size_t)(k0+r)*D + col0 + c4];
            float ys[4] = {v.x, v.y, v.z, v.w};
#pragma unroll
            for (int u = 0; u < 4; u++) {
                uint32_t hi = f2tf(ys[u]);
                BH2[r*BPITCH + c4+u] = __uint_as_float(hi);
                BL2[r*BPITCH + c4+u] = __uint_as_float(f2tf(ys[u] - __uint_as_float(hi)));
            }
        }
        __syncthreads();
#pragma unroll
        for (int ks = 0; ks < 32; ks += 8) {
            uint32_t ah[2][4], al[2][4];
#pragma unroll
            for (int mi = 0; mi < 2; mi++) {
                int rb = mw + mi*16;
                ah[mi][0] = __float_as_uint(AHs[(rb+g  )*APITCH + ks+tg  ]);
                ah[mi][1] = __float_as_uint(AHs[(rb+g+8)*APITCH + ks+tg  ]);
                ah[mi][2] = __float_as_uint(AHs[(rb+g  )*APITCH + ks+tg+4]);
                ah[mi][3] = __float_as_uint(AHs[(rb+g+8)*APITCH + ks+tg+4]);
                al[mi][0] = __float_as_uint(ALs[(rb+g  )*APITCH + ks+tg  ]);
                al[mi][1] = __float_as_uint(ALs[(rb+g+8)*APITCH + ks+tg  ]);
                al[mi][2] = __float_as_uint(ALs[(rb+g  )*APITCH + ks+tg+4]);
                al[mi][3] = __float_as_uint(ALs[(rb+g+8)*APITCH + ks+tg+4]);
            }
#pragma unroll
            for (int ni = 0; ni < 4; ni++) {
                uint32_t bh[2], bl[2];
                bh[0] = __float_as_uint(BH1[(ks+tg  )*BPITCH + nw + ni*8 + g]);
                bh[1] = __float_as_uint(BH1[(ks+tg+4)*BPITCH + nw + ni*8 + g]);
                bl[0] = __float_as_uint(BL1[(ks+tg  )*BPITCH + nw + ni*8 + g]);
                bl[1] = __float_as_uint(BL1[(ks+tg+4)*BPITCH + nw + ni*8 + g]);
#pragma unroll
                for (int mi = 0; mi < 2; mi++) {
                    mma8(accA[mi*4+ni], ah[mi], bh);
                    mma8(accA[mi*4+ni], ah[mi], bl);
                    mma8(accA[mi*4+ni], al[mi], bh);
                }
                bh[0] = __float_as_uint(BH2[(ks+tg  )*BPITCH + nw + ni*8 + g]);
                bh[1] = __float_as_uint(BH2[(ks+tg+4)*BPITCH + nw + ni*8 + g]);
                bl[0] = __float_as_uint(BL2[(ks+tg  )*BPITCH + nw + ni*8 + g]);
                bl[1] = __float_as_uint(BL2[(ks+tg+4)*BPITCH + nw + ni*8 + g]);
#pragma unroll
                for (int mi = 0; mi < 2; mi++) {
                    mma8(accB[mi*4+ni], ah[mi], bh);
                    mma8(accB[mi*4+ni], ah[mi], bl);
                    mma8(accB[mi*4+ni], al[mi], bh);
                }
            }
        }
        __syncthreads();
    }
#pragma unroll
    for (int mi = 0; mi < 2; mi++) {
#pragma unroll
        for (int ni = 0; ni < 4; ni++) {
            int c = col0 + nw + ni*8 + 2*tg;
            size_t r1 = (size_t)(row0 + mw + mi*16 + g);
            size_t r2 = r1 + 8;
            float b0 = b1[c], b1v = b1[c+1];
            float v00 = accA[mi*4+ni][0] + b0 + resid1[r1*D+c];
            float v01 = accA[mi*4+ni][1] + b1v + resid1[r1*D+c+1];
            float v10 = accA[mi*4+ni][2] + b0 + resid1[r2*D+c];
            float v11 = accA[mi*4+ni][3] + b1v + resid1[r2*D+c+1];
            *(float2*)&out1[r1*D + c] = make_float2(v00, v01);
            *(float2*)&out1[r2*D + c] = make_float2(v10, v11);
            b0 = b2[c]; b1v = b2[c+1];
            v00 = accB[mi*4+ni][0] + b0;  v01 = accB[mi*4+ni][1] + b1v;
            v10 = accB[mi*4+ni][2] + b0;  v11 = accB[mi*4+ni][3] + b1v;
            *(float2*)&out2[r1*D + c] = make_float2(v00, v01);
            *(float2*)&out2[r2*D + c] = make_float2(v10, v11);
        }
    }
}

// ---- FPS v3: packed distances + warp-parallel cross reduce, 1 barrier/iter ----
__device__ void fps_body(int b, const float* __restrict__ decpc,
                         const float* __restrict__ encpc)
{
    extern __shared__ float smext[];
    float* sx = smext;
    float* sy = smext + NC;
    float* sz = smext + 2*NC;
    __shared__ unsigned long long swk[2][16];

    int tid = threadIdx.x;
    int wid = tid >> 5, lid = tid & 31;

    for (int j = tid; j < N1; j += 512) {
        sx[j] = decpc[((size_t)b*N1 + j)*3 + 0];
        sy[j] = decpc[((size_t)b*N1 + j)*3 + 1];
        sz[j] = decpc[((size_t)b*N1 + j)*3 + 2];
        sx[N1+j] = encpc[((size_t)b*N2 + j)*3 + 0];
        sy[N1+j] = encpc[((size_t)b*N2 + j)*3 + 1];
        sz[N1+j] = encpc[((size_t)b*N2 + j)*3 + 2];
    }
    if (tid == 0) g_fidx[b*N1] = 0;
    int cur = 0;
    __syncthreads();

    unsigned long long PX[4], PY[4], PZ[4];
    float md[8];
#pragma unroll
    for (int p = 0; p < 4; p++) {
        int j0 = tid + (2*p)*512, j1 = tid + (2*p+1)*512;
        PX[p] = pack2(sx[j0], sx[j1]);
        PY[p] = pack2(sy[j0], sy[j1]);
        PZ[p] = pack2(sz[j0], sz[j1]);
        md[2*p] = 1e10f; md[2*p+1] = 1e10f;
    }

    for (int i = 1; i < N1; i++) {
        float lx = sx[cur], ly = sy[cur], lz = sz[cur];
        unsigned long long NLX = pack2(-lx, -lx);
        unsigned long long NLY = pack2(-ly, -ly);
        unsigned long long NLZ = pack2(-lz, -lz);
#pragma unroll
        for (int p = 0; p < 4; p++) {
            unsigned long long dx, dy, dz, dd;
            ADD2(dx, PX[p], NLX);
            ADD2(dy, PY[p], NLY);
            ADD2(dz, PZ[p], NLZ);
            MUL2(dd, dx, dx);
            FMA2(dd, dy, dy, dd);
            FMA2(dd, dz, dz, dd);
            float d0, d1; unpack2(dd, d0, d1);
            md[2*p]   = fminf(md[2*p],   d0);
            md[2*p+1] = fminf(md[2*p+1], d1);
        }
        float bv = fmaxf(fmaxf(fmaxf(md[0],md[1]), fmaxf(md[2],md[3])),
                         fmaxf(fmaxf(md[4],md[5]), fmaxf(md[6],md[7])));
        int bt = 0;
#pragma unroll
        for (int t = 7; t >= 0; t--) if (md[t] == bv) bt = t;
        int besti = tid + bt*512;

        unsigned kb = __float_as_uint(bv);
        unsigned mk;
        asm("redux.sync.max.u32 %0, %1, 0xffffffff;" : "=r"(mk) : "r"(kb));
        unsigned idxc = (kb == mk) ? (0xffffffffu - (unsigned)besti) : 0u;
        unsigned mi;
        asm("redux.sync.max.u32 %0, %1, 0xffffffff;" : "=r"(mi) : "r"(idxc));
        int pb = i & 1;
        if (lid == 0)
            swk[pb][wid] = (((unsigned long long)mk) << 32) | (unsigned long long)mi;
        __syncthreads();
        unsigned long long kv = swk[pb][lid & 15];
        unsigned hi32 = (unsigned)(kv >> 32);
        unsigned lo32 = (unsigned)kv;
        unsigned mh;
        asm("redux.sync.max.u32 %0, %1, 0xffffffff;" : "=r"(mh) : "r"(hi32));
        unsigned lc = (hi32 == mh) ? lo32 : 0u;
        unsigned ml;
        asm("redux.sync.max.u32 %0, %1, 0xffffffff;" : "=r"(ml) : "r"(lc));
        cur = (int)(0xffffffffu - ml);
        if (tid == 0) g_fidx[b*N1 + i] = cur;
    }
}

// ---------------- small 64-col GEMM body (weight precomputes), 512 thr --------
#define TBM 64
#define TBK 16
__device__ void gemm64_body(const float* __restrict__ A, const float* __restrict__ W,
                            float* __restrict__ C, int row0, int N, int K)
{
    __shared__ float As64[TBK][TBM];
    __shared__ float Bs64[TBK][64];
    int tid = threadIdx.x;
    for (int k0 = 0; k0 < K; k0 += TBK) {
#pragma unroll
        for (int u = 0; u < 2; u++) {
            int e = tid + u*512;
            int r = e >> 4, c = e & 15;
            As64[c][r] = A[(size_t)(row0 + r)*K + k0 + c];
            int r2 = e >> 6, c2 = e & 63;
            Bs64[r2][c2] = W[(size_t)(k0 + r2)*N + c2];
        }
        __syncthreads();
        if (tid < 256) {
            int tx = tid & 15, ty = tid >> 4;
            float acc[4][4] = {};
#pragma unroll
            for (int kk = 0; kk < TBK; kk++) {
                float a[4], bb[4];
#pragma unroll
                for (int i = 0; i < 4; i++) a[i] = As64[kk][ty*4+i];
#pragma unroll
                for (int j = 0; j < 4; j++) bb[j] = Bs64[kk][tx*4+j];
#pragma unroll
                for (int i = 0; i < 4; i++)
#pragma unroll
                    for (int j = 0; j < 4; j++)
                        acc[i][j] += a[i]*bb[j];
            }
#pragma unroll
            for (int i = 0; i < 4; i++)
#pragma unroll
                for (int j = 0; j < 4; j++) {
                    size_t off = (size_t)(row0 + ty*4 + i)*N + tx*4 + j;
                    if (k0 == 0) C[off] = acc[i][j];
                    else         C[off] += acc[i][j];
                }
        }
        __syncthreads();
    }
}

// ---------------- cvec body: (bk - bq + bp2) @ Wa1 + ba1, 512 thr --------------
__device__ void cvec_body(const float* __restrict__ bk, const float* __restrict__ bq,
                          const float* __restrict__ bp2, const float* __restrict__ Wa1,
                          const float* __restrict__ ba1)
{
    __shared__ float shc[512];
    int c = threadIdx.x & 63;
    int part = threadIdx.x >> 6;     // 0..7
    float s = 0.f;
    for (int i = part*32; i < part*32 + 32; i++)
        s += (bk[i] - bq[i] + bp2[i]) * Wa1[(size_t)i*HA + c];
    shc[threadIdx.x] = s;
    __syncthreads();
    if (part == 0) {
        float t = ba1[c];
#pragma unroll
        for (int p = 0; p < 8; p++) t += shc[p*64 + c];
        g_cvec[c] = t;
    }
}

// ---------------- weight hi/lo split body (once per launch) -------------------
__device__ void wsplit_body(const float* __restrict__ W, float* __restrict__ out, int n)
{
    for (int i = threadIdx.x; i < n; i += 512) {
        float x = W[i];
        uint32_t hi = f2tf(x);
        out[2*i]   = __uint_as_float(hi);
        out[2*i+1] = __uint_as_float(f2tf(x - __uint_as_float(hi)));
    }
}

// ---------------- phase-1 mega-kernel -----------------------------------------
// [0,4)=FPS [4,132)=pre1 [132,260)=pre2 [260,264)=WkWa1 [264,268)=WqWa1
// [268]=Wp2a [269]=cvec [270]=zero_stats [271]=split Wa2 [272]=split Wp2
__global__ void __launch_bounds__(512)
phase1_kernel(const float* __restrict__ dec_pc, const float* __restrict__ enc_pc,
              const float* __restrict__ dec_x,  const float* __restrict__ enc_x,
              const float* __restrict__ W_pre1, const float* __restrict__ b_pre1,
              const float* __restrict__ W_pre2, const float* __restrict__ b_pre2,
              const float* __restrict__ Wk, const float* __restrict__ Wq,
              const float* __restrict__ Wa1, const float* __restrict__ Wp2,
              const float* __restrict__ bk, const float* __restrict__ bq,
              const float* __restrict__ bp2, const float* __restrict__ ba1,
              const float* __restrict__ Wa2)
{
    int bid = blockIdx.x;
    if (bid < 4) {
        fps_body(bid, dec_pc, enc_pc);
    } else if (bid < 132) {
        int t = bid - 4;
        gemm_tf32_body(dec_x, W_pre1, b_pre1, nullptr, g_dx, t & 1, t >> 1, D, D);
    } else if (bid < 260) {
        int t = bid - 132;
        gemm_tf32_body(enc_x, W_pre2, b_pre2, nullptr, g_ex, t & 1, t >> 1, D, D);
    } else if (bid < 264) {
        gemm64_body(Wk, Wa1, g_WkWa1, (bid-260)*64, HA, D);
    } else if (bid < 268) {
        gemm64_body(Wq, Wa1, g_WqWa1, (bid-264)*64, HA, D);
    } else if (bid == 268) {
        gemm64_body(Wp2, Wa1, g_Wp2a, 0, HA, D);
    } else if (bid == 269) {
        cvec_body(bk, bq, bp2, Wa1, ba1);
    } else if (bid == 270) {
        if (threadIdx.x < 256) g_stats[threadIdx.x] = 0.0f;
    } else if (bid == 271) {
        wsplit_body(Wa2, g_Wa2hl, HA*D);
    } else {
        wsplit_body(Wp2, g_Wp2hl, HP*D);
    }
}

// ---------------- gather sampled features + coords + pc passthrough -----------
// blocks [0,2048): feature/coord gather; [2048,2144): pc copies into out
__global__ void gather_kernel(const float* __restrict__ decpc,
                              const float* __restrict__ encpc,
                              float* __restrict__ opc1,
                              float* __restrict__ opc2)
{
    int bid = blockIdx.x;
    if (bid < 2048) {
        int row = bid*4 + (threadIdx.x >> 6);
        int c4  = (threadIdx.x & 63) * 4;
        int b = row >> 11;
        int j = g_fidx[row];
        const float* src = (j < N1) ? &g_dx[((size_t)b*N1 + j)*D]
                                    : &g_ex[((size_t)b*N2 + (j - N1))*D];
        *(float4*)&g_sx[(size_t)row*D + c4] = *(const float4*)&src[c4];
        if ((threadIdx.x & 63) < 3) {
            int cc = threadIdx.x & 63;
            const float* ps = (j < N1) ? &decpc[((size_t)b*N1 + j)*3]
                                       : &encpc[((size_t)b*N2 + (j - N1))*3];
            g_spc[(size_t)row*3 + cc] = ps[cc];
        }
    } else {
        int e = (bid - 2048)*256 + threadIdx.x;   // 0..24575 float2 units
        if (e < 12288)
            *((float2*)opc1 + e) = *((const float2*)decpc + e);
        else
            *((float2*)opc2 + (e - 12288)) = *((const float2*)encpc + (e - 12288));
    }
}

// ---------------- N=64 GEMM body for 512 threads (qa/ka) -----------------------
__device__ void n64_body_512(const float* __restrict__ A, const float* __restrict__ W,
                             float* __restrict__ C, int row0)
{
    __shared__ float Asq[16][132];
    __shared__ float Bsq[16][64];
    int tid = threadIdx.x;
    int tx = tid & 15, ty = tid >> 4;          // ty 0..31
    float acc[4][4] = {};
    for (int k0 = 0; k0 < D; k0 += 16) {
        {
            int r = tid >> 2, kq = (tid & 3) * 4;
            float4 va = *(const float4*)&A[(size_t)(row0 + r)*D + k0 + kq];
            Asq[kq+0][r] = va.x; Asq[kq+1][r] = va.y;
            Asq[kq+2][r] = va.z; Asq[kq+3][r] = va.w;
        }
        if (tid < 256) {
            int r = tid >> 4, cq = (tid & 15) * 4;
            *(float4*)&Bsq[r][cq] = *(const float4*)&W[(size_t)(k0 + r)*HA + cq];
        }
        __syncthreads();
#pragma unroll
        for (int kk = 0; kk < 16; kk++) {
            float a[4], bb[4];
#pragma unroll
            for (int i = 0; i < 4; i++) a[i] = Asq[kk][ty*4+i];
#pragma unroll
            for (int j = 0; j < 4; j++) bb[j] = Bsq[kk][tx*4+j];
#pragma unroll
            for (int i = 0; i < 4; i++)
#pragma unroll
                for (int j = 0; j < 4; j++)
                    acc[i][j] += a[i]*bb[j];
        }
        __syncthreads();
    }
#pragma unroll
    for (int i = 0; i < 4; i++)
#pragma unroll
        for (int j = 0; j < 4; j++)
            C[(size_t)(row0 + ty*4 + i)*HA + tx*4 + j] = acc[i][j];
}

// ---------------- phase-2 mega-kernel: KNN + qa/ka + v -------------------------
__global__ void __launch_bounds__(512)
phase2_kernel(const float* __restrict__ decpc,
              const float* __restrict__ Wv, const float* __restrict__ bv)
{
    int bid = blockIdx.x;
    if (bid < 32) {
        extern __shared__ float s2[];
        float* px = s2; float* py = px + 2048; float* pz = py + 2048; float* s2s = pz + 2048;
        unsigned long long* buf = (unsigned long long*)(s2 + 8192);
        int tid = threadIdx.x;
        int b = bid >> 3, qb = bid & 7;
        for (int m = tid; m < 2048; m += 512) {
            float x = g_spc[((size_t)b*N1 + m)*3 + 0];
            float y = g_spc[((size_t)b*N1 + m)*3 + 1];
            float z = g_spc[((size_t)b*N1 + m)*3 + 2];
            px[m] = x; py[m] = y; pz[m] = z;
            s2s[m] = x*x + y*y + z*z;
        }
        __syncthreads();
        int qi = tid & 255, h = tid >> 8;
        int q = qb*256 + qi;
        float qx = decpc[((size_t)b*N1 + q)*3 + 0];
        float qy = decpc[((size_t)b*N1 + q)*3 + 1];
        float qz = decpc[((size_t)b*N1 + q)*3 + 2];
        float s1 = qx*qx + qy*qy + qz*qz;
        float bd[KNN]; int bi[KNN];
#pragma unroll
        for (int t = 0; t < KNN; t++) { bd[t] = 1e30f; bi[t] = 0; }
        int mbase = h * 1024;
        for (int mm = 0; mm < 1024; mm++) {
            int m = mbase + mm;
            float d = s1 + s2s[m] - 2.0f*(qx*px[m] + qy*py[m] + qz*pz[m]);
            if (d < bd[KNN-1]) {
                bd[KNN-1] = d; bi[KNN-1] = m;
#pragma unroll
                for (int t = KNN-1; t > 0; t--) {
                    if (bd[t] < bd[t-1]) {
                        float td = bd[t]; bd[t] = bd[t-1]; bd[t-1] = td;
                        int   ti = bi[t]; bi[t] = bi[t-1]; bi[t-1] = ti;
                    }
                }
            }
        }
#pragma unroll
        for (int t = 0; t < KNN; t++) {
            unsigned u = __float_as_uint(bd[t]);
            u = ((int)u < 0) ? ~u : (u | 0x80000000u);
            buf[(size_t)tid*KNN + t] = (((unsigned long long)u) << 32) | (unsigned)bi[t];
        }
        __syncthreads();
        if (h == 0) {
            const unsigned long long* A_ = &buf[(size_t)qi*KNN];
            const unsigned long long* B_ = &buf[(size_t)(qi+256)*KNN];
            int* outp = &g_nidx[((size_t)b*N1 + q)*KNN];
            int ia = 0, ib = 0;
#pragma unroll
            for (int o = 0; o < KNN; o++) {
                unsigned long long av = A_[ia], bv_ = B_[ib];
                if ((av >> 32) <= (bv_ >> 32)) { outp[o] = (int)(unsigned)av; ia++; }
                else                           { outp[o] = (int)(unsigned)bv_; ib++; }
            }
        }
    } else if (bid < 160) {
        int t = bid - 32;
        int sel = t >> 6, tile = t & 63;
        n64_body_512(sel ? g_sx : g_dx, sel ? g_WkWa1 : g_WqWa1,
                     sel ? g_ka : g_qa, tile*128);
    } else {
        int t = bid - 160;
        gemm_tf32_body(g_sx, Wv, bv, nullptr, g_v, t & 1, t >> 1, D, D);
    }
}

// ---------------- hpos + fused BN stats ----------------------------------------
__global__ void __launch_bounds__(256)
hpos_kernel(const float* __restrict__ decpc,
            const float* __restrict__ Wp1,
            const float* __restrict__ bp1)
{
    int tid = threadIdx.x;
    int c = tid & 63;
    int rg = tid >> 6;
    float w0 = Wp1[c], w1 = Wp1[64+c], w2 = Wp1[128+c], bb = bp1[c];
    float s = 0.f, s2 = 0.f;
    int base = blockIdx.x * 256;
    for (int it = 0; it < 64; it++) {
        int m = base + it*4 + rg;
        int b = m >> 15;
        int n = (m >> 4) & 2047;
        int j = g_nidx[m];
        const float* pp = &g_spc[((size_t)b*N1 + j)*3];
        const float* qq = &decpc[((size_t)b*N1 + n)*3];
        float p0 = pp[0]-qq[0], p1 = pp[1]-qq[1], p2 = pp[2]-qq[2];
        float h = p0*w0 + p1*w1 + p2*w2 + bb;
        g_hpos[(size_t)m*HP + c] = h;
        s += h; s2 += h*h;
    }
    __shared__ float sh[256], sh2[256];
    sh[tid] = s; sh2[tid] = s2;
    __syncthreads();
    if (rg == 0) {
        atomicAdd(&g_stats[c],    sh[c] + sh[64+c] + sh[128+c] + sh[192+c]);
        atomicAdd(&g_stats[64+c], sh2[c] + sh2[64+c] + sh2[128+c] + sh2[192+c]);
    }
}

// ---- hattn = relu(bn_pos(hp)) @ Wp2a + ka[gather] - qa + cvec + stats --------
__global__ void __launch_bounds__(256)
hattn_kernel(const float* __restrict__ gp, const float* __restrict__ betap)
{
    __shared__ float Aw[64][65];
    __shared__ float Bw[64*64];
    __shared__ float psc[64], psh[64];
    __shared__ float rs[16][64], rs2[16][64];
    int tid = threadIdx.x;
    int m0 = blockIdx.x * 64;
    if (tid < 64) {
        float mean = g_stats[tid] * INV_MROW;
        float var  = g_stats[64+tid] * INV_MROW - mean*mean;
        float sc = gp[tid]*rsqrtf(var + 1e-5f);
        psc[tid] = sc;
        psh[tid] = betap[tid] - mean*sc;
    }
    __syncthreads();
#pragma unroll
    for (int i = 0; i < 16; i++) {
        int idx = tid + i*256;
        int r = idx >> 6, k = idx & 63;
        float h = g_hpos[(size_t)(m0+r)*64 + k];
        Aw[r][k] = fmaxf(h*psc[k] + psh[k], 0.0f);
        Bw[idx] = g_Wp2a[idx];
    }
    __syncthreads();
    int tx = tid & 15, ty = tid >> 4;
    float acc[4][4] = {};
#pragma unroll 4
    for (int kk = 0; kk < 64; kk++) {
        float a[4], bb[4];
#pragma unroll
        for (int i = 0; i < 4; i++) a[i] = Aw[ty*4+i][kk];
#pragma unroll
        for (int j = 0; j < 4; j++) bb[j] = Bw[kk*64 + tx*4 + j];
#pragma unroll
        for (int i = 0; i < 4; i++)
#pragma unroll
            for (int j = 0; j < 4; j++)
                acc[i][j] += a[i]*bb[j];
    }
    float ps[4] = {0,0,0,0}, ps2[4] = {0,0,0,0};
#pragma unroll
    for (int i = 0; i < 4; i++) {
        int m = m0 + ty*4 + i;
        int b = m >> 15;
        int n = (m >> 4) & 2047;
        int jj = g_nidx[m];
        const float* kar = &g_ka[(((size_t)b<<11) + jj)*HA];
        const float* qar = &g_qa[(((size_t)b<<11) + n )*HA];
#pragma unroll
        for (int j = 0; j < 4; j++) {
            int c = tx*4 + j;
            float v = acc[i][j] + kar[c] - qar[c] + g_cvec[c];
            g_hattn[(size_t)m*HA + c] = v;
            ps[j] += v; ps2[j] += v*v;
        }
    }
#pragma unroll
    for (int j = 0; j < 4; j++) {
        rs[ty][tx*4+j] = ps[j];
        rs2[ty][tx*4+j] = ps2[j];
    }
    __syncthreads();
    if (tid < 64) {
        float s = 0.f, s2 = 0.f;
#pragma unroll
        for (int t = 0; t < 16; t++) { s += rs[t][tid]; s2 += rs2[t][tid]; }
        atomicAdd(&g_stats[128+tid], s);
        atomicAdd(&g_stats[192+tid], s2);
    }
}

// ---- fused: attn+pos GEMMs (merged k-loop) via tf32x2 mma + softmax + agg ----
__global__ void __launch_bounds__(256)
attnout_kernel(const float* __restrict__ ba2,
               const float* __restrict__ bp2,
               const float* __restrict__ gp, const float* __restrict__ betap,
               const float* __restrict__ ga, const float* __restrict__ betaa)
{
    extern __shared__ float sm[];
    float* Ahr    = sm;                 // [64][68]
    float* Apr    = Ahr + 64*68;        // [64][68]
    float* attn_s = Apr + 64*68;        // [64][132]
    float* pos_s  = attn_s + 64*132;    // [64][132]
    float* BhA    = pos_s + 64*132;     // [16][136]
    float* BlA    = BhA + 16*136;       // [16][136]
    float* BhP    = BlA + 16*136;       // [16][136]
    float* BlP    = BhP + 16*136;       // [16][136]
    float* scbuf  = BlP + 16*136;       // psc,psh,asc,ash [4][64]
    int*   sj     = (int*)(scbuf + 256);// [64]

    int tid = threadIdx.x;
    int m0 = blockIdx.x * 64;
    int warp = tid >> 5, lane = tid & 31;
    int mw = (warp & 3) * 16, nw = (warp >> 2) * 64;
    int g = lane >> 2, tg = lane & 3;

    if (tid < 64) {
        float mean = g_stats[tid] * INV_MROW;
        float var  = g_stats[64+tid] * INV_MROW - mean*mean;
        float sc = gp[tid]*rsqrtf(var + 1e-5f);
        scbuf[tid] = sc;
        scbuf[64+tid] = betap[tid] - mean*sc;
        mean = g_stats[128+tid] * INV_MROW;
        var  = g_stats[192+tid] * INV_MROW - mean*mean;
        sc = ga[tid]*rsqrtf(var + 1e-5f);
        scbuf[128+tid] = sc;
        scbuf[192+tid] = betaa[tid] - mean*sc;
        sj[tid] = g_nidx[m0 + tid];
    }
    __syncthreads();

#pragma unroll
    for (int i = 0; i < 16; i++) {
        int idx = tid + i*256;
        int r = idx >> 6, k = idx & 63;
        float ha = g_hattn[(size_t)(m0+r)*64 + k];
        Ahr[r*68 + k] = fmaxf(ha*scbuf[128+k] + scbuf[192+k], 0.0f);
        float hp = g_hpos[(size_t)(m0+r)*64 + k];
        Apr[r*68 + k] = fmaxf(hp*scbuf[k] + scbuf[64+k], 0.0f);
    }

    for (int half = 0; half < 2; half++) {
        int c0 = half * 128;
        float accA[8][4] = {};
        float accP[8][4] = {};
        for (int k0 = 0; k0 < 64; k0 += 16) {
            __syncthreads();
#pragma unroll
            for (int i = 0; i < 8; i++) {
                int idx = tid + i*256;
                int r = idx >> 7, c = idx & 127;
                float2 hlA = *(const float2*)&g_Wa2hl[((size_t)(k0+r)*D + c0 + c)*2];
                BhA[r*136 + c] = hlA.x;
                BlA[r*136 + c] = hlA.y;
                float2 hlP = *(const float2*)&g_Wp2hl[((size_t)(k0+r)*D + c0 + c)*2];
                BhP[r*136 + c] = hlP.x;
                BlP[r*136 + c] = hlP.y;
            }
            __syncthreads();
#pragma unroll
            for (int ks = 0; ks < 16; ks += 8) {
                uint32_t ahA[4], alA[4], ahP[4], alP[4];
                {
                    float x0 = Ahr[(mw+g  )*68 + k0+ks+tg  ];
                    float x1 = Ahr[(mw+g+8)*68 + k0+ks+tg  ];
                    float x2 = Ahr[(mw+g  )*68 + k0+ks+tg+4];
                    float x3 = Ahr[(mw+g+8)*68 + k0+ks+tg+4];
                    ahA[0] = f2tf(x0); alA[0] = f2tf(x0 - __uint_as_float(ahA[0]));
                    ahA[1] = f2tf(x1); alA[1] = f2tf(x1 - __uint_as_float(ahA[1]));
                    ahA[2] = f2tf(x2); alA[2] = f2tf(x2 - __uint_as_float(ahA[2]));
                    ahA[3] = f2tf(x3); alA[3] = f2tf(x3 - __uint_as_float(ahA[3]));
                    float y0 = Apr[(mw+g  )*68 + k0+ks+tg  ];
                    float y1 = Apr[(mw+g+8)*68 + k0+ks+tg  ];
                    float y2 = Apr[(mw+g  )*68 + k0+ks+tg+4];
                    float y3 = Apr[(mw+g+8)*68 + k0+ks+tg+4];
                    ahP[0] = f2tf(y0); alP[0] = f2tf(y0 - __uint_as_float(ahP[0]));
                    ahP[1] = f2tf(y1); alP[1] = f2tf(y1 - __uint_as_float(ahP[1]));
                    ahP[2] = f2tf(y2); alP[2] = f2tf(y2 - __uint_as_float(ahP[2]));
                    ahP[3] = f2tf(y3); alP[3] = f2tf(y3 - __uint_as_float(ahP[3]));
                }
#pragma unroll
                for (int ni = 0; ni < 8; ni++) {
                    uint32_t bhf[2], blf[2];
                    bhf[0] = __float_as_uint(BhA[(ks+tg  )*136 + nw + ni*8 + g]);
                    bhf[1] = __float_as_uint(BhA[(ks+tg+4)*136 + nw + ni*8 + g]);
                    blf[0] = __float_as_uint(BlA[(ks+tg  )*136 + nw + ni*8 + g]);
                    blf[1] = __float_as_uint(BlA[(ks+tg+4)*136 + nw + ni*8 + g]);
                    mma8(accA[ni], ahA, bhf);
                    mma8(accA[ni], ahA, blf);
                    mma8(accA[ni], alA, bhf);
                    bhf[0] = __float_as_uint(BhP[(ks+tg  )*136 + nw + ni*8 + g]);
                    bhf[1] = __float_as_uint(BhP[(ks+tg+4)*136 + nw + ni*8 + g]);
                    blf[0] = __float_as_uint(BlP[(ks+tg  )*136 + nw + ni*8 + g]);
                    blf[1] = __float_as_uint(BlP[(ks+tg+4)*136 + nw + ni*8 + g]);
                    mma8(accP[ni], ahP, bhf);
                    mma8(accP[ni], ahP, blf);
                    mma8(accP[ni], alP, bhf);
                }
            }
        }
        __syncthreads();
#pragma unroll
        for (int ni = 0; ni < 8; ni++) {
            int c = nw + ni*8 + 2*tg;
            float a0 = ba2[c0 + c], a1 = ba2[c0 + c + 1];
            float p0 = bp2[c0 + c], p1 = bp2[c0 + c + 1];
            attn_s[(mw+g  )*132 + c]     = accA[ni][0] + a0;
            attn_s[(mw+g  )*132 + c + 1] = accA[ni][1] + a1;
            attn_s[(mw+g+8)*132 + c]     = accA[ni][2] + a0;
            attn_s[(mw+g+8)*132 + c + 1] = accA[ni][3] + a1;
            pos_s [(mw+g  )*132 + c]     = accP[ni][0] + p0;
            pos_s [(mw+g  )*132 + c + 1] = accP[ni][1] + p1;
            pos_s [(mw+g+8)*132 + c]     = accP[ni][2] + p0;
            pos_s [(mw+g+8)*132 + c + 1] = accP[ni][3] + p1;
        }
        __syncthreads();

#pragma unroll
        for (int e = tid; e < 512; e += 256) {
            int q = e >> 7;            // 0..3
            int c = e & 127;
            int mrow = q*16;
            float mx = -1e30f;
#pragma unroll
            for (int k = 0; k < KNN; k++)
                mx = fmaxf(mx, attn_s[(mrow+k)*132 + c]);
            float w[KNN]; float s = 0.f;
#pragma unroll
            for (int k = 0; k < KNN; k++) {
                w[k] = __expf(attn_s[(mrow+k)*132 + c] - mx);
                s += w[k];
            }
            float inv = 1.0f / s;
            int qg = (m0 >> 4) + q;
            int b = qg >> 11;
            float x = 0.f;
#pragma unroll
            for (int k = 0; k < KNN; k++) {
                int j = sj[mrow + k];
                float vv = g_v[(((size_t)b<<11) + j)*D + c0 + c] + pos_s[(mrow+k)*132 + c];
                x += vv * w[k];
            }
            g_x[(size_t)qg*D + c0 + c] = x * inv;
        }
        __syncthreads();
    }
}

// =================================================================================
extern "C" void kernel_launch(void* const* d_in, const int* in_sizes, int n_in,
                              void* d_out, int out_size)
{
    const float* dec_x   = (const float*)d_in[0];
    const float* dec_pc  = (const float*)d_in[1];
    const float* enc_x   = (const float*)d_in[2];
    const float* enc_pc  = (const float*)d_in[3];
    const float* W_pre1  = (const float*)d_in[4];
    const float* b_pre1  = (const float*)d_in[5];
    const float* W_pre2  = (const float*)d_in[6];
    const float* b_pre2  = (const float*)d_in[7];
    const float* Wq      = (const float*)d_in[8];
    const float* bq      = (const float*)d_in[9];
    const float* Wk      = (const float*)d_in[10];
    const float* bk      = (const float*)d_in[11];
    const float* Wv      = (const float*)d_in[12];
    const float* bv      = (const float*)d_in[13];
    const float* Wp1     = (const float*)d_in[14];
    const float* bp1     = (const float*)d_in[15];
    const float* gp      = (const float*)d_in[16];
    const float* betap   = (const float*)d_in[17];
    const float* Wp2     = (const float*)d_in[18];
    const float* bp2     = (const float*)d_in[19];
    const float* Wa1     = (const float*)d_in[20];
    const float* ba1     = (const float*)d_in[21];
    const float* ga      = (const float*)d_in[22];
    const float* betaa   = (const float*)d_in[23];
    const float* Wa2     = (const float*)d_in[24];
    const float* ba2     = (const float*)d_in[25];
    const float* W_post1 = (const float*)d_in[26];
    const float* b_post1 = (const float*)d_in[27];
    const float* W_post2 = (const float*)d_in[28];
    const float* b_post2 = (const float*)d_in[29];
    float* out = (float*)d_out;

    float *p_x;
    cudaGetSymbolAddress((void**)&p_x, g_x);

    const int M8 = B*N1;                         // 8192
    const int PH1_SMEM  = TF32_SMEM_FLOATS*4;                 // 71680 (>= FPS 49152)
    const int PH2_SMEM  = 8192*4 + 512*KNN*8;                 // 98304
    const int ATTN_SMEM = (64*68*2 + 64*132*2 + 4*16*136 + 256)*4 + 64*4; // ~139KB
    const int POST_SMEM = POST_SMEM_FLOATS*4;                 // 106496

    float* out1 = out;                                   // [B,N1,256]
    float* opc1 = out + (size_t)M8*D;                    // [B,N1,3]
    float* out2 = opc1 + (size_t)M8*3;                   // [B,N1,256]
    float* opc2 = out2 + (size_t)M8*D;                   // [B,N2,3]

    // 1) phase-1: FPS || pre-projections || weight precomputes || splits || zero
    cudaFuncSetAttribute(phase1_kernel, cudaFuncAttributeMaxDynamicSharedMemorySize, PH1_SMEM);
    phase1_kernel<<<273, 512, PH1_SMEM>>>(dec_pc, enc_pc, dec_x, enc_x,
                                          W_pre1, b_pre1, W_pre2, b_pre2,
                                          Wk, Wq, Wa1, Wp2, bk, bq, bp2, ba1, Wa2);

    // 2) gather sampled features + coords (+ pc passthrough copies)
    gather_kernel<<<2048 + 96, 256>>>(dec_pc, enc_pc, opc1, opc2);

    // 3) phase-2: KNN || qa/ka || v
    cudaFuncSetAttribute(phase2_kernel, cudaFuncAttributeMaxDynamicSharedMemorySize, PH2_SMEM);
    phase2_kernel<<<288, 512, PH2_SMEM>>>(dec_pc, Wv, bv);

    // 4) hpos + fused pos-BN stats
    hpos_kernel<<<512, 256>>>(dec_pc, Wp1, bp1);

    // 5) hattn (inline pos-BN finalize) + fused attn-BN stats
    hattn_kernel<<<MROW/64, 256>>>(gp, betap);

    // 6) fused attn+pos mma GEMMs (merged k-loop) + softmax + aggregation
    cudaFuncSetAttribute(attnout_kernel, cudaFuncAttributeMaxDynamicSharedMemorySize, ATTN_SMEM);
    attnout_kernel<<<MROW/64, 256, ATTN_SMEM>>>(ba2, bp2, gp, betap, ga, betaa);

    // 7) outputs: both post GEMMs in one kernel, A staged once
    cudaFuncSetAttribute(gemm_post_kernel, cudaFuncAttributeMaxDynamicSharedMemorySize, POST_SMEM);
    gemm_post_kernel<<<dim3(2, M8/128), 512, POST_SMEM>>>(p_x, W_post1, b_post1, dec_x, out1,
                                                          W_post2, b_post2, out2);
}